// round 1
// baseline (speedup 1.0000x reference)
#include <cuda_runtime.h>
#include <math.h>

#define SEQ 2048
#define EMB 1024
#define NH  16
#define HD  64
#define NB  4
#define TOK (NB * SEQ)     // 8192
#define BHN (NB * NH)      // 64

// Scratch (device globals: allocation-free rule)
__device__ __align__(128) float g_Q[(size_t)BHN * SEQ * HD];
__device__ __align__(128) float g_K[(size_t)BHN * SEQ * HD];
__device__ __align__(128) float g_V[(size_t)BHN * SEQ * HD];
__device__ __align__(128) float g_O[(size_t)TOK * EMB];

// ---------------------------------------------------------------------------
// GEMM: C[m,n] = sum_k A[m,k] * W[n,k] + bias[n]
// M=8192, N=1024, K=1024. 128x128 block tile, 8x8 micro, 256 threads.
// srcIsO: A comes from g_O (out projection). scatterDst: 0=plain to Cout,
// 1/2/3 = scatter into g_Q/g_K/g_V in [b*H+h, s, d] layout.
// ---------------------------------------------------------------------------
__global__ __launch_bounds__(256, 2) void gemm_bias_kernel(
    const float* __restrict__ Ain,
    const float* __restrict__ Wt,
    const float* __restrict__ bias,
    float* __restrict__ Cout,
    int srcIsO, int scatterDst)
{
    __shared__ __align__(16) float As[16][128];
    __shared__ __align__(16) float Bs[16][128];

    const float* A = srcIsO ? g_O : Ain;
    const int tid = threadIdx.x;
    const int tx = tid & 15;
    const int ty = tid >> 4;
    const int bm = blockIdx.y * 128;
    const int bn = blockIdx.x * 128;

    float acc[8][8];
#pragma unroll
    for (int i = 0; i < 8; i++)
#pragma unroll
        for (int j = 0; j < 8; j++) acc[i][j] = 0.f;

    for (int k0 = 0; k0 < EMB; k0 += 16) {
#pragma unroll
        for (int l = 0; l < 2; l++) {
            int idx = tid + l * 256;       // 0..511
            int row = idx >> 2;            // 0..127
            int q   = (idx & 3) << 2;      // 0,4,8,12
            float4 va = *(const float4*)(A  + (size_t)(bm + row) * EMB + k0 + q);
            As[q + 0][row] = va.x; As[q + 1][row] = va.y;
            As[q + 2][row] = va.z; As[q + 3][row] = va.w;
            float4 vb = *(const float4*)(Wt + (size_t)(bn + row) * EMB + k0 + q);
            Bs[q + 0][row] = vb.x; Bs[q + 1][row] = vb.y;
            Bs[q + 2][row] = vb.z; Bs[q + 3][row] = vb.w;
        }
        __syncthreads();

#pragma unroll
        for (int kk = 0; kk < 16; kk++) {
            float4 a0 = *(const float4*)&As[kk][ty * 4];
            float4 a1 = *(const float4*)&As[kk][64 + ty * 4];
            float4 b0 = *(const float4*)&Bs[kk][tx * 4];
            float4 b1 = *(const float4*)&Bs[kk][64 + tx * 4];
            float ar[8] = {a0.x, a0.y, a0.z, a0.w, a1.x, a1.y, a1.z, a1.w};
            float br[8] = {b0.x, b0.y, b0.z, b0.w, b1.x, b1.y, b1.z, b1.w};
#pragma unroll
            for (int i = 0; i < 8; i++)
#pragma unroll
                for (int j = 0; j < 8; j++)
                    acc[i][j] += ar[i] * br[j];
        }
        __syncthreads();
    }

    // epilogue
#pragma unroll
    for (int i = 0; i < 8; i++) {
        int m = bm + ((i < 4) ? (ty * 4 + i) : (64 + ty * 4 + i - 4));
#pragma unroll
        for (int cj = 0; cj < 2; cj++) {
            int cb = bn + cj * 64 + tx * 4;
            float4 bv = *(const float4*)(bias + cb);
            float4 o;
            o.x = acc[i][cj * 4 + 0] + bv.x;
            o.y = acc[i][cj * 4 + 1] + bv.y;
            o.z = acc[i][cj * 4 + 2] + bv.z;
            o.w = acc[i][cj * 4 + 3] + bv.w;
            if (scatterDst == 0) {
                *(float4*)(Cout + (size_t)m * EMB + cb) = o;
            } else {
                int b = m >> 11;          // m / SEQ
                int s = m & (SEQ - 1);
                int h = cb >> 6;          // cb / HD
                int d = cb & (HD - 1);
                float* dst = (scatterDst == 1) ? g_Q : (scatterDst == 2) ? g_K : g_V;
                *(float4*)(dst + (((size_t)(b * NH + h)) * SEQ + s) * HD + d) = o;
            }
        }
    }
}

// ---------------------------------------------------------------------------
// Flash attention: per (bh, q-tile of 128). Keys/values tiled by 64.
// 256 threads, 8x4 micro-tiles on the 128x64 score tile. fp32 everywhere.
// ---------------------------------------------------------------------------
#define PSTR 68   // padded P row stride (floats): conflict-free STS.128

__global__ __launch_bounds__(256, 2) void attn_kernel()
{
    extern __shared__ __align__(16) float sh[];
    float* Qs   = sh;                 // [64][128]  Qs[d*128 + i]  (d-major)
    float* Ks   = Qs + 64 * 128;      // [64][64]   Ks[d*64  + j]  (d-major)
    float* Vs   = Ks + 64 * 64;       // [64][64]   Vs[j*64  + d]  (row-major)
    float* Ps   = Vs + 64 * 64;       // [128][PSTR] Ps[i*PSTR + j]
    float* mrow = Ps + 128 * PSTR;    // [128]
    float* lrow = mrow + 128;         // [128]
    float* srow = lrow + 128;         // [128]
    float* pred = srow + 128;         // [128][2]

    const int tid = threadIdx.x;
    const int tx  = tid & 15;
    const int ty  = tid >> 4;
    const int bh  = blockIdx.y;       // 0..63
    const int it  = blockIdx.x;       // q tile 0..15

    const float* Qg = g_Q + ((size_t)bh * SEQ + (size_t)it * 128) * HD;
    const float* Kg = g_K + (size_t)bh * SEQ * HD;
    const float* Vg = g_V + (size_t)bh * SEQ * HD;

    // load Q tile transposed into Qs[d][i]
#pragma unroll
    for (int l = 0; l < 8; l++) {
        int idx = tid + l * 256;       // 0..2047
        int row = idx >> 4;            // 0..127
        int q   = (idx & 15) << 2;     // 0..60
        float4 v = *(const float4*)(Qg + (size_t)row * HD + q);
        Qs[(q + 0) * 128 + row] = v.x;
        Qs[(q + 1) * 128 + row] = v.y;
        Qs[(q + 2) * 128 + row] = v.z;
        Qs[(q + 3) * 128 + row] = v.w;
    }
    if (tid < 128) { mrow[tid] = -1e30f; lrow[tid] = 0.f; }

    float o[8][4];
#pragma unroll
    for (int i = 0; i < 8; i++)
#pragma unroll
        for (int c = 0; c < 4; c++) o[i][c] = 0.f;

    for (int jt = 0; jt < SEQ / 64; jt++) {
        __syncthreads();   // protect Ks/Vs/Ps from previous iteration's readers

        const float* kg = Kg + (size_t)jt * 64 * HD;
        const float* vg = Vg + (size_t)jt * 64 * HD;
#pragma unroll
        for (int l = 0; l < 4; l++) {
            int idx = tid + l * 256;   // 0..1023
            int row = idx >> 4;        // 0..63
            int q   = (idx & 15) << 2;
            float4 v = *(const float4*)(kg + (size_t)row * HD + q);
            Ks[(q + 0) * 64 + row] = v.x;
            Ks[(q + 1) * 64 + row] = v.y;
            Ks[(q + 2) * 64 + row] = v.z;
            Ks[(q + 3) * 64 + row] = v.w;
            float4 w = *(const float4*)(vg + (size_t)row * HD + q);
            *(float4*)&Vs[row * 64 + q] = w;
        }
        __syncthreads();

        // S = Q K^T  (128x64 tile, micro 8 rows x 4 cols)
        float sacc[8][4];
#pragma unroll
        for (int i = 0; i < 8; i++)
#pragma unroll
            for (int c = 0; c < 4; c++) sacc[i][c] = 0.f;

#pragma unroll 8
        for (int d = 0; d < HD; d++) {
            float4 q0 = *(const float4*)&Qs[d * 128 + ty * 4];
            float4 q1 = *(const float4*)&Qs[d * 128 + 64 + ty * 4];
            float4 k0 = *(const float4*)&Ks[d * 64 + tx * 4];
            float aq[8] = {q0.x, q0.y, q0.z, q0.w, q1.x, q1.y, q1.z, q1.w};
            float bk[4] = {k0.x, k0.y, k0.z, k0.w};
#pragma unroll
            for (int i = 0; i < 8; i++)
#pragma unroll
                for (int c = 0; c < 4; c++)
                    sacc[i][c] += aq[i] * bk[c];
        }

        // write scaled scores to Ps (row-major, conflict-free STS.128)
        const float sc = 0.125f;   // 1/sqrt(64)
#pragma unroll
        for (int i = 0; i < 8; i++) {
            int irow = (i < 4) ? (ty * 4 + i) : (64 + ty * 4 + i - 4);
            float4 p;
            p.x = sacc[i][0] * sc; p.y = sacc[i][1] * sc;
            p.z = sacc[i][2] * sc; p.w = sacc[i][3] * sc;
            *(float4*)&Ps[irow * PSTR + tx * 4] = p;
        }
        __syncthreads();

        // online softmax: 2 threads per row, interleaved columns
        {
            int i = tid >> 1, half = tid & 1;
            float mloc = -1e30f;
#pragma unroll 8
            for (int j = half; j < 64; j += 2)
                mloc = fmaxf(mloc, Ps[i * PSTR + j]);
            pred[i * 2 + half] = mloc;
            __syncthreads();
            float mold = mrow[i];
            float mnew = fmaxf(mold, fmaxf(pred[i * 2], pred[i * 2 + 1]));
            float ssum = 0.f;
#pragma unroll 8
            for (int j = half; j < 64; j += 2) {
                float p = __expf(Ps[i * PSTR + j] - mnew);
                Ps[i * PSTR + j] = p;
                ssum += p;
            }
            pred[i * 2 + half] = ssum;
            __syncthreads();
            if (half == 0) {
                float scl = __expf(mold - mnew);
                lrow[i] = lrow[i] * scl + pred[i * 2] + pred[i * 2 + 1];
                mrow[i] = mnew;
                srow[i] = scl;
            }
        }
        __syncthreads();

        // rescale O and accumulate O += P V
#pragma unroll
        for (int i = 0; i < 8; i++) {
            int irow = (i < 4) ? (ty * 4 + i) : (64 + ty * 4 + i - 4);
            float scl = srow[irow];
#pragma unroll
            for (int c = 0; c < 4; c++) o[i][c] *= scl;
        }

#pragma unroll 2
        for (int j0 = 0; j0 < 64; j0 += 4) {
            float pfr[8][4];
            float vfr[4][4];
#pragma unroll
            for (int i = 0; i < 8; i++) {
                int irow = (i < 4) ? (ty * 4 + i) : (64 + ty * 4 + i - 4);
                *(float4*)pfr[i] = *(const float4*)&Ps[irow * PSTR + j0];
            }
#pragma unroll
            for (int jj = 0; jj < 4; jj++)
                *(float4*)vfr[jj] = *(const float4*)&Vs[(j0 + jj) * 64 + tx * 4];
#pragma unroll
            for (int jj = 0; jj < 4; jj++)
#pragma unroll
                for (int i = 0; i < 8; i++)
#pragma unroll
                    for (int c = 0; c < 4; c++)
                        o[i][c] += pfr[i][jj] * vfr[jj][c];
        }
    }

    // epilogue: normalize and write to g_O in [b, s, e] layout
    const int b = bh >> 4;     // bh / NH
    const int h = bh & (NH - 1);
#pragma unroll
    for (int i = 0; i < 8; i++) {
        int irow = (i < 4) ? (ty * 4 + i) : (64 + ty * 4 + i - 4);
        float inv = 1.f / lrow[irow];
        int sg = it * 128 + irow;
        float4 ov;
        ov.x = o[i][0] * inv; ov.y = o[i][1] * inv;
        ov.z = o[i][2] * inv; ov.w = o[i][3] * inv;
        *(float4*)(g_O + ((size_t)(b * SEQ + sg)) * EMB + h * HD + tx * 4) = ov;
    }
}

// ---------------------------------------------------------------------------

#define ATTN_SMEM_FLOATS (64 * 128 + 64 * 64 + 64 * 64 + 128 * PSTR + 128 * 3 + 256)
#define ATTN_SMEM_BYTES  (ATTN_SMEM_FLOATS * 4)

extern "C" void kernel_launch(void* const* d_in, const int* in_sizes, int n_in,
                              void* d_out, int out_size)
{
    (void)in_sizes; (void)n_in; (void)out_size;
    const float* x   = (const float*)d_in[0];
    const float* w_q = (const float*)d_in[1];
    const float* b_q = (const float*)d_in[2];
    const float* w_k = (const float*)d_in[3];
    const float* b_k = (const float*)d_in[4];
    const float* w_v = (const float*)d_in[5];
    const float* b_v = (const float*)d_in[6];
    const float* w_o = (const float*)d_in[7];
    const float* b_o = (const float*)d_in[8];
    float* out = (float*)d_out;

    cudaFuncSetAttribute(attn_kernel, cudaFuncAttributeMaxDynamicSharedMemorySize,
                         ATTN_SMEM_BYTES);

    dim3 gsz(EMB / 128, TOK / 128);   // (8, 64)
    gemm_bias_kernel<<<gsz, 256>>>(x, w_q, b_q, nullptr, 0, 1);
    gemm_bias_kernel<<<gsz, 256>>>(x, w_k, b_k, nullptr, 0, 2);
    gemm_bias_kernel<<<gsz, 256>>>(x, w_v, b_v, nullptr, 0, 3);

    attn_kernel<<<dim3(SEQ / 128, BHN), 256, ATTN_SMEM_BYTES>>>();

    gemm_bias_kernel<<<gsz, 256>>>(nullptr, w_o, b_o, out, 1, 0);
}

// round 3
// speedup vs baseline: 1.3905x; 1.3905x over previous
#include <cuda_runtime.h>
#include <cuda_bf16.h>
#include <cstdint>
#include <math.h>

#define SEQ 2048
#define EMB 1024
#define NH  16
#define HD  64
#define NB  4
#define TOK (NB * SEQ)     // 8192
#define BHN (NB * NH)      // 64

// Scratch (device globals: allocation-free rule)
__device__ __align__(128) float g_Q[(size_t)BHN * SEQ * HD];
__device__ __align__(128) float g_K[(size_t)BHN * SEQ * HD];
__device__ __align__(128) float g_V[(size_t)BHN * SEQ * HD];
__device__ __align__(128) float g_O[(size_t)TOK * EMB];

// ---------------------------------------------------------------------------
// mma.sync helpers (base-target tensor core path; tcgen05 is rejected because
// the harness compiles at the sm_103 family target, not sm_103a)
// ---------------------------------------------------------------------------
__device__ __forceinline__ uint32_t smem_to_u32(const void* p) {
    uint32_t a;
    asm("{ .reg .u64 t; cvta.to.shared.u64 t, %1; cvt.u32.u64 %0, t; }" : "=r"(a) : "l"(p));
    return a;
}
__device__ __forceinline__ void ldsm_x4(uint32_t* r, uint32_t addr) {
    asm volatile("ldmatrix.sync.aligned.m8n8.x4.shared.b16 {%0,%1,%2,%3}, [%4];"
        : "=r"(r[0]), "=r"(r[1]), "=r"(r[2]), "=r"(r[3]) : "r"(addr));
}
__device__ __forceinline__ void mma16816(float* c, const uint32_t* a, const uint32_t* b) {
    asm volatile("mma.sync.aligned.m16n8k16.row.col.f32.bf16.bf16.f32 "
        "{%0,%1,%2,%3}, {%4,%5,%6,%7}, {%8,%9}, {%0,%1,%2,%3};"
        : "+f"(c[0]), "+f"(c[1]), "+f"(c[2]), "+f"(c[3])
        : "r"(a[0]), "r"(a[1]), "r"(a[2]), "r"(a[3]), "r"(b[0]), "r"(b[1]));
}

__device__ __forceinline__ void cvt2_hilo(float x, float y, uint32_t& hi, uint32_t& lo) {
    __nv_bfloat162 h = __floats2bfloat162_rn(x, y);
    float hx = __bfloat162float(h.x);
    float hy = __bfloat162float(h.y);
    __nv_bfloat162 l = __floats2bfloat162_rn(x - hx, y - hy);
    hi = *reinterpret_cast<uint32_t*>(&h);
    lo = *reinterpret_cast<uint32_t*>(&l);
}

// ---------------------------------------------------------------------------
// HMMA GEMM: C[m,n] = sum_k A[m,k] * W[n,k] + bias[n]
// M=8192, N=1024, K=1024. CTA 128x128, BK=32, 8 warps (warp tile 32x64).
// bf16 hi/lo split: 3 MMA products per fragment pair (fp32-grade accuracy).
// scatterDst: 0 plain (Cout), 1/2/3 -> g_Q/g_K/g_V in [b*H+h, s, d] layout.
// ---------------------------------------------------------------------------
#define ASTRB 80           // smem row stride in bytes (32 bf16 + 8 pad)
#define OFF_AHI 0
#define OFF_ALO 10240
#define OFF_BHI 20480
#define OFF_BLO 30720

__global__ __launch_bounds__(256, 2) void gemm_tc_kernel(
    const float* __restrict__ Ain,
    const float* __restrict__ Wt,
    const float* __restrict__ bias,
    float* __restrict__ Cout,
    int srcIsO, int scatterDst)
{
    __shared__ __align__(16) char smem[40960];
    uint32_t sb = smem_to_u32(smem);
    const float* A = srcIsO ? g_O : Ain;

    const int tid  = threadIdx.x;
    const int lane = tid & 31;
    const int w    = tid >> 5;
    const int wm   = w & 3;          // 0..3 : 32-row M slice
    const int wn   = w >> 2;         // 0..1 : 64-col N slice
    const int bm   = blockIdx.y * 128;
    const int bn   = blockIdx.x * 128;

    float acc[2][8][4];
#pragma unroll
    for (int i = 0; i < 2; i++)
#pragma unroll
        for (int j = 0; j < 8; j++)
#pragma unroll
            for (int c = 0; c < 4; c++) acc[i][j][c] = 0.f;

    // ldmatrix addresses (within-warp, fixed per thread)
    // A x4: row = lane&15, byte col = (lane>>4)*16
    const int a_row = lane & 15;
    const int a_co  = (lane >> 4) * 16;
    // B x4: row = ((lane>>4)&1)*8 + (lane&7), byte col = ((lane>>3)&1)*16
    const int b_row = ((lane >> 4) & 1) * 8 + (lane & 7);
    const int b_co  = ((lane >> 3) & 1) * 16;

    for (int kc = 0; kc < EMB / 32; kc++) {
        const int k0 = kc * 32;
        __syncthreads();   // protect smem from previous iteration's readers

        // stage A/B chunk: 128 rows x 32 cols fp32 -> bf16 hi/lo
#pragma unroll
        for (int l = 0; l < 4; l++) {
            int idx = tid + l * 256;        // 0..1023
            int row = idx >> 3;             // 0..127
            int kk  = (idx & 7) * 4;        // 0,4,..,28
            uint32_t soff = (uint32_t)(row * ASTRB + kk * 2);

            float4 va = *(const float4*)(A + (size_t)(bm + row) * EMB + k0 + kk);
            uint2 hi, lo;
            cvt2_hilo(va.x, va.y, hi.x, lo.x);
            cvt2_hilo(va.z, va.w, hi.y, lo.y);
            *(uint2*)(smem + OFF_AHI + soff) = hi;
            *(uint2*)(smem + OFF_ALO + soff) = lo;

            float4 vb = *(const float4*)(Wt + (size_t)(bn + row) * EMB + k0 + kk);
            cvt2_hilo(vb.x, vb.y, hi.x, lo.x);
            cvt2_hilo(vb.z, vb.w, hi.y, lo.y);
            *(uint2*)(smem + OFF_BHI + soff) = hi;
            *(uint2*)(smem + OFF_BLO + soff) = lo;
        }
        __syncthreads();

#pragma unroll
        for (int ks = 0; ks < 2; ks++) {
            uint32_t ah[2][4], al[2][4];
#pragma unroll
            for (int mi = 0; mi < 2; mi++) {
                uint32_t ad = sb + (uint32_t)((wm * 32 + mi * 16 + a_row) * ASTRB
                                              + ks * 32 + a_co);
                ldsm_x4(ah[mi], ad + OFF_AHI);
                ldsm_x4(al[mi], ad + OFF_ALO);
            }
#pragma unroll
            for (int np = 0; np < 4; np++) {
                uint32_t bh[4], bl[4];
                uint32_t bd = sb + (uint32_t)((wn * 64 + np * 16 + b_row) * ASTRB
                                              + ks * 32 + b_co);
                ldsm_x4(bh, bd + OFF_BHI);
                ldsm_x4(bl, bd + OFF_BLO);
#pragma unroll
                for (int sub = 0; sub < 2; sub++) {
#pragma unroll
                    for (int mi = 0; mi < 2; mi++) {
                        float* c = acc[mi][np * 2 + sub];
                        mma16816(c, ah[mi], &bh[sub * 2]);   // hi*hi
                        mma16816(c, ah[mi], &bl[sub * 2]);   // hi*lo
                        mma16816(c, al[mi], &bh[sub * 2]);   // lo*hi
                    }
                }
            }
        }
    }

    // epilogue: C fragment -> bias add -> (scatter) store, float2 per element pair
#pragma unroll
    for (int mi = 0; mi < 2; mi++) {
#pragma unroll
        for (int nf = 0; nf < 8; nf++) {
            int col = bn + wn * 64 + nf * 8 + (lane & 3) * 2;
            float2 bv = *(const float2*)(bias + col);
#pragma unroll
            for (int h = 0; h < 2; h++) {
                int m = bm + wm * 32 + mi * 16 + (lane >> 2) + h * 8;
                float2 o;
                o.x = acc[mi][nf][h * 2 + 0] + bv.x;
                o.y = acc[mi][nf][h * 2 + 1] + bv.y;
                if (scatterDst == 0) {
                    *(float2*)(Cout + (size_t)m * EMB + col) = o;
                } else {
                    int b = m >> 11;
                    int s = m & (SEQ - 1);
                    int hh = col >> 6;
                    int d  = col & (HD - 1);
                    float* dst = (scatterDst == 1) ? g_Q : (scatterDst == 2) ? g_K : g_V;
                    *(float2*)(dst + (((size_t)(b * NH + hh)) * SEQ + s) * HD + d) = o;
                }
            }
        }
    }
}

// ---------------------------------------------------------------------------
// Flash attention (unchanged from R1): per (bh, q-tile of 128), KV tiles of 64.
// ---------------------------------------------------------------------------
#define PSTR 68

__global__ __launch_bounds__(256, 2) void attn_kernel()
{
    extern __shared__ __align__(16) float sh[];
    float* Qs   = sh;                 // [64][128]
    float* Ks   = Qs + 64 * 128;      // [64][64]
    float* Vs   = Ks + 64 * 64;       // [64][64]
    float* Ps   = Vs + 64 * 64;       // [128][PSTR]
    float* mrow = Ps + 128 * PSTR;
    float* lrow = mrow + 128;
    float* srow = lrow + 128;
    float* pred = srow + 128;

    const int tid = threadIdx.x;
    const int tx  = tid & 15;
    const int ty  = tid >> 4;
    const int bh  = blockIdx.y;
    const int it  = blockIdx.x;

    const float* Qg = g_Q + ((size_t)bh * SEQ + (size_t)it * 128) * HD;
    const float* Kg = g_K + (size_t)bh * SEQ * HD;
    const float* Vg = g_V + (size_t)bh * SEQ * HD;

#pragma unroll
    for (int l = 0; l < 8; l++) {
        int idx = tid + l * 256;
        int row = idx >> 4;
        int q   = (idx & 15) << 2;
        float4 v = *(const float4*)(Qg + (size_t)row * HD + q);
        Qs[(q + 0) * 128 + row] = v.x;
        Qs[(q + 1) * 128 + row] = v.y;
        Qs[(q + 2) * 128 + row] = v.z;
        Qs[(q + 3) * 128 + row] = v.w;
    }
    if (tid < 128) { mrow[tid] = -1e30f; lrow[tid] = 0.f; }

    float o[8][4];
#pragma unroll
    for (int i = 0; i < 8; i++)
#pragma unroll
        for (int c = 0; c < 4; c++) o[i][c] = 0.f;

    for (int jt = 0; jt < SEQ / 64; jt++) {
        __syncthreads();

        const float* kg = Kg + (size_t)jt * 64 * HD;
        const float* vg = Vg + (size_t)jt * 64 * HD;
#pragma unroll
        for (int l = 0; l < 4; l++) {
            int idx = tid + l * 256;
            int row = idx >> 4;
            int q   = (idx & 15) << 2;
            float4 v = *(const float4*)(kg + (size_t)row * HD + q);
            Ks[(q + 0) * 64 + row] = v.x;
            Ks[(q + 1) * 64 + row] = v.y;
            Ks[(q + 2) * 64 + row] = v.z;
            Ks[(q + 3) * 64 + row] = v.w;
            float4 w = *(const float4*)(vg + (size_t)row * HD + q);
            *(float4*)&Vs[row * 64 + q] = w;
        }
        __syncthreads();

        float sacc[8][4];
#pragma unroll
        for (int i = 0; i < 8; i++)
#pragma unroll
            for (int c = 0; c < 4; c++) sacc[i][c] = 0.f;

#pragma unroll 8
        for (int d = 0; d < HD; d++) {
            float4 q0 = *(const float4*)&Qs[d * 128 + ty * 4];
            float4 q1 = *(const float4*)&Qs[d * 128 + 64 + ty * 4];
            float4 k0 = *(const float4*)&Ks[d * 64 + tx * 4];
            float aq[8] = {q0.x, q0.y, q0.z, q0.w, q1.x, q1.y, q1.z, q1.w};
            float bk[4] = {k0.x, k0.y, k0.z, k0.w};
#pragma unroll
            for (int i = 0; i < 8; i++)
#pragma unroll
                for (int c = 0; c < 4; c++)
                    sacc[i][c] += aq[i] * bk[c];
        }

        const float sc = 0.125f;
#pragma unroll
        for (int i = 0; i < 8; i++) {
            int irow = (i < 4) ? (ty * 4 + i) : (64 + ty * 4 + i - 4);
            float4 p;
            p.x = sacc[i][0] * sc; p.y = sacc[i][1] * sc;
            p.z = sacc[i][2] * sc; p.w = sacc[i][3] * sc;
            *(float4*)&Ps[irow * PSTR + tx * 4] = p;
        }
        __syncthreads();

        {
            int i = tid >> 1, half = tid & 1;
            float mloc = -1e30f;
#pragma unroll 8
            for (int j = half; j < 64; j += 2)
                mloc = fmaxf(mloc, Ps[i * PSTR + j]);
            pred[i * 2 + half] = mloc;
            __syncthreads();
            float mold = mrow[i];
            float mnew = fmaxf(mold, fmaxf(pred[i * 2], pred[i * 2 + 1]));
            float ssum = 0.f;
#pragma unroll 8
            for (int j = half; j < 64; j += 2) {
                float p = __expf(Ps[i * PSTR + j] - mnew);
                Ps[i * PSTR + j] = p;
                ssum += p;
            }
            pred[i * 2 + half] = ssum;
            __syncthreads();
            if (half == 0) {
                float scl = __expf(mold - mnew);
                lrow[i] = lrow[i] * scl + pred[i * 2] + pred[i * 2 + 1];
                mrow[i] = mnew;
                srow[i] = scl;
            }
        }
        __syncthreads();

#pragma unroll
        for (int i = 0; i < 8; i++) {
            int irow = (i < 4) ? (ty * 4 + i) : (64 + ty * 4 + i - 4);
            float scl = srow[irow];
#pragma unroll
            for (int c = 0; c < 4; c++) o[i][c] *= scl;
        }

#pragma unroll 2
        for (int j0 = 0; j0 < 64; j0 += 4) {
            float pfr[8][4];
            float vfr[4][4];
#pragma unroll
            for (int i = 0; i < 8; i++) {
                int irow = (i < 4) ? (ty * 4 + i) : (64 + ty * 4 + i - 4);
                *(float4*)pfr[i] = *(const float4*)&Ps[irow * PSTR + j0];
            }
#pragma unroll
            for (int jj = 0; jj < 4; jj++)
                *(float4*)vfr[jj] = *(const float4*)&Vs[(j0 + jj) * 64 + tx * 4];
#pragma unroll
            for (int jj = 0; jj < 4; jj++)
#pragma unroll
                for (int i = 0; i < 8; i++)
#pragma unroll
                    for (int c = 0; c < 4; c++)
                        o[i][c] += pfr[i][jj] * vfr[jj][c];
        }
    }

    const int b = bh >> 4;
    const int h = bh & (NH - 1);
#pragma unroll
    for (int i = 0; i < 8; i++) {
        int irow = (i < 4) ? (ty * 4 + i) : (64 + ty * 4 + i - 4);
        float inv = 1.f / lrow[irow];
        int sg = it * 128 + irow;
        float4 ov;
        ov.x = o[i][0] * inv; ov.y = o[i][1] * inv;
        ov.z = o[i][2] * inv; ov.w = o[i][3] * inv;
        *(float4*)(g_O + ((size_t)(b * SEQ + sg)) * EMB + h * HD + tx * 4) = ov;
    }
}

// ---------------------------------------------------------------------------

#define ATTN_SMEM_FLOATS (64 * 128 + 64 * 64 + 64 * 64 + 128 * PSTR + 128 * 3 + 256)
#define ATTN_SMEM_BYTES  (ATTN_SMEM_FLOATS * 4)

extern "C" void kernel_launch(void* const* d_in, const int* in_sizes, int n_in,
                              void* d_out, int out_size)
{
    (void)in_sizes; (void)n_in; (void)out_size;
    const float* x   = (const float*)d_in[0];
    const float* w_q = (const float*)d_in[1];
    const float* b_q = (const float*)d_in[2];
    const float* w_k = (const float*)d_in[3];
    const float* b_k = (const float*)d_in[4];
    const float* w_v = (const float*)d_in[5];
    const float* b_v = (const float*)d_in[6];
    const float* w_o = (const float*)d_in[7];
    const float* b_o = (const float*)d_in[8];
    float* out = (float*)d_out;

    cudaFuncSetAttribute(attn_kernel, cudaFuncAttributeMaxDynamicSharedMemorySize,
                         ATTN_SMEM_BYTES);

    dim3 gsz(EMB / 128, TOK / 128);   // (8, 64)
    gemm_tc_kernel<<<gsz, 256>>>(x, w_q, b_q, nullptr, 0, 1);
    gemm_tc_kernel<<<gsz, 256>>>(x, w_k, b_k, nullptr, 0, 2);
    gemm_tc_kernel<<<gsz, 256>>>(x, w_v, b_v, nullptr, 0, 3);

    attn_kernel<<<dim3(SEQ / 128, BHN), 256, ATTN_SMEM_BYTES>>>();

    gemm_tc_kernel<<<gsz, 256>>>(nullptr, w_o, b_o, out, 1, 0);
}

// round 4
// speedup vs baseline: 3.8395x; 2.7611x over previous
#include <cuda_runtime.h>
#include <cuda_bf16.h>
#include <cuda_fp16.h>
#include <cstdint>
#include <math.h>

#define SEQ 2048
#define EMB 1024
#define NH  16
#define HD  64
#define NB  4
#define TOK (NB * SEQ)     // 8192
#define BHN (NB * NH)      // 64

// Scratch (device globals: allocation-free rule)
__device__ __align__(128) __half g_Qh[(size_t)BHN * SEQ * HD];
__device__ __align__(128) __half g_Kh[(size_t)BHN * SEQ * HD];
__device__ __align__(128) __half g_Vh[(size_t)BHN * SEQ * HD];
__device__ __align__(128) float  g_O [(size_t)TOK * EMB];

// ---------------------------------------------------------------------------
// mma.sync helpers (base-target tensor core path)
// ---------------------------------------------------------------------------
__device__ __forceinline__ uint32_t smem_to_u32(const void* p) {
    uint32_t a;
    asm("{ .reg .u64 t; cvta.to.shared.u64 t, %1; cvt.u32.u64 %0, t; }" : "=r"(a) : "l"(p));
    return a;
}
__device__ __forceinline__ void ldsm_x4(uint32_t* r, uint32_t addr) {
    asm volatile("ldmatrix.sync.aligned.m8n8.x4.shared.b16 {%0,%1,%2,%3}, [%4];"
        : "=r"(r[0]), "=r"(r[1]), "=r"(r[2]), "=r"(r[3]) : "r"(addr));
}
__device__ __forceinline__ void ldsm_x4_t(uint32_t* r, uint32_t addr) {
    asm volatile("ldmatrix.sync.aligned.m8n8.x4.trans.shared.b16 {%0,%1,%2,%3}, [%4];"
        : "=r"(r[0]), "=r"(r[1]), "=r"(r[2]), "=r"(r[3]) : "r"(addr));
}
__device__ __forceinline__ void mma16816bf(float* c, const uint32_t* a, const uint32_t* b) {
    asm volatile("mma.sync.aligned.m16n8k16.row.col.f32.bf16.bf16.f32 "
        "{%0,%1,%2,%3}, {%4,%5,%6,%7}, {%8,%9}, {%0,%1,%2,%3};"
        : "+f"(c[0]), "+f"(c[1]), "+f"(c[2]), "+f"(c[3])
        : "r"(a[0]), "r"(a[1]), "r"(a[2]), "r"(a[3]), "r"(b[0]), "r"(b[1]));
}
__device__ __forceinline__ void mma16816h(float* c, const uint32_t* a, const uint32_t* b) {
    asm volatile("mma.sync.aligned.m16n8k16.row.col.f32.f16.f16.f32 "
        "{%0,%1,%2,%3}, {%4,%5,%6,%7}, {%8,%9}, {%0,%1,%2,%3};"
        : "+f"(c[0]), "+f"(c[1]), "+f"(c[2]), "+f"(c[3])
        : "r"(a[0]), "r"(a[1]), "r"(a[2]), "r"(a[3]), "r"(b[0]), "r"(b[1]));
}
__device__ __forceinline__ float ex2f(float x) {
    float r;
    asm("ex2.approx.f32 %0, %1;" : "=f"(r) : "f"(x));
    return r;
}
__device__ __forceinline__ void cvt2_hilo(float x, float y, uint32_t& hi, uint32_t& lo) {
    __nv_bfloat162 h = __floats2bfloat162_rn(x, y);
    float hx = __bfloat162float(h.x);
    float hy = __bfloat162float(h.y);
    __nv_bfloat162 l = __floats2bfloat162_rn(x - hx, y - hy);
    hi = *reinterpret_cast<uint32_t*>(&h);
    lo = *reinterpret_cast<uint32_t*>(&l);
}

// Q pre-scale: 1/sqrt(HD) * log2(e), folded so attention uses ex2 directly
#define QSCALE 0.1803368801111244f

// ---------------------------------------------------------------------------
// HMMA GEMM: C[m,n] = sum_k A[m,k] * W[n,k] + bias[n]
// M=8192, N=1024, K=1024. CTA 128x128, BK=32, 8 warps (warp tile 32x64).
// bf16 hi/lo split: 3 MMA products (fp32-grade accuracy).
// scatterDst: 0 plain fp32 (Cout), 1/2/3 -> g_Qh/g_Kh/g_Vh as fp16
// in [b*H+h, s, d] layout (Q additionally scaled by QSCALE).
// ---------------------------------------------------------------------------
#define ASTRB 80           // smem row stride in bytes (32 bf16 + 8 pad)
#define OFF_AHI 0
#define OFF_ALO 10240
#define OFF_BHI 20480
#define OFF_BLO 30720

__global__ __launch_bounds__(256, 2) void gemm_tc_kernel(
    const float* __restrict__ Ain,
    const float* __restrict__ Wt,
    const float* __restrict__ bias,
    float* __restrict__ Cout,
    int srcIsO, int scatterDst)
{
    __shared__ __align__(16) char smem[40960];
    uint32_t sb = smem_to_u32(smem);
    const float* A = srcIsO ? g_O : Ain;

    const int tid  = threadIdx.x;
    const int lane = tid & 31;
    const int w    = tid >> 5;
    const int wm   = w & 3;
    const int wn   = w >> 2;
    const int bm   = blockIdx.y * 128;
    const int bn   = blockIdx.x * 128;

    float acc[2][8][4];
#pragma unroll
    for (int i = 0; i < 2; i++)
#pragma unroll
        for (int j = 0; j < 8; j++)
#pragma unroll
            for (int c = 0; c < 4; c++) acc[i][j][c] = 0.f;

    const int a_row = lane & 15;
    const int a_co  = (lane >> 4) * 16;
    const int b_row = ((lane >> 4) & 1) * 8 + (lane & 7);
    const int b_co  = ((lane >> 3) & 1) * 16;

    for (int kc = 0; kc < EMB / 32; kc++) {
        const int k0 = kc * 32;
        __syncthreads();

#pragma unroll
        for (int l = 0; l < 4; l++) {
            int idx = tid + l * 256;
            int row = idx >> 3;
            int kk  = (idx & 7) * 4;
            uint32_t soff = (uint32_t)(row * ASTRB + kk * 2);

            float4 va = *(const float4*)(A + (size_t)(bm + row) * EMB + k0 + kk);
            uint2 hi, lo;
            cvt2_hilo(va.x, va.y, hi.x, lo.x);
            cvt2_hilo(va.z, va.w, hi.y, lo.y);
            *(uint2*)(smem + OFF_AHI + soff) = hi;
            *(uint2*)(smem + OFF_ALO + soff) = lo;

            float4 vb = *(const float4*)(Wt + (size_t)(bn + row) * EMB + k0 + kk);
            cvt2_hilo(vb.x, vb.y, hi.x, lo.x);
            cvt2_hilo(vb.z, vb.w, hi.y, lo.y);
            *(uint2*)(smem + OFF_BHI + soff) = hi;
            *(uint2*)(smem + OFF_BLO + soff) = lo;
        }
        __syncthreads();

#pragma unroll
        for (int ks = 0; ks < 2; ks++) {
            uint32_t ah[2][4], al[2][4];
#pragma unroll
            for (int mi = 0; mi < 2; mi++) {
                uint32_t ad = sb + (uint32_t)((wm * 32 + mi * 16 + a_row) * ASTRB
                                              + ks * 32 + a_co);
                ldsm_x4(ah[mi], ad + OFF_AHI);
                ldsm_x4(al[mi], ad + OFF_ALO);
            }
#pragma unroll
            for (int np = 0; np < 4; np++) {
                uint32_t bh[4], bl[4];
                uint32_t bd = sb + (uint32_t)((wn * 64 + np * 16 + b_row) * ASTRB
                                              + ks * 32 + b_co);
                ldsm_x4(bh, bd + OFF_BHI);
                ldsm_x4(bl, bd + OFF_BLO);
#pragma unroll
                for (int sub = 0; sub < 2; sub++) {
#pragma unroll
                    for (int mi = 0; mi < 2; mi++) {
                        float* c = acc[mi][np * 2 + sub];
                        mma16816bf(c, ah[mi], &bh[sub * 2]);
                        mma16816bf(c, ah[mi], &bl[sub * 2]);
                        mma16816bf(c, al[mi], &bh[sub * 2]);
                    }
                }
            }
        }
    }

#pragma unroll
    for (int mi = 0; mi < 2; mi++) {
#pragma unroll
        for (int nf = 0; nf < 8; nf++) {
            int col = bn + wn * 64 + nf * 8 + (lane & 3) * 2;
            float2 bv = *(const float2*)(bias + col);
#pragma unroll
            for (int h = 0; h < 2; h++) {
                int m = bm + wm * 32 + mi * 16 + (lane >> 2) + h * 8;
                float2 o;
                o.x = acc[mi][nf][h * 2 + 0] + bv.x;
                o.y = acc[mi][nf][h * 2 + 1] + bv.y;
                if (scatterDst == 0) {
                    *(float2*)(Cout + (size_t)m * EMB + col) = o;
                } else {
                    int b = m >> 11;
                    int s = m & (SEQ - 1);
                    int hh = col >> 6;
                    int d  = col & (HD - 1);
                    float sc = (scatterDst == 1) ? QSCALE : 1.0f;
                    __half2 hv = __floats2half2_rn(o.x * sc, o.y * sc);
                    __half* dst = (scatterDst == 1) ? g_Qh : (scatterDst == 2) ? g_Kh : g_Vh;
                    *(__half2*)(dst + (((size_t)(b * NH + hh)) * SEQ + s) * HD + d) = hv;
                }
            }
        }
    }
}

// ---------------------------------------------------------------------------
// Tensor-core flash attention (fp16 mma, FA2-style warp-owns-rows).
// CTA = 128 threads (4 warps); each warp owns 16 q rows; CTA tile = 64 q rows.
// KV tiles of 64. Softmax fully register/shfl-resident; S C-fragments are
// reinterpreted as P A-fragments (no smem round-trip).
// ---------------------------------------------------------------------------
#define HSTR 72            // smem row stride in halfs (64 + 8 pad) = 144B

__global__ __launch_bounds__(128, 4) void attn_tc_kernel()
{
    __shared__ __align__(16) __half Qs[64 * HSTR];
    __shared__ __align__(16) __half Ks[64 * HSTR];
    __shared__ __align__(16) __half Vs[64 * HSTR];

    const int tid  = threadIdx.x;
    const int lane = tid & 31;
    const int w    = tid >> 5;
    const int bh   = blockIdx.y;       // 0..63
    const int it   = blockIdx.x;       // q tile 0..31 (64 rows each)

    const uint32_t sQ = smem_to_u32(Qs);
    const uint32_t sK = smem_to_u32(Ks);
    const uint32_t sV = smem_to_u32(Vs);

    const __half* Qg = g_Qh + ((size_t)bh * SEQ + (size_t)it * 64) * HD;
    const __half* Kg = g_Kh + (size_t)bh * SEQ * HD;
    const __half* Vg = g_Vh + (size_t)bh * SEQ * HD;

    // load Q tile (64 rows x 64 halfs), 16B chunks
#pragma unroll
    for (int l = 0; l < 4; l++) {
        int idx = tid + l * 128;       // 0..511
        int row = idx >> 3;
        int ch  = (idx & 7) * 8;
        *(uint4*)&Qs[row * HSTR + ch] = *(const uint4*)(Qg + (size_t)row * HD + ch);
    }
    __syncthreads();

    // loop-invariant Q A-fragments: rows w*16 + (lane&15)
    const int a_row = lane & 15;
    const int a_co  = (lane >> 4) * 16;
    uint32_t qa[4][4];
#pragma unroll
    for (int ks = 0; ks < 4; ks++) {
        uint32_t ad = sQ + (uint32_t)((w * 16 + a_row) * (HSTR * 2) + ks * 32 + a_co);
        ldsm_x4(qa[ks], ad);
    }

    const int b_row = ((lane >> 4) & 1) * 8 + (lane & 7);
    const int b_co  = ((lane >> 3) & 1) * 16;
    const int v_row = lane & 15;
    const int v_co  = (lane >> 4) * 16;

    float o[8][4];
#pragma unroll
    for (int nf = 0; nf < 8; nf++)
#pragma unroll
        for (int c = 0; c < 4; c++) o[nf][c] = 0.f;
    float m0 = -1e30f, m1 = -1e30f, l0 = 0.f, l1 = 0.f;

    for (int jt = 0; jt < SEQ / 64; jt++) {
        __syncthreads();   // previous iteration's readers done
        const __half* kg = Kg + (size_t)jt * 64 * HD;
        const __half* vg = Vg + (size_t)jt * 64 * HD;
#pragma unroll
        for (int l = 0; l < 4; l++) {
            int idx = tid + l * 128;
            int row = idx >> 3;
            int ch  = (idx & 7) * 8;
            *(uint4*)&Ks[row * HSTR + ch] = *(const uint4*)(kg + (size_t)row * HD + ch);
            *(uint4*)&Vs[row * HSTR + ch] = *(const uint4*)(vg + (size_t)row * HD + ch);
        }
        __syncthreads();

        // S = Q K^T  (16 x 64 per warp)
        float s[8][4];
#pragma unroll
        for (int nf = 0; nf < 8; nf++)
#pragma unroll
            for (int c = 0; c < 4; c++) s[nf][c] = 0.f;
#pragma unroll
        for (int nt = 0; nt < 4; nt++) {
#pragma unroll
            for (int ks = 0; ks < 4; ks++) {
                uint32_t kb[4];
                uint32_t bd = sK + (uint32_t)((nt * 16 + b_row) * (HSTR * 2) + ks * 32 + b_co);
                ldsm_x4(kb, bd);
                mma16816h(s[nt * 2 + 0], qa[ks], &kb[0]);
                mma16816h(s[nt * 2 + 1], qa[ks], &kb[2]);
            }
        }

        // online softmax (rows r0=lane>>2, r1=r0+8; quad shfl reduce)
        float mx0 = -1e30f, mx1 = -1e30f;
#pragma unroll
        for (int nf = 0; nf < 8; nf++) {
            mx0 = fmaxf(mx0, fmaxf(s[nf][0], s[nf][1]));
            mx1 = fmaxf(mx1, fmaxf(s[nf][2], s[nf][3]));
        }
        mx0 = fmaxf(mx0, __shfl_xor_sync(0xffffffffu, mx0, 1));
        mx0 = fmaxf(mx0, __shfl_xor_sync(0xffffffffu, mx0, 2));
        mx1 = fmaxf(mx1, __shfl_xor_sync(0xffffffffu, mx1, 1));
        mx1 = fmaxf(mx1, __shfl_xor_sync(0xffffffffu, mx1, 2));

        float mn0 = fmaxf(m0, mx0);
        float mn1 = fmaxf(m1, mx1);
        float sc0 = ex2f(m0 - mn0);
        float sc1 = ex2f(m1 - mn1);

        float ps0 = 0.f, ps1 = 0.f;
#pragma unroll
        for (int nf = 0; nf < 8; nf++) {
            s[nf][0] = ex2f(s[nf][0] - mn0);
            s[nf][1] = ex2f(s[nf][1] - mn0);
            s[nf][2] = ex2f(s[nf][2] - mn1);
            s[nf][3] = ex2f(s[nf][3] - mn1);
            ps0 += s[nf][0] + s[nf][1];
            ps1 += s[nf][2] + s[nf][3];
        }
        ps0 += __shfl_xor_sync(0xffffffffu, ps0, 1);
        ps0 += __shfl_xor_sync(0xffffffffu, ps0, 2);
        ps1 += __shfl_xor_sync(0xffffffffu, ps1, 1);
        ps1 += __shfl_xor_sync(0xffffffffu, ps1, 2);

        l0 = l0 * sc0 + ps0;  m0 = mn0;
        l1 = l1 * sc1 + ps1;  m1 = mn1;

#pragma unroll
        for (int nf = 0; nf < 8; nf++) {
            o[nf][0] *= sc0; o[nf][1] *= sc0;
            o[nf][2] *= sc1; o[nf][3] *= sc1;
        }

        // P C-fragments -> A-fragments (register cvt)
        uint32_t pa[4][4];
#pragma unroll
        for (int kt = 0; kt < 4; kt++) {
            __half2 h0 = __floats2half2_rn(s[2 * kt][0],     s[2 * kt][1]);
            __half2 h1 = __floats2half2_rn(s[2 * kt][2],     s[2 * kt][3]);
            __half2 h2 = __floats2half2_rn(s[2 * kt + 1][0], s[2 * kt + 1][1]);
            __half2 h3 = __floats2half2_rn(s[2 * kt + 1][2], s[2 * kt + 1][3]);
            pa[kt][0] = *reinterpret_cast<uint32_t*>(&h0);
            pa[kt][1] = *reinterpret_cast<uint32_t*>(&h1);
            pa[kt][2] = *reinterpret_cast<uint32_t*>(&h2);
            pa[kt][3] = *reinterpret_cast<uint32_t*>(&h3);
        }

        // O += P V  (V via ldmatrix.trans from [k][n] layout)
#pragma unroll
        for (int kt = 0; kt < 4; kt++) {
#pragma unroll
            for (int nt = 0; nt < 4; nt++) {
                uint32_t vb[4];
                uint32_t vd = sV + (uint32_t)((kt * 16 + v_row) * (HSTR * 2) + nt * 32 + v_co);
                ldsm_x4_t(vb, vd);
                mma16816h(o[nt * 2 + 0], pa[kt], &vb[0]);
                mma16816h(o[nt * 2 + 1], pa[kt], &vb[2]);
            }
        }
    }

    // epilogue: normalize, write fp32 to g_O in [b, s, e] layout
    const int b = bh >> 4;
    const int h = bh & (NH - 1);
    const float inv0 = 1.f / l0;
    const float inv1 = 1.f / l1;
    const int r0 = it * 64 + w * 16 + (lane >> 2);
#pragma unroll
    for (int nf = 0; nf < 8; nf++) {
        int col = h * HD + nf * 8 + (lane & 3) * 2;
        float2 v0 = { o[nf][0] * inv0, o[nf][1] * inv0 };
        float2 v1 = { o[nf][2] * inv1, o[nf][3] * inv1 };
        *(float2*)(g_O + ((size_t)(b * SEQ + r0))     * EMB + col) = v0;
        *(float2*)(g_O + ((size_t)(b * SEQ + r0 + 8)) * EMB + col) = v1;
    }
}

// ---------------------------------------------------------------------------

extern "C" void kernel_launch(void* const* d_in, const int* in_sizes, int n_in,
                              void* d_out, int out_size)
{
    (void)in_sizes; (void)n_in; (void)out_size;
    const float* x   = (const float*)d_in[0];
    const float* w_q = (const float*)d_in[1];
    const float* b_q = (const float*)d_in[2];
    const float* w_k = (const float*)d_in[3];
    const float* b_k = (const float*)d_in[4];
    const float* w_v = (const float*)d_in[5];
    const float* b_v = (const float*)d_in[6];
    const float* w_o = (const float*)d_in[7];
    const float* b_o = (const float*)d_in[8];
    float* out = (float*)d_out;

    dim3 gsz(EMB / 128, TOK / 128);   // (8, 64)
    gemm_tc_kernel<<<gsz, 256>>>(x, w_q, b_q, nullptr, 0, 1);
    gemm_tc_kernel<<<gsz, 256>>>(x, w_k, b_k, nullptr, 0, 2);
    gemm_tc_kernel<<<gsz, 256>>>(x, w_v, b_v, nullptr, 0, 3);

    attn_tc_kernel<<<dim3(SEQ / 64, BHN), 128>>>();

    gemm_tc_kernel<<<gsz, 256>>>(nullptr, w_o, b_o, out, 1, 0);
}

// round 5
// speedup vs baseline: 4.4274x; 1.1531x over previous
#include <cuda_runtime.h>
#include <cuda_bf16.h>
#include <cuda_fp16.h>
#include <cstdint>
#include <math.h>

#define SEQ 2048
#define EMB 1024
#define NH  16
#define HD  64
#define NB  4
#define TOK (NB * SEQ)     // 8192
#define BHN (NB * NH)      // 64

// Scratch (device globals: allocation-free rule)
__device__ __align__(128) __half g_Qh[(size_t)BHN * SEQ * HD];
__device__ __align__(128) __half g_Kh[(size_t)BHN * SEQ * HD];
__device__ __align__(128) __half g_Vh[(size_t)BHN * SEQ * HD];
__device__ __align__(128) __nv_bfloat16 g_Xhi[(size_t)TOK * EMB];
__device__ __align__(128) __nv_bfloat16 g_Xlo[(size_t)TOK * EMB];
__device__ __align__(128) __nv_bfloat16 g_Ohi[(size_t)TOK * EMB];
__device__ __align__(128) __nv_bfloat16 g_Olo[(size_t)TOK * EMB];
__device__ __align__(128) __nv_bfloat16 g_Whi[(size_t)4 * EMB * EMB];
__device__ __align__(128) __nv_bfloat16 g_Wlo[(size_t)4 * EMB * EMB];

// ---------------------------------------------------------------------------
// PTX helpers
// ---------------------------------------------------------------------------
__device__ __forceinline__ uint32_t smem_to_u32(const void* p) {
    uint32_t a;
    asm("{ .reg .u64 t; cvta.to.shared.u64 t, %1; cvt.u32.u64 %0, t; }" : "=r"(a) : "l"(p));
    return a;
}
__device__ __forceinline__ void ldsm_x4(uint32_t* r, uint32_t addr) {
    asm volatile("ldmatrix.sync.aligned.m8n8.x4.shared.b16 {%0,%1,%2,%3}, [%4];"
        : "=r"(r[0]), "=r"(r[1]), "=r"(r[2]), "=r"(r[3]) : "r"(addr));
}
__device__ __forceinline__ void ldsm_x4_t(uint32_t* r, uint32_t addr) {
    asm volatile("ldmatrix.sync.aligned.m8n8.x4.trans.shared.b16 {%0,%1,%2,%3}, [%4];"
        : "=r"(r[0]), "=r"(r[1]), "=r"(r[2]), "=r"(r[3]) : "r"(addr));
}
__device__ __forceinline__ void mma16816bf(float* c, const uint32_t* a, const uint32_t* b) {
    asm volatile("mma.sync.aligned.m16n8k16.row.col.f32.bf16.bf16.f32 "
        "{%0,%1,%2,%3}, {%4,%5,%6,%7}, {%8,%9}, {%0,%1,%2,%3};"
        : "+f"(c[0]), "+f"(c[1]), "+f"(c[2]), "+f"(c[3])
        : "r"(a[0]), "r"(a[1]), "r"(a[2]), "r"(a[3]), "r"(b[0]), "r"(b[1]));
}
__device__ __forceinline__ void mma16816h(float* c, const uint32_t* a, const uint32_t* b) {
    asm volatile("mma.sync.aligned.m16n8k16.row.col.f32.f16.f16.f32 "
        "{%0,%1,%2,%3}, {%4,%5,%6,%7}, {%8,%9}, {%0,%1,%2,%3};"
        : "+f"(c[0]), "+f"(c[1]), "+f"(c[2]), "+f"(c[3])
        : "r"(a[0]), "r"(a[1]), "r"(a[2]), "r"(a[3]), "r"(b[0]), "r"(b[1]));
}
__device__ __forceinline__ float ex2f(float x) {
    float r;
    asm("ex2.approx.f32 %0, %1;" : "=f"(r) : "f"(x));
    return r;
}
__device__ __forceinline__ void cp_async16(uint32_t dst, const void* src) {
    asm volatile("cp.async.cg.shared.global [%0], [%1], 16;" :: "r"(dst), "l"(src));
}
#define CP_COMMIT() asm volatile("cp.async.commit_group;" ::: "memory")
#define CP_WAIT0()  asm volatile("cp.async.wait_group 0;" ::: "memory")

__device__ __forceinline__ void cvt2_hilo(float x, float y, uint32_t& hi, uint32_t& lo) {
    __nv_bfloat162 h = __floats2bfloat162_rn(x, y);
    float hx = __bfloat162float(h.x);
    float hy = __bfloat162float(h.y);
    __nv_bfloat162 l = __floats2bfloat162_rn(x - hx, y - hy);
    hi = *reinterpret_cast<uint32_t*>(&h);
    lo = *reinterpret_cast<uint32_t*>(&l);
}

// Q pre-scale: 1/sqrt(HD) * log2(e)
#define QSCALE 0.1803368801111244f

// ---------------------------------------------------------------------------
// Pre-convert: fp32 -> bf16 hi/lo. sel 0 -> X, 1..4 -> W[sel-1].
// ---------------------------------------------------------------------------
__global__ __launch_bounds__(256) void cvt_kernel(const float* __restrict__ src, int sel, int n4)
{
    int i = blockIdx.x * blockDim.x + threadIdx.x;
    if (i >= n4) return;
    __nv_bfloat16* hi;
    __nv_bfloat16* lo;
    if (sel == 0) { hi = g_Xhi; lo = g_Xlo; }
    else          { hi = g_Whi + (size_t)(sel - 1) * EMB * EMB;
                    lo = g_Wlo + (size_t)(sel - 1) * EMB * EMB; }
    float4 v = ((const float4*)src)[i];
    uint2 h, l;
    cvt2_hilo(v.x, v.y, h.x, l.x);
    cvt2_hilo(v.z, v.w, h.y, l.y);
    ((uint2*)hi)[i] = h;
    ((uint2*)lo)[i] = l;
}

// ---------------------------------------------------------------------------
// bf16 hi/lo GEMM with cp.async 2-stage pipeline.
// C[m,n] = sum_k A[m,k]*W[n,k] + bias[n].  CTA 128x128, BK=32, 8 warps.
// aSel: 0=X, 1=O. wIdx selects weight matrix.
// scatterDst: 0 plain fp32 Cout; 1/2/3 -> g_Qh/g_Kh/g_Vh fp16 scatter.
// smem/stage: AHI 8K | ALO 8K | BHI 8K | BLO 8K = 32KB; 2 stages = 64KB.
// Rows are 64B (32 bf16); chunk16 swizzle: c ^ ((row>>1)&3)  (ldsm conflict-free)
// ---------------------------------------------------------------------------
#define GSTG 32768

__device__ __forceinline__ void gemm_stage(
    uint32_t sbs, int tid, int bm, int bn, int k0,
    const __nv_bfloat16* __restrict__ Ahi, const __nv_bfloat16* __restrict__ Alo,
    const __nv_bfloat16* __restrict__ Bhi, const __nv_bfloat16* __restrict__ Blo)
{
#pragma unroll
    for (int l = 0; l < 8; l++) {
        const int buf = l >> 1;
        int i   = (l & 1) * 256 + tid;
        int row = i >> 2;
        int c   = i & 3;
        uint32_t dst = sbs + buf * 8192 + row * 64 + ((c ^ ((row >> 1) & 3)) * 16);
        const __nv_bfloat16* src;
        if (buf == 0)      src = Ahi + (size_t)(bm + row) * EMB + k0 + c * 8;
        else if (buf == 1) src = Alo + (size_t)(bm + row) * EMB + k0 + c * 8;
        else if (buf == 2) src = Bhi + (size_t)(bn + row) * EMB + k0 + c * 8;
        else               src = Blo + (size_t)(bn + row) * EMB + k0 + c * 8;
        cp_async16(dst, src);
    }
}

__global__ __launch_bounds__(256, 2) void gemm_bf_kernel(
    int aSel, int wIdx,
    const float* __restrict__ bias,
    float* __restrict__ Cout,
    int scatterDst)
{
    extern __shared__ __align__(16) char smem[];
    uint32_t sb = smem_to_u32(smem);

    const __nv_bfloat16* Ahi = aSel ? g_Ohi : g_Xhi;
    const __nv_bfloat16* Alo = aSel ? g_Olo : g_Xlo;
    const __nv_bfloat16* Bhi = g_Whi + (size_t)wIdx * EMB * EMB;
    const __nv_bfloat16* Blo = g_Wlo + (size_t)wIdx * EMB * EMB;

    const int tid  = threadIdx.x;
    const int lane = tid & 31;
    const int w    = tid >> 5;
    const int wm   = w & 3;
    const int wn   = w >> 2;
    const int bm   = blockIdx.y * 128;
    const int bn   = blockIdx.x * 128;

    float acc[2][8][4];
#pragma unroll
    for (int i = 0; i < 2; i++)
#pragma unroll
        for (int j = 0; j < 8; j++)
#pragma unroll
            for (int c = 0; c < 4; c++) acc[i][j][c] = 0.f;

    const int a_row = lane & 15;
    const int a_ch  = lane >> 4;            // chunk16 within ks half
    const int b_row = ((lane >> 4) & 1) * 8 + (lane & 7);
    const int b_ch  = (lane >> 3) & 1;

    const int NK = EMB / 32;
    gemm_stage(sb, tid, bm, bn, 0, Ahi, Alo, Bhi, Blo);
    CP_COMMIT();

    for (int kc = 0; kc < NK; kc++) {
        CP_WAIT0();
        __syncthreads();
        if (kc + 1 < NK) {
            gemm_stage(sb + ((kc + 1) & 1) * GSTG, tid, bm, bn, (kc + 1) * 32,
                       Ahi, Alo, Bhi, Blo);
            CP_COMMIT();
        }
        uint32_t sbs = sb + (kc & 1) * GSTG;

#pragma unroll
        for (int ks = 0; ks < 2; ks++) {
            uint32_t ah[2][4], al[2][4];
#pragma unroll
            for (int mi = 0; mi < 2; mi++) {
                int ar = wm * 32 + mi * 16 + a_row;
                int lc = ks * 2 + a_ch;
                uint32_t ad = sbs + ar * 64 + ((lc ^ ((ar >> 1) & 3)) * 16);
                ldsm_x4(ah[mi], ad);
                ldsm_x4(al[mi], ad + 8192);
            }
#pragma unroll
            for (int np = 0; np < 4; np++) {
                uint32_t bh[4], bl[4];
                int br = wn * 64 + np * 16 + b_row;
                int lc = ks * 2 + b_ch;
                uint32_t bd = sbs + 16384 + br * 64 + ((lc ^ ((br >> 1) & 3)) * 16);
                ldsm_x4(bh, bd);
                ldsm_x4(bl, bd + 8192);
#pragma unroll
                for (int sub = 0; sub < 2; sub++) {
#pragma unroll
                    for (int mi = 0; mi < 2; mi++) {
                        float* c = acc[mi][np * 2 + sub];
                        mma16816bf(c, ah[mi], &bh[sub * 2]);
                        mma16816bf(c, ah[mi], &bl[sub * 2]);
                        mma16816bf(c, al[mi], &bh[sub * 2]);
                    }
                }
            }
        }
    }

    // epilogue
#pragma unroll
    for (int mi = 0; mi < 2; mi++) {
#pragma unroll
        for (int nf = 0; nf < 8; nf++) {
            int col = bn + wn * 64 + nf * 8 + (lane & 3) * 2;
            float2 bv = *(const float2*)(bias + col);
#pragma unroll
            for (int h = 0; h < 2; h++) {
                int m = bm + wm * 32 + mi * 16 + (lane >> 2) + h * 8;
                float2 o;
                o.x = acc[mi][nf][h * 2 + 0] + bv.x;
                o.y = acc[mi][nf][h * 2 + 1] + bv.y;
                if (scatterDst == 0) {
                    *(float2*)(Cout + (size_t)m * EMB + col) = o;
                } else {
                    int b = m >> 11;
                    int s = m & (SEQ - 1);
                    int hh = col >> 6;
                    int d  = col & (HD - 1);
                    float sc = (scatterDst == 1) ? QSCALE : 1.0f;
                    __half2 hv = __floats2half2_rn(o.x * sc, o.y * sc);
                    __half* dst = (scatterDst == 1) ? g_Qh : (scatterDst == 2) ? g_Kh : g_Vh;
                    *(__half2*)(dst + (((size_t)(b * NH + hh)) * SEQ + s) * HD + d) = hv;
                }
            }
        }
    }
}

// ---------------------------------------------------------------------------
// Tensor-core flash attention, fp16 mma, cp.async double-buffered K/V.
// CTA = 128 threads (4 warps); warp owns 16 q rows; CTA q tile = 64; KV tile 64.
// smem rows = 64 halfs = 128B; chunk16 swizzle: c ^ (row&7) (conflict-free).
// Output written as bf16 hi/lo for the out-projection GEMM.
// ---------------------------------------------------------------------------
__global__ __launch_bounds__(128, 4) void attn_tc_kernel()
{
    __shared__ __align__(16) __half Qs[64 * 64];
    __shared__ __align__(16) __half KVs[2][2][64 * 64];   // [stage][K/V]

    const int tid  = threadIdx.x;
    const int lane = tid & 31;
    const int w    = tid >> 5;
    const int bh   = blockIdx.y;
    const int it   = blockIdx.x;

    const uint32_t sQ  = smem_to_u32(Qs);
    const uint32_t sKV = smem_to_u32(KVs);

    const __half* Qg = g_Qh + ((size_t)bh * SEQ + (size_t)it * 64) * HD;
    const __half* Kg = g_Kh + (size_t)bh * SEQ * HD;
    const __half* Vg = g_Vh + (size_t)bh * SEQ * HD;

    // stage Q tile (swizzled)
#pragma unroll
    for (int l = 0; l < 4; l++) {
        int idx = tid + l * 128;       // 0..511
        int row = idx >> 3;
        int ch  = idx & 7;
        *(uint4*)&Qs[row * 64 + ((ch ^ (row & 7)) * 8)] =
            *(const uint4*)(Qg + (size_t)row * HD + ch * 8);
    }

    // prologue: issue KV tile 0
    {
#pragma unroll
        for (int l = 0; l < 8; l++) {
            const int kv = l >> 2;
            int i   = (l & 3) * 128 + tid;
            int row = i >> 3;
            int ch  = i & 7;
            uint32_t dst = sKV + kv * 8192 + row * 128 + ((ch ^ (row & 7)) * 16);
            const __half* src = (kv ? Vg : Kg) + (size_t)row * HD + ch * 8;
            cp_async16(dst, src);
        }
        CP_COMMIT();
    }
    __syncthreads();

    // loop-invariant Q A-fragments
    const int a_row = lane & 15;
    const int a_ch  = lane >> 4;
    uint32_t qa[4][4];
#pragma unroll
    for (int ks = 0; ks < 4; ks++) {
        int qr = w * 16 + a_row;
        int lc = ks * 2 + a_ch;
        ldsm_x4(qa[ks], sQ + qr * 128 + ((lc ^ (qr & 7)) * 16));
    }

    const int b_row = ((lane >> 4) & 1) * 8 + (lane & 7);
    const int b_ch  = (lane >> 3) & 1;
    const int v_row = lane & 15;
    const int v_ch  = lane >> 4;

    float o[8][4];
#pragma unroll
    for (int nf = 0; nf < 8; nf++)
#pragma unroll
        for (int c = 0; c < 4; c++) o[nf][c] = 0.f;
    float m0 = -1e30f, m1 = -1e30f, sum0 = 0.f, sum1 = 0.f;

    const int NT = SEQ / 64;
    for (int jt = 0; jt < NT; jt++) {
        CP_WAIT0();
        __syncthreads();
        if (jt + 1 < NT) {
            const __half* kg = Kg + (size_t)(jt + 1) * 64 * HD;
            const __half* vg = Vg + (size_t)(jt + 1) * 64 * HD;
            uint32_t sbs = sKV + ((jt + 1) & 1) * 16384;
#pragma unroll
            for (int l = 0; l < 8; l++) {
                const int kv = l >> 2;
                int i   = (l & 3) * 128 + tid;
                int row = i >> 3;
                int ch  = i & 7;
                uint32_t dst = sbs + kv * 8192 + row * 128 + ((ch ^ (row & 7)) * 16);
                const __half* src = (kv ? vg : kg) + (size_t)row * HD + ch * 8;
                cp_async16(dst, src);
            }
            CP_COMMIT();
        }
        uint32_t sK = sKV + (jt & 1) * 16384;
        uint32_t sV = sK + 8192;

        // S = Q K^T
        float s[8][4];
#pragma unroll
        for (int nf = 0; nf < 8; nf++)
#pragma unroll
            for (int c = 0; c < 4; c++) s[nf][c] = 0.f;
#pragma unroll
        for (int nt = 0; nt < 4; nt++) {
#pragma unroll
            for (int ks = 0; ks < 4; ks++) {
                uint32_t kb[4];
                int kr = nt * 16 + b_row;
                int lc = ks * 2 + b_ch;
                ldsm_x4(kb, sK + kr * 128 + ((lc ^ (kr & 7)) * 16));
                mma16816h(s[nt * 2 + 0], qa[ks], &kb[0]);
                mma16816h(s[nt * 2 + 1], qa[ks], &kb[2]);
            }
        }

        // online softmax
        float mx0 = -1e30f, mx1 = -1e30f;
#pragma unroll
        for (int nf = 0; nf < 8; nf++) {
            mx0 = fmaxf(mx0, fmaxf(s[nf][0], s[nf][1]));
            mx1 = fmaxf(mx1, fmaxf(s[nf][2], s[nf][3]));
        }
        mx0 = fmaxf(mx0, __shfl_xor_sync(0xffffffffu, mx0, 1));
        mx0 = fmaxf(mx0, __shfl_xor_sync(0xffffffffu, mx0, 2));
        mx1 = fmaxf(mx1, __shfl_xor_sync(0xffffffffu, mx1, 1));
        mx1 = fmaxf(mx1, __shfl_xor_sync(0xffffffffu, mx1, 2));

        float mn0 = fmaxf(m0, mx0);
        float mn1 = fmaxf(m1, mx1);
        float sc0 = ex2f(m0 - mn0);
        float sc1 = ex2f(m1 - mn1);

        float ps0 = 0.f, ps1 = 0.f;
#pragma unroll
        for (int nf = 0; nf < 8; nf++) {
            s[nf][0] = ex2f(s[nf][0] - mn0);
            s[nf][1] = ex2f(s[nf][1] - mn0);
            s[nf][2] = ex2f(s[nf][2] - mn1);
            s[nf][3] = ex2f(s[nf][3] - mn1);
            ps0 += s[nf][0] + s[nf][1];
            ps1 += s[nf][2] + s[nf][3];
        }
        ps0 += __shfl_xor_sync(0xffffffffu, ps0, 1);
        ps0 += __shfl_xor_sync(0xffffffffu, ps0, 2);
        ps1 += __shfl_xor_sync(0xffffffffu, ps1, 1);
        ps1 += __shfl_xor_sync(0xffffffffu, ps1, 2);

        sum0 = sum0 * sc0 + ps0;  m0 = mn0;
        sum1 = sum1 * sc1 + ps1;  m1 = mn1;

#pragma unroll
        for (int nf = 0; nf < 8; nf++) {
            o[nf][0] *= sc0; o[nf][1] *= sc0;
            o[nf][2] *= sc1; o[nf][3] *= sc1;
        }

        // P C-frags -> A-frags
        uint32_t pa[4][4];
#pragma unroll
        for (int kt = 0; kt < 4; kt++) {
            __half2 h0 = __floats2half2_rn(s[2 * kt][0],     s[2 * kt][1]);
            __half2 h1 = __floats2half2_rn(s[2 * kt][2],     s[2 * kt][3]);
            __half2 h2 = __floats2half2_rn(s[2 * kt + 1][0], s[2 * kt + 1][1]);
            __half2 h3 = __floats2half2_rn(s[2 * kt + 1][2], s[2 * kt + 1][3]);
            pa[kt][0] = *reinterpret_cast<uint32_t*>(&h0);
            pa[kt][1] = *reinterpret_cast<uint32_t*>(&h1);
            pa[kt][2] = *reinterpret_cast<uint32_t*>(&h2);
            pa[kt][3] = *reinterpret_cast<uint32_t*>(&h3);
        }

        // O += P V
#pragma unroll
        for (int kt = 0; kt < 4; kt++) {
#pragma unroll
            for (int nt = 0; nt < 4; nt++) {
                uint32_t vb[4];
                int vr = kt * 16 + v_row;
                int lc = nt * 2 + v_ch;
                ldsm_x4_t(vb, sV + vr * 128 + ((lc ^ (vr & 7)) * 16));
                mma16816h(o[nt * 2 + 0], pa[kt], &vb[0]);
                mma16816h(o[nt * 2 + 1], pa[kt], &vb[2]);
            }
        }
        __syncthreads();
    }

    // epilogue: normalize, write bf16 hi/lo to g_Ohi/g_Olo in [b, s, e] layout
    const int b = bh >> 4;
    const int h = bh & (NH - 1);
    const float inv0 = 1.f / sum0;
    const float inv1 = 1.f / sum1;
    const int r0 = it * 64 + w * 16 + (lane >> 2);
#pragma unroll
    for (int nf = 0; nf < 8; nf++) {
        int col = h * HD + nf * 8 + (lane & 3) * 2;
        uint32_t hi, lo;
        size_t off0 = ((size_t)(b * SEQ + r0)) * EMB + col;
        size_t off1 = ((size_t)(b * SEQ + r0 + 8)) * EMB + col;
        cvt2_hilo(o[nf][0] * inv0, o[nf][1] * inv0, hi, lo);
        *(uint32_t*)(g_Ohi + off0) = hi;
        *(uint32_t*)(g_Olo + off0) = lo;
        cvt2_hilo(o[nf][2] * inv1, o[nf][3] * inv1, hi, lo);
        *(uint32_t*)(g_Ohi + off1) = hi;
        *(uint32_t*)(g_Olo + off1) = lo;
    }
}

// ---------------------------------------------------------------------------

extern "C" void kernel_launch(void* const* d_in, const int* in_sizes, int n_in,
                              void* d_out, int out_size)
{
    (void)in_sizes; (void)n_in; (void)out_size;
    const float* x   = (const float*)d_in[0];
    const float* w_q = (const float*)d_in[1];
    const float* b_q = (const float*)d_in[2];
    const float* w_k = (const float*)d_in[3];
    const float* b_k = (const float*)d_in[4];
    const float* w_v = (const float*)d_in[5];
    const float* b_v = (const float*)d_in[6];
    const float* w_o = (const float*)d_in[7];
    const float* b_o = (const float*)d_in[8];
    float* out = (float*)d_out;

    cudaFuncSetAttribute(gemm_bf_kernel, cudaFuncAttributeMaxDynamicSharedMemorySize,
                         2 * GSTG);

    // pre-convert inputs to bf16 hi/lo
    cvt_kernel<<<(TOK * EMB / 4 + 255) / 256, 256>>>(x,   0, TOK * EMB / 4);
    cvt_kernel<<<(EMB * EMB / 4 + 255) / 256, 256>>>(w_q, 1, EMB * EMB / 4);
    cvt_kernel<<<(EMB * EMB / 4 + 255) / 256, 256>>>(w_k, 2, EMB * EMB / 4);
    cvt_kernel<<<(EMB * EMB / 4 + 255) / 256, 256>>>(w_v, 3, EMB * EMB / 4);
    cvt_kernel<<<(EMB * EMB / 4 + 255) / 256, 256>>>(w_o, 4, EMB * EMB / 4);

    dim3 gsz(EMB / 128, TOK / 128);   // (8, 64)
    gemm_bf_kernel<<<gsz, 256, 2 * GSTG>>>(0, 0, b_q, nullptr, 1);
    gemm_bf_kernel<<<gsz, 256, 2 * GSTG>>>(0, 1, b_k, nullptr, 2);
    gemm_bf_kernel<<<gsz, 256, 2 * GSTG>>>(0, 2, b_v, nullptr, 3);

    attn_tc_kernel<<<dim3(SEQ / 64, BHN), 128>>>();

    gemm_bf_kernel<<<gsz, 256, 2 * GSTG>>>(1, 3, b_o, out, 0);
}

// round 6
// speedup vs baseline: 7.9207x; 1.7890x over previous
#include <cuda_runtime.h>
#include <cuda_fp16.h>
#include <cstdint>
#include <math.h>

#define SEQ 2048
#define EMB 1024
#define NH  16
#define HD  64
#define NB  4
#define TOK (NB * SEQ)     // 8192
#define BHN (NB * NH)      // 64

// Scratch (device globals: allocation-free rule)
__device__ __align__(128) __half g_Qh[(size_t)BHN * SEQ * HD];
__device__ __align__(128) __half g_Kh[(size_t)BHN * SEQ * HD];
__device__ __align__(128) __half g_Vh[(size_t)BHN * SEQ * HD];
__device__ __align__(128) __half g_Xh[(size_t)TOK * EMB];
__device__ __align__(128) __half g_Oh[(size_t)TOK * EMB];
__device__ __align__(128) __half g_Wh[(size_t)4 * EMB * EMB];

// ---------------------------------------------------------------------------
// PTX helpers
// ---------------------------------------------------------------------------
__device__ __forceinline__ uint32_t smem_to_u32(const void* p) {
    uint32_t a;
    asm("{ .reg .u64 t; cvta.to.shared.u64 t, %1; cvt.u32.u64 %0, t; }" : "=r"(a) : "l"(p));
    return a;
}
__device__ __forceinline__ void ldsm_x4(uint32_t* r, uint32_t addr) {
    asm volatile("ldmatrix.sync.aligned.m8n8.x4.shared.b16 {%0,%1,%2,%3}, [%4];"
        : "=r"(r[0]), "=r"(r[1]), "=r"(r[2]), "=r"(r[3]) : "r"(addr));
}
__device__ __forceinline__ void ldsm_x4_t(uint32_t* r, uint32_t addr) {
    asm volatile("ldmatrix.sync.aligned.m8n8.x4.trans.shared.b16 {%0,%1,%2,%3}, [%4];"
        : "=r"(r[0]), "=r"(r[1]), "=r"(r[2]), "=r"(r[3]) : "r"(addr));
}
__device__ __forceinline__ void mma16816h(float* c, const uint32_t* a, const uint32_t* b) {
    asm volatile("mma.sync.aligned.m16n8k16.row.col.f32.f16.f16.f32 "
        "{%0,%1,%2,%3}, {%4,%5,%6,%7}, {%8,%9}, {%0,%1,%2,%3};"
        : "+f"(c[0]), "+f"(c[1]), "+f"(c[2]), "+f"(c[3])
        : "r"(a[0]), "r"(a[1]), "r"(a[2]), "r"(a[3]), "r"(b[0]), "r"(b[1]));
}
__device__ __forceinline__ float ex2f(float x) {
    float r;
    asm("ex2.approx.f32 %0, %1;" : "=f"(r) : "f"(x));
    return r;
}
__device__ __forceinline__ void cp_async16(uint32_t dst, const void* src) {
    asm volatile("cp.async.cg.shared.global [%0], [%1], 16;" :: "r"(dst), "l"(src));
}
#define CP_COMMIT() asm volatile("cp.async.commit_group;" ::: "memory")
#define CP_WAIT0()  asm volatile("cp.async.wait_group 0;" ::: "memory")

// Q pre-scale: 1/sqrt(HD) * log2(e)
#define QSCALE 0.1803368801111244f

// ---------------------------------------------------------------------------
// Pre-convert fp32 -> fp16. sel 0 -> X, 1..4 -> W[sel-1].
// ---------------------------------------------------------------------------
__global__ __launch_bounds__(256) void cvt_kernel(const float* __restrict__ src, int sel, int n4)
{
    int i = blockIdx.x * blockDim.x + threadIdx.x;
    if (i >= n4) return;
    __half* dst = (sel == 0) ? g_Xh : (g_Wh + (size_t)(sel - 1) * EMB * EMB);
    float4 v = ((const float4*)src)[i];
    __half2 h0 = __floats2half2_rn(v.x, v.y);
    __half2 h1 = __floats2half2_rn(v.z, v.w);
    uint2 o = { *reinterpret_cast<uint32_t*>(&h0), *reinterpret_cast<uint32_t*>(&h1) };
    ((uint2*)dst)[i] = o;
}

// ---------------------------------------------------------------------------
// fp16 GEMM with cp.async 2-stage pipeline.
// C[m,n] = sum_k A[m,k]*W[n,k] + bias[n].  CTA 128x128, BK=32, 8 warps.
// mode 0: fused QKV (blockIdx.z = 0/1/2 selects W and Q/K/V scatter dest).
// mode 1: out projection (A = g_Oh, W = W[3], plain fp32 store + bias).
// smem/stage: A 8K | B 8K = 16KB; 2 stages = 32KB (static).
// Rows 64B (32 fp16); chunk16 swizzle: c ^ ((row>>1)&3) (ldsm conflict-free).
// ---------------------------------------------------------------------------
#define GSTG 16384

__device__ __forceinline__ void gemm_stage(
    uint32_t sbs, int tid, int bm, int bn, int k0,
    const __half* __restrict__ Ag, const __half* __restrict__ Bg)
{
#pragma unroll
    for (int l = 0; l < 4; l++) {
        const int buf = l >> 1;                 // 0=A, 1=B
        int i   = (l & 1) * 256 + tid;          // 0..511
        int row = i >> 2;                       // 0..127
        int c   = i & 3;                        // chunk16
        uint32_t dst = sbs + buf * 8192 + row * 64 + ((c ^ ((row >> 1) & 3)) * 16);
        const __half* src = (buf ? Bg + (size_t)(bn + row) * EMB
                                 : Ag + (size_t)(bm + row) * EMB) + k0 + c * 8;
        cp_async16(dst, src);
    }
}

__global__ __launch_bounds__(256, 2) void gemm_h_kernel(
    int mode,
    const float* __restrict__ bias0,
    const float* __restrict__ bias1,
    const float* __restrict__ bias2,
    float* __restrict__ Cout)
{
    __shared__ __align__(16) char smem[2 * GSTG];
    uint32_t sb = smem_to_u32(smem);

    const int proj = (mode == 0) ? blockIdx.z : 3;
    const __half* Ag = (mode == 0) ? g_Xh : g_Oh;
    const __half* Bg = g_Wh + (size_t)proj * EMB * EMB;
    const float* bias = (mode == 1) ? bias0
                       : (proj == 0) ? bias0 : (proj == 1) ? bias1 : bias2;

    const int tid  = threadIdx.x;
    const int lane = tid & 31;
    const int w    = tid >> 5;
    const int wm   = w & 3;
    const int wn   = w >> 2;
    const int bm   = blockIdx.y * 128;
    const int bn   = blockIdx.x * 128;

    float acc[2][8][4];
#pragma unroll
    for (int i = 0; i < 2; i++)
#pragma unroll
        for (int j = 0; j < 8; j++)
#pragma unroll
            for (int c = 0; c < 4; c++) acc[i][j][c] = 0.f;

    const int a_row = lane & 15;
    const int a_ch  = lane >> 4;
    const int b_row = ((lane >> 4) & 1) * 8 + (lane & 7);
    const int b_ch  = (lane >> 3) & 1;

    const int NK = EMB / 32;
    gemm_stage(sb, tid, bm, bn, 0, Ag, Bg);
    CP_COMMIT();

    for (int kc = 0; kc < NK; kc++) {
        CP_WAIT0();
        __syncthreads();
        if (kc + 1 < NK) {
            gemm_stage(sb + ((kc + 1) & 1) * GSTG, tid, bm, bn, (kc + 1) * 32, Ag, Bg);
            CP_COMMIT();
        }
        uint32_t sbs = sb + (kc & 1) * GSTG;

#pragma unroll
        for (int ks = 0; ks < 2; ks++) {
            uint32_t ah[2][4];
#pragma unroll
            for (int mi = 0; mi < 2; mi++) {
                int ar = wm * 32 + mi * 16 + a_row;
                int lc = ks * 2 + a_ch;
                ldsm_x4(ah[mi], sbs + ar * 64 + ((lc ^ ((ar >> 1) & 3)) * 16));
            }
#pragma unroll
            for (int np = 0; np < 4; np++) {
                uint32_t bb[4];
                int br = wn * 64 + np * 16 + b_row;
                int lc = ks * 2 + b_ch;
                ldsm_x4(bb, sbs + 8192 + br * 64 + ((lc ^ ((br >> 1) & 3)) * 16));
#pragma unroll
                for (int sub = 0; sub < 2; sub++) {
#pragma unroll
                    for (int mi = 0; mi < 2; mi++) {
                        mma16816h(acc[mi][np * 2 + sub], ah[mi], &bb[sub * 2]);
                    }
                }
            }
        }
        __syncthreads();
    }

    // epilogue
#pragma unroll
    for (int mi = 0; mi < 2; mi++) {
#pragma unroll
        for (int nf = 0; nf < 8; nf++) {
            int col = bn + wn * 64 + nf * 8 + (lane & 3) * 2;
            float2 bv = *(const float2*)(bias + col);
#pragma unroll
            for (int h = 0; h < 2; h++) {
                int m = bm + wm * 32 + mi * 16 + (lane >> 2) + h * 8;
                float2 o;
                o.x = acc[mi][nf][h * 2 + 0] + bv.x;
                o.y = acc[mi][nf][h * 2 + 1] + bv.y;
                if (mode == 1) {
                    *(float2*)(Cout + (size_t)m * EMB + col) = o;
                } else {
                    int b = m >> 11;
                    int s = m & (SEQ - 1);
                    int hh = col >> 6;
                    int d  = col & (HD - 1);
                    float sc = (proj == 0) ? QSCALE : 1.0f;
                    __half2 hv = __floats2half2_rn(o.x * sc, o.y * sc);
                    __half* dst = (proj == 0) ? g_Qh : (proj == 1) ? g_Kh : g_Vh;
                    *(__half2*)(dst + (((size_t)(b * NH + hh)) * SEQ + s) * HD + d) = hv;
                }
            }
        }
    }
}

// ---------------------------------------------------------------------------
// Tensor-core flash attention, fp16 mma, cp.async double-buffered K/V.
// CTA = 128 threads (4 warps); warp owns 16 q rows; CTA q tile = 64; KV tile 64.
// smem rows = 64 halfs = 128B; chunk16 swizzle: c ^ (row&7).
// Output written fp16 to g_Oh for the out-projection GEMM.
// ---------------------------------------------------------------------------
__global__ __launch_bounds__(128, 4) void attn_tc_kernel()
{
    __shared__ __align__(16) __half Qs[64 * 64];
    __shared__ __align__(16) __half KVs[2][2][64 * 64];   // [stage][K/V]

    const int tid  = threadIdx.x;
    const int lane = tid & 31;
    const int w    = tid >> 5;
    const int bh   = blockIdx.y;
    const int it   = blockIdx.x;

    const uint32_t sQ  = smem_to_u32(Qs);
    const uint32_t sKV = smem_to_u32(KVs);

    const __half* Qg = g_Qh + ((size_t)bh * SEQ + (size_t)it * 64) * HD;
    const __half* Kg = g_Kh + (size_t)bh * SEQ * HD;
    const __half* Vg = g_Vh + (size_t)bh * SEQ * HD;

    // stage Q tile (swizzled)
#pragma unroll
    for (int l = 0; l < 4; l++) {
        int idx = tid + l * 128;       // 0..511
        int row = idx >> 3;
        int ch  = idx & 7;
        *(uint4*)&Qs[row * 64 + ((ch ^ (row & 7)) * 8)] =
            *(const uint4*)(Qg + (size_t)row * HD + ch * 8);
    }

    // prologue: issue KV tile 0
    {
#pragma unroll
        for (int l = 0; l < 8; l++) {
            const int kv = l >> 2;
            int i   = (l & 3) * 128 + tid;
            int row = i >> 3;
            int ch  = i & 7;
            uint32_t dst = sKV + kv * 8192 + row * 128 + ((ch ^ (row & 7)) * 16);
            const __half* src = (kv ? Vg : Kg) + (size_t)row * HD + ch * 8;
            cp_async16(dst, src);
        }
        CP_COMMIT();
    }
    __syncthreads();

    // loop-invariant Q A-fragments
    const int a_row = lane & 15;
    const int a_ch  = lane >> 4;
    uint32_t qa[4][4];
#pragma unroll
    for (int ks = 0; ks < 4; ks++) {
        int qr = w * 16 + a_row;
        int lc = ks * 2 + a_ch;
        ldsm_x4(qa[ks], sQ + qr * 128 + ((lc ^ (qr & 7)) * 16));
    }

    const int b_row = ((lane >> 4) & 1) * 8 + (lane & 7);
    const int b_ch  = (lane >> 3) & 1;
    const int v_row = lane & 15;
    const int v_ch  = lane >> 4;

    float o[8][4];
#pragma unroll
    for (int nf = 0; nf < 8; nf++)
#pragma unroll
        for (int c = 0; c < 4; c++) o[nf][c] = 0.f;
    float m0 = -1e30f, m1 = -1e30f, sum0 = 0.f, sum1 = 0.f;

    const int NT = SEQ / 64;
    for (int jt = 0; jt < NT; jt++) {
        CP_WAIT0();
        __syncthreads();
        if (jt + 1 < NT) {
            const __half* kg = Kg + (size_t)(jt + 1) * 64 * HD;
            const __half* vg = Vg + (size_t)(jt + 1) * 64 * HD;
            uint32_t sbs = sKV + ((jt + 1) & 1) * 16384;
#pragma unroll
            for (int l = 0; l < 8; l++) {
                const int kv = l >> 2;
                int i   = (l & 3) * 128 + tid;
                int row = i >> 3;
                int ch  = i & 7;
                uint32_t dst = sbs + kv * 8192 + row * 128 + ((ch ^ (row & 7)) * 16);
                const __half* src = (kv ? vg : kg) + (size_t)row * HD + ch * 8;
                cp_async16(dst, src);
            }
            CP_COMMIT();
        }
        uint32_t sK = sKV + (jt & 1) * 16384;
        uint32_t sV = sK + 8192;

        // S = Q K^T
        float s[8][4];
#pragma unroll
        for (int nf = 0; nf < 8; nf++)
#pragma unroll
            for (int c = 0; c < 4; c++) s[nf][c] = 0.f;
#pragma unroll
        for (int nt = 0; nt < 4; nt++) {
#pragma unroll
            for (int ks = 0; ks < 4; ks++) {
                uint32_t kb[4];
                int kr = nt * 16 + b_row;
                int lc = ks * 2 + b_ch;
                ldsm_x4(kb, sK + kr * 128 + ((lc ^ (kr & 7)) * 16));
                mma16816h(s[nt * 2 + 0], qa[ks], &kb[0]);
                mma16816h(s[nt * 2 + 1], qa[ks], &kb[2]);
            }
        }

        // online softmax
        float mx0 = -1e30f, mx1 = -1e30f;
#pragma unroll
        for (int nf = 0; nf < 8; nf++) {
            mx0 = fmaxf(mx0, fmaxf(s[nf][0], s[nf][1]));
            mx1 = fmaxf(mx1, fmaxf(s[nf][2], s[nf][3]));
        }
        mx0 = fmaxf(mx0, __shfl_xor_sync(0xffffffffu, mx0, 1));
        mx0 = fmaxf(mx0, __shfl_xor_sync(0xffffffffu, mx0, 2));
        mx1 = fmaxf(mx1, __shfl_xor_sync(0xffffffffu, mx1, 1));
        mx1 = fmaxf(mx1, __shfl_xor_sync(0xffffffffu, mx1, 2));

        float mn0 = fmaxf(m0, mx0);
        float mn1 = fmaxf(m1, mx1);
        float sc0 = ex2f(m0 - mn0);
        float sc1 = ex2f(m1 - mn1);

        float ps0 = 0.f, ps1 = 0.f;
#pragma unroll
        for (int nf = 0; nf < 8; nf++) {
            s[nf][0] = ex2f(s[nf][0] - mn0);
            s[nf][1] = ex2f(s[nf][1] - mn0);
            s[nf][2] = ex2f(s[nf][2] - mn1);
            s[nf][3] = ex2f(s[nf][3] - mn1);
            ps0 += s[nf][0] + s[nf][1];
            ps1 += s[nf][2] + s[nf][3];
        }
        ps0 += __shfl_xor_sync(0xffffffffu, ps0, 1);
        ps0 += __shfl_xor_sync(0xffffffffu, ps0, 2);
        ps1 += __shfl_xor_sync(0xffffffffu, ps1, 1);
        ps1 += __shfl_xor_sync(0xffffffffu, ps1, 2);

        sum0 = sum0 * sc0 + ps0;  m0 = mn0;
        sum1 = sum1 * sc1 + ps1;  m1 = mn1;

#pragma unroll
        for (int nf = 0; nf < 8; nf++) {
            o[nf][0] *= sc0; o[nf][1] *= sc0;
            o[nf][2] *= sc1; o[nf][3] *= sc1;
        }

        // P C-frags -> A-frags
        uint32_t pa[4][4];
#pragma unroll
        for (int kt = 0; kt < 4; kt++) {
            __half2 h0 = __floats2half2_rn(s[2 * kt][0],     s[2 * kt][1]);
            __half2 h1 = __floats2half2_rn(s[2 * kt][2],     s[2 * kt][3]);
            __half2 h2 = __floats2half2_rn(s[2 * kt + 1][0], s[2 * kt + 1][1]);
            __half2 h3 = __floats2half2_rn(s[2 * kt + 1][2], s[2 * kt + 1][3]);
            pa[kt][0] = *reinterpret_cast<uint32_t*>(&h0);
            pa[kt][1] = *reinterpret_cast<uint32_t*>(&h1);
            pa[kt][2] = *reinterpret_cast<uint32_t*>(&h2);
            pa[kt][3] = *reinterpret_cast<uint32_t*>(&h3);
        }

        // O += P V
#pragma unroll
        for (int kt = 0; kt < 4; kt++) {
#pragma unroll
            for (int nt = 0; nt < 4; nt++) {
                uint32_t vb[4];
                int vr = kt * 16 + v_row;
                int lc = nt * 2 + v_ch;
                ldsm_x4_t(vb, sV + vr * 128 + ((lc ^ (vr & 7)) * 16));
                mma16816h(o[nt * 2 + 0], pa[kt], &vb[0]);
                mma16816h(o[nt * 2 + 1], pa[kt], &vb[2]);
            }
        }
        __syncthreads();
    }

    // epilogue: normalize, write fp16 to g_Oh in [b, s, e] layout
    const int b = bh >> 4;
    const int h = bh & (NH - 1);
    const float inv0 = 1.f / sum0;
    const float inv1 = 1.f / sum1;
    const int r0 = it * 64 + w * 16 + (lane >> 2);
#pragma unroll
    for (int nf = 0; nf < 8; nf++) {
        int col = h * HD + nf * 8 + (lane & 3) * 2;
        __half2 v0 = __floats2half2_rn(o[nf][0] * inv0, o[nf][1] * inv0);
        __half2 v1 = __floats2half2_rn(o[nf][2] * inv1, o[nf][3] * inv1);
        *(__half2*)(g_Oh + ((size_t)(b * SEQ + r0))     * EMB + col) = v0;
        *(__half2*)(g_Oh + ((size_t)(b * SEQ + r0 + 8)) * EMB + col) = v1;
    }
}

// ---------------------------------------------------------------------------

extern "C" void kernel_launch(void* const* d_in, const int* in_sizes, int n_in,
                              void* d_out, int out_size)
{
    (void)in_sizes; (void)n_in; (void)out_size;
    const float* x   = (const float*)d_in[0];
    const float* w_q = (const float*)d_in[1];
    const float* b_q = (const float*)d_in[2];
    const float* w_k = (const float*)d_in[3];
    const float* b_k = (const float*)d_in[4];
    const float* w_v = (const float*)d_in[5];
    const float* b_v = (const float*)d_in[6];
    const float* w_o = (const float*)d_in[7];
    const float* b_o = (const float*)d_in[8];
    float* out = (float*)d_out;

    // pre-convert inputs to fp16
    cvt_kernel<<<(TOK * EMB / 4 + 255) / 256, 256>>>(x,   0, TOK * EMB / 4);
    cvt_kernel<<<(EMB * EMB / 4 + 255) / 256, 256>>>(w_q, 1, EMB * EMB / 4);
    cvt_kernel<<<(EMB * EMB / 4 + 255) / 256, 256>>>(w_k, 2, EMB * EMB / 4);
    cvt_kernel<<<(EMB * EMB / 4 + 255) / 256, 256>>>(w_v, 3, EMB * EMB / 4);
    cvt_kernel<<<(EMB * EMB / 4 + 255) / 256, 256>>>(w_o, 4, EMB * EMB / 4);

    // fused Q/K/V projections
    gemm_h_kernel<<<dim3(EMB / 128, TOK / 128, 3), 256>>>(0, b_q, b_k, b_v, nullptr);

    attn_tc_kernel<<<dim3(SEQ / 64, BHN), 128>>>();

    // out projection
    gemm_h_kernel<<<dim3(EMB / 128, TOK / 128, 1), 256>>>(1, b_o, nullptr, nullptr, out);
}

// round 7
// speedup vs baseline: 8.1527x; 1.0293x over previous
#include <cuda_runtime.h>
#include <cuda_fp16.h>
#include <cstdint>
#include <math.h>

#define SEQ 2048
#define EMB 1024
#define NH  16
#define HD  64
#define NB  4
#define TOK (NB * SEQ)     // 8192
#define BHN (NB * NH)      // 64

// Scratch (device globals: allocation-free rule)
__device__ __align__(128) __half g_Qh[(size_t)BHN * SEQ * HD];
__device__ __align__(128) __half g_Kh[(size_t)BHN * SEQ * HD];
__device__ __align__(128) __half g_Vh[(size_t)BHN * SEQ * HD];
__device__ __align__(128) __half g_Xh[(size_t)TOK * EMB];
__device__ __align__(128) __half g_Oh[(size_t)TOK * EMB];
__device__ __align__(128) __half g_Wh[(size_t)4 * EMB * EMB];

// ---------------------------------------------------------------------------
// PTX helpers
// ---------------------------------------------------------------------------
__device__ __forceinline__ uint32_t smem_to_u32(const void* p) {
    uint32_t a;
    asm("{ .reg .u64 t; cvta.to.shared.u64 t, %1; cvt.u32.u64 %0, t; }" : "=r"(a) : "l"(p));
    return a;
}
__device__ __forceinline__ void ldsm_x4(uint32_t* r, uint32_t addr) {
    asm volatile("ldmatrix.sync.aligned.m8n8.x4.shared.b16 {%0,%1,%2,%3}, [%4];"
        : "=r"(r[0]), "=r"(r[1]), "=r"(r[2]), "=r"(r[3]) : "r"(addr));
}
__device__ __forceinline__ void ldsm_x4_t(uint32_t* r, uint32_t addr) {
    asm volatile("ldmatrix.sync.aligned.m8n8.x4.trans.shared.b16 {%0,%1,%2,%3}, [%4];"
        : "=r"(r[0]), "=r"(r[1]), "=r"(r[2]), "=r"(r[3]) : "r"(addr));
}
__device__ __forceinline__ void mma16816h(float* c, const uint32_t* a, const uint32_t* b) {
    asm volatile("mma.sync.aligned.m16n8k16.row.col.f32.f16.f16.f32 "
        "{%0,%1,%2,%3}, {%4,%5,%6,%7}, {%8,%9}, {%0,%1,%2,%3};"
        : "+f"(c[0]), "+f"(c[1]), "+f"(c[2]), "+f"(c[3])
        : "r"(a[0]), "r"(a[1]), "r"(a[2]), "r"(a[3]), "r"(b[0]), "r"(b[1]));
}
__device__ __forceinline__ float ex2f(float x) {
    float r;
    asm("ex2.approx.f32 %0, %1;" : "=f"(r) : "f"(x));
    return r;
}
__device__ __forceinline__ void cp_async16(uint32_t dst, const void* src) {
    asm volatile("cp.async.cg.shared.global [%0], [%1], 16;" :: "r"(dst), "l"(src));
}
#define CP_COMMIT() asm volatile("cp.async.commit_group;" ::: "memory")
#define CP_WAIT0()  asm volatile("cp.async.wait_group 0;" ::: "memory")

// Q pre-scale: 1/sqrt(HD) * log2(e)
#define QSCALE 0.1803368801111244f

// ---------------------------------------------------------------------------
// Fused pre-convert fp32 -> fp16: x then w_q|w_k|w_v|w_o (one launch).
// ---------------------------------------------------------------------------
#define NX4 (TOK * EMB / 4)
#define NW4 (EMB * EMB / 4)

__global__ __launch_bounds__(256) void cvt_all_kernel(
    const float* __restrict__ x,
    const float* __restrict__ wq, const float* __restrict__ wk,
    const float* __restrict__ wv, const float* __restrict__ wo)
{
    int i = blockIdx.x * blockDim.x + threadIdx.x;
    const float4* src;
    uint2* dst;
    if (i < NX4) {
        src = (const float4*)x + i;
        dst = (uint2*)g_Xh + i;
    } else {
        int j = i - NX4;
        int w = j / NW4;
        int r = j - w * NW4;
        const float* s = (w == 0) ? wq : (w == 1) ? wk : (w == 2) ? wv : wo;
        src = (const float4*)s + r;
        dst = (uint2*)g_Wh + j;
    }
    float4 v = *src;
    __half2 h0 = __floats2half2_rn(v.x, v.y);
    __half2 h1 = __floats2half2_rn(v.z, v.w);
    uint2 o = { *reinterpret_cast<uint32_t*>(&h0), *reinterpret_cast<uint32_t*>(&h1) };
    *dst = o;
}

// ---------------------------------------------------------------------------
// fp16 GEMM with cp.async 2-stage pipeline.
// C[m,n] = sum_k A[m,k]*W[n,k] + bias[n].  CTA 128x128, BK=32, 8 warps.
// mode 0: fused QKV (blockIdx.z selects W + scatter dest).
// mode 1: out projection (A = g_Oh, W = W[3], fp32 store + bias).
// ---------------------------------------------------------------------------
#define GSTG 16384

__device__ __forceinline__ void gemm_stage(
    uint32_t sbs, int tid, int bm, int bn, int k0,
    const __half* __restrict__ Ag, const __half* __restrict__ Bg)
{
#pragma unroll
    for (int l = 0; l < 4; l++) {
        const int buf = l >> 1;                 // 0=A, 1=B
        int i   = (l & 1) * 256 + tid;          // 0..511
        int row = i >> 2;                       // 0..127
        int c   = i & 3;                        // chunk16
        uint32_t dst = sbs + buf * 8192 + row * 64 + ((c ^ ((row >> 1) & 3)) * 16);
        const __half* src = (buf ? Bg + (size_t)(bn + row) * EMB
                                 : Ag + (size_t)(bm + row) * EMB) + k0 + c * 8;
        cp_async16(dst, src);
    }
}

__global__ __launch_bounds__(256, 2) void gemm_h_kernel(
    int mode,
    const float* __restrict__ bias0,
    const float* __restrict__ bias1,
    const float* __restrict__ bias2,
    float* __restrict__ Cout)
{
    __shared__ __align__(16) char smem[2 * GSTG];
    uint32_t sb = smem_to_u32(smem);

    const int proj = (mode == 0) ? blockIdx.z : 3;
    const __half* Ag = (mode == 0) ? g_Xh : g_Oh;
    const __half* Bg = g_Wh + (size_t)proj * EMB * EMB;
    const float* bias = (mode == 1) ? bias0
                       : (proj == 0) ? bias0 : (proj == 1) ? bias1 : bias2;

    const int tid  = threadIdx.x;
    const int lane = tid & 31;
    const int w    = tid >> 5;
    const int wm   = w & 3;
    const int wn   = w >> 2;
    const int bm   = blockIdx.y * 128;
    const int bn   = blockIdx.x * 128;

    float acc[2][8][4];
#pragma unroll
    for (int i = 0; i < 2; i++)
#pragma unroll
        for (int j = 0; j < 8; j++)
#pragma unroll
            for (int c = 0; c < 4; c++) acc[i][j][c] = 0.f;

    const int a_row = lane & 15;
    const int a_ch  = lane >> 4;
    const int b_row = ((lane >> 4) & 1) * 8 + (lane & 7);
    const int b_ch  = (lane >> 3) & 1;

    const int NK = EMB / 32;
    gemm_stage(sb, tid, bm, bn, 0, Ag, Bg);
    CP_COMMIT();

    for (int kc = 0; kc < NK; kc++) {
        CP_WAIT0();
        __syncthreads();
        if (kc + 1 < NK) {
            gemm_stage(sb + ((kc + 1) & 1) * GSTG, tid, bm, bn, (kc + 1) * 32, Ag, Bg);
            CP_COMMIT();
        }
        uint32_t sbs = sb + (kc & 1) * GSTG;

#pragma unroll
        for (int ks = 0; ks < 2; ks++) {
            uint32_t ah[2][4];
#pragma unroll
            for (int mi = 0; mi < 2; mi++) {
                int ar = wm * 32 + mi * 16 + a_row;
                int lc = ks * 2 + a_ch;
                ldsm_x4(ah[mi], sbs + ar * 64 + ((lc ^ ((ar >> 1) & 3)) * 16));
            }
#pragma unroll
            for (int np = 0; np < 4; np++) {
                uint32_t bb[4];
                int br = wn * 64 + np * 16 + b_row;
                int lc = ks * 2 + b_ch;
                ldsm_x4(bb, sbs + 8192 + br * 64 + ((lc ^ ((br >> 1) & 3)) * 16));
#pragma unroll
                for (int sub = 0; sub < 2; sub++) {
#pragma unroll
                    for (int mi = 0; mi < 2; mi++) {
                        mma16816h(acc[mi][np * 2 + sub], ah[mi], &bb[sub * 2]);
                    }
                }
            }
        }
        // no bottom barrier: next iteration's cp.async targets the other buffer,
        // and its issue point is behind the top barrier all readers passed.
    }

    // epilogue
#pragma unroll
    for (int mi = 0; mi < 2; mi++) {
#pragma unroll
        for (int nf = 0; nf < 8; nf++) {
            int col = bn + wn * 64 + nf * 8 + (lane & 3) * 2;
            float2 bv = *(const float2*)(bias + col);
#pragma unroll
            for (int h = 0; h < 2; h++) {
                int m = bm + wm * 32 + mi * 16 + (lane >> 2) + h * 8;
                float2 o;
                o.x = acc[mi][nf][h * 2 + 0] + bv.x;
                o.y = acc[mi][nf][h * 2 + 1] + bv.y;
                if (mode == 1) {
                    *(float2*)(Cout + (size_t)m * EMB + col) = o;
                } else {
                    int b = m >> 11;
                    int s = m & (SEQ - 1);
                    int hh = col >> 6;
                    int d  = col & (HD - 1);
                    float sc = (proj == 0) ? QSCALE : 1.0f;
                    __half2 hv = __floats2half2_rn(o.x * sc, o.y * sc);
                    __half* dst = (proj == 0) ? g_Qh : (proj == 1) ? g_Kh : g_Vh;
                    *(__half2*)(dst + (((size_t)(b * NH + hh)) * SEQ + s) * HD + d) = hv;
                }
            }
        }
    }
}

// ---------------------------------------------------------------------------
// Tensor-core flash attention, fp16 mma, cp.async double-buffered K/V.
// CTA = 128 threads (4 warps); warp owns 16 q rows; CTA q tile = 64.
// KV tile = 128 (halves per-tile softmax/sync fixed cost vs 64).
// Dynamic smem: Q 8KB + 2 stages x (K 16KB + V 16KB) = 72KB.
// ---------------------------------------------------------------------------
#define ATTN_SMEM (8192 + 2 * 32768)

__global__ __launch_bounds__(128, 2) void attn_tc_kernel()
{
    extern __shared__ __align__(16) char asmem[];
    const uint32_t sQ  = smem_to_u32(asmem);
    const uint32_t sKV = sQ + 8192;

    const int tid  = threadIdx.x;
    const int lane = tid & 31;
    const int w    = tid >> 5;
    const int bh   = blockIdx.y;
    const int it   = blockIdx.x;

    const __half* Qg = g_Qh + ((size_t)bh * SEQ + (size_t)it * 64) * HD;
    const __half* Kg = g_Kh + (size_t)bh * SEQ * HD;
    const __half* Vg = g_Vh + (size_t)bh * SEQ * HD;

    // stage Q tile (64 rows x 64 halfs, swizzled)
    __half* Qs = (__half*)asmem;
#pragma unroll
    for (int l = 0; l < 4; l++) {
        int idx = tid + l * 128;       // 0..511
        int row = idx >> 3;
        int ch  = idx & 7;
        *(uint4*)&Qs[row * 64 + ((ch ^ (row & 7)) * 8)] =
            *(const uint4*)(Qg + (size_t)row * HD + ch * 8);
    }

    // prologue: issue KV tile 0 (128 rows each of K and V)
    {
#pragma unroll
        for (int l = 0; l < 16; l++) {
            const int kv = l >> 3;
            int i   = (l & 7) * 128 + tid;       // 0..1023
            int row = i >> 3;                    // 0..127
            int ch  = i & 7;
            uint32_t dst = sKV + kv * 16384 + row * 128 + ((ch ^ (row & 7)) * 16);
            const __half* src = (kv ? Vg : Kg) + (size_t)row * HD + ch * 8;
            cp_async16(dst, src);
        }
        CP_COMMIT();
    }
    __syncthreads();

    // loop-invariant Q A-fragments
    const int a_row = lane & 15;
    const int a_ch  = lane >> 4;
    uint32_t qa[4][4];
#pragma unroll
    for (int ks = 0; ks < 4; ks++) {
        int qr = w * 16 + a_row;
        int lc = ks * 2 + a_ch;
        ldsm_x4(qa[ks], sQ + qr * 128 + ((lc ^ (qr & 7)) * 16));
    }

    const int b_row = ((lane >> 4) & 1) * 8 + (lane & 7);
    const int b_ch  = (lane >> 3) & 1;
    const int v_row = lane & 15;
    const int v_ch  = lane >> 4;

    float o[8][4];
#pragma unroll
    for (int nf = 0; nf < 8; nf++)
#pragma unroll
        for (int c = 0; c < 4; c++) o[nf][c] = 0.f;
    float m0 = -1e30f, m1 = -1e30f, sum0 = 0.f, sum1 = 0.f;

    const int NT = SEQ / 128;
    for (int jt = 0; jt < NT; jt++) {
        CP_WAIT0();
        __syncthreads();
        if (jt + 1 < NT) {
            const __half* kg = Kg + (size_t)(jt + 1) * 128 * HD;
            const __half* vg = Vg + (size_t)(jt + 1) * 128 * HD;
            uint32_t sbs = sKV + ((jt + 1) & 1) * 32768;
#pragma unroll
            for (int l = 0; l < 16; l++) {
                const int kv = l >> 3;
                int i   = (l & 7) * 128 + tid;
                int row = i >> 3;
                int ch  = i & 7;
                uint32_t dst = sbs + kv * 16384 + row * 128 + ((ch ^ (row & 7)) * 16);
                const __half* src = (kv ? vg : kg) + (size_t)row * HD + ch * 8;
                cp_async16(dst, src);
            }
            CP_COMMIT();
        }
        uint32_t sK = sKV + (jt & 1) * 32768;
        uint32_t sV = sK + 16384;

        // S = Q K^T  (16 x 128 per warp)
        float s[16][4];
#pragma unroll
        for (int nf = 0; nf < 16; nf++)
#pragma unroll
            for (int c = 0; c < 4; c++) s[nf][c] = 0.f;
#pragma unroll
        for (int nt = 0; nt < 8; nt++) {
#pragma unroll
            for (int ks = 0; ks < 4; ks++) {
                uint32_t kb[4];
                int kr = nt * 16 + b_row;
                int lc = ks * 2 + b_ch;
                ldsm_x4(kb, sK + kr * 128 + ((lc ^ (kr & 7)) * 16));
                mma16816h(s[nt * 2 + 0], qa[ks], &kb[0]);
                mma16816h(s[nt * 2 + 1], qa[ks], &kb[2]);
            }
        }

        // online softmax
        float mx0 = -1e30f, mx1 = -1e30f;
#pragma unroll
        for (int nf = 0; nf < 16; nf++) {
            mx0 = fmaxf(mx0, fmaxf(s[nf][0], s[nf][1]));
            mx1 = fmaxf(mx1, fmaxf(s[nf][2], s[nf][3]));
        }
        mx0 = fmaxf(mx0, __shfl_xor_sync(0xffffffffu, mx0, 1));
        mx0 = fmaxf(mx0, __shfl_xor_sync(0xffffffffu, mx0, 2));
        mx1 = fmaxf(mx1, __shfl_xor_sync(0xffffffffu, mx1, 1));
        mx1 = fmaxf(mx1, __shfl_xor_sync(0xffffffffu, mx1, 2));

        float mn0 = fmaxf(m0, mx0);
        float mn1 = fmaxf(m1, mx1);
        float sc0 = ex2f(m0 - mn0);
        float sc1 = ex2f(m1 - mn1);

        float ps0 = 0.f, ps1 = 0.f;
#pragma unroll
        for (int nf = 0; nf < 16; nf++) {
            s[nf][0] = ex2f(s[nf][0] - mn0);
            s[nf][1] = ex2f(s[nf][1] - mn0);
            s[nf][2] = ex2f(s[nf][2] - mn1);
            s[nf][3] = ex2f(s[nf][3] - mn1);
            ps0 += s[nf][0] + s[nf][1];
            ps1 += s[nf][2] + s[nf][3];
        }
        ps0 += __shfl_xor_sync(0xffffffffu, ps0, 1);
        ps0 += __shfl_xor_sync(0xffffffffu, ps0, 2);
        ps1 += __shfl_xor_sync(0xffffffffu, ps1, 1);
        ps1 += __shfl_xor_sync(0xffffffffu, ps1, 2);

        sum0 = sum0 * sc0 + ps0;  m0 = mn0;
        sum1 = sum1 * sc1 + ps1;  m1 = mn1;

#pragma unroll
        for (int nf = 0; nf < 8; nf++) {
            o[nf][0] *= sc0; o[nf][1] *= sc0;
            o[nf][2] *= sc1; o[nf][3] *= sc1;
        }

        // P C-frags -> A-frags (register cvt)
        uint32_t pa[8][4];
#pragma unroll
        for (int kt = 0; kt < 8; kt++) {
            __half2 h0 = __floats2half2_rn(s[2 * kt][0],     s[2 * kt][1]);
            __half2 h1 = __floats2half2_rn(s[2 * kt][2],     s[2 * kt][3]);
            __half2 h2 = __floats2half2_rn(s[2 * kt + 1][0], s[2 * kt + 1][1]);
            __half2 h3 = __floats2half2_rn(s[2 * kt + 1][2], s[2 * kt + 1][3]);
            pa[kt][0] = *reinterpret_cast<uint32_t*>(&h0);
            pa[kt][1] = *reinterpret_cast<uint32_t*>(&h1);
            pa[kt][2] = *reinterpret_cast<uint32_t*>(&h2);
            pa[kt][3] = *reinterpret_cast<uint32_t*>(&h3);
        }

        // O += P V  (P 16x128, V 128x64 via ldmatrix.trans)
#pragma unroll
        for (int kt = 0; kt < 8; kt++) {
#pragma unroll
            for (int nt = 0; nt < 4; nt++) {
                uint32_t vb[4];
                int vr = kt * 16 + v_row;
                int lc = nt * 2 + v_ch;
                ldsm_x4_t(vb, sV + vr * 128 + ((lc ^ (vr & 7)) * 16));
                mma16816h(o[nt * 2 + 0], pa[kt], &vb[0]);
                mma16816h(o[nt * 2 + 1], pa[kt], &vb[2]);
            }
        }
        // no bottom barrier (double-buffered; see gemm comment)
    }

    // epilogue: normalize, write fp16 to g_Oh in [b, s, e] layout
    const int b = bh >> 4;
    const int h = bh & (NH - 1);
    const float inv0 = 1.f / sum0;
    const float inv1 = 1.f / sum1;
    const int r0 = it * 64 + w * 16 + (lane >> 2);
#pragma unroll
    for (int nf = 0; nf < 8; nf++) {
        int col = h * HD + nf * 8 + (lane & 3) * 2;
        __half2 v0 = __floats2half2_rn(o[nf][0] * inv0, o[nf][1] * inv0);
        __half2 v1 = __floats2half2_rn(o[nf][2] * inv1, o[nf][3] * inv1);
        *(__half2*)(g_Oh + ((size_t)(b * SEQ + r0))     * EMB + col) = v0;
        *(__half2*)(g_Oh + ((size_t)(b * SEQ + r0 + 8)) * EMB + col) = v1;
    }
}

// ---------------------------------------------------------------------------

extern "C" void kernel_launch(void* const* d_in, const int* in_sizes, int n_in,
                              void* d_out, int out_size)
{
    (void)in_sizes; (void)n_in; (void)out_size;
    const float* x   = (const float*)d_in[0];
    const float* w_q = (const float*)d_in[1];
    const float* b_q = (const float*)d_in[2];
    const float* w_k = (const float*)d_in[3];
    const float* b_k = (const float*)d_in[4];
    const float* w_v = (const float*)d_in[5];
    const float* b_v = (const float*)d_in[6];
    const float* w_o = (const float*)d_in[7];
    const float* b_o = (const float*)d_in[8];
    float* out = (float*)d_out;

    cudaFuncSetAttribute(attn_tc_kernel, cudaFuncAttributeMaxDynamicSharedMemorySize,
                         ATTN_SMEM);

    // fused pre-convert (x + 4 weight matrices) in one launch
    cvt_all_kernel<<<(NX4 + 4 * NW4 + 255) / 256, 256>>>(x, w_q, w_k, w_v, w_o);

    // fused Q/K/V projections
    gemm_h_kernel<<<dim3(EMB / 128, TOK / 128, 3), 256>>>(0, b_q, b_k, b_v, nullptr);

    attn_tc_kernel<<<dim3(SEQ / 64, BHN), 128, ATTN_SMEM>>>();

    // out projection
    gemm_h_kernel<<<dim3(EMB / 128, TOK / 128, 1), 256>>>(1, b_o, nullptr, nullptr, out);
}

// round 8
// speedup vs baseline: 8.1786x; 1.0032x over previous
#include <cuda_runtime.h>
#include <cuda_fp16.h>
#include <cstdint>
#include <math.h>

#define SEQ 2048
#define EMB 1024
#define NH  16
#define HD  64
#define NB  4
#define TOK (NB * SEQ)     // 8192
#define BHN (NB * NH)      // 64

// Scratch (device globals: allocation-free rule)
__device__ __align__(128) __half g_Qh[(size_t)BHN * SEQ * HD];
__device__ __align__(128) __half g_Kh[(size_t)BHN * SEQ * HD];
__device__ __align__(128) __half g_Vh[(size_t)BHN * SEQ * HD];
__device__ __align__(128) __half g_Xh[(size_t)TOK * EMB];
__device__ __align__(128) __half g_Oh[(size_t)TOK * EMB];
__device__ __align__(128) __half g_Wh[(size_t)4 * EMB * EMB];

// ---------------------------------------------------------------------------
// PTX helpers
// ---------------------------------------------------------------------------
__device__ __forceinline__ uint32_t smem_to_u32(const void* p) {
    uint32_t a;
    asm("{ .reg .u64 t; cvta.to.shared.u64 t, %1; cvt.u32.u64 %0, t; }" : "=r"(a) : "l"(p));
    return a;
}
__device__ __forceinline__ void ldsm_x4(uint32_t* r, uint32_t addr) {
    asm volatile("ldmatrix.sync.aligned.m8n8.x4.shared.b16 {%0,%1,%2,%3}, [%4];"
        : "=r"(r[0]), "=r"(r[1]), "=r"(r[2]), "=r"(r[3]) : "r"(addr));
}
__device__ __forceinline__ void ldsm_x4_t(uint32_t* r, uint32_t addr) {
    asm volatile("ldmatrix.sync.aligned.m8n8.x4.trans.shared.b16 {%0,%1,%2,%3}, [%4];"
        : "=r"(r[0]), "=r"(r[1]), "=r"(r[2]), "=r"(r[3]) : "r"(addr));
}
__device__ __forceinline__ void mma16816h(float* c, const uint32_t* a, const uint32_t* b) {
    asm volatile("mma.sync.aligned.m16n8k16.row.col.f32.f16.f16.f32 "
        "{%0,%1,%2,%3}, {%4,%5,%6,%7}, {%8,%9}, {%0,%1,%2,%3};"
        : "+f"(c[0]), "+f"(c[1]), "+f"(c[2]), "+f"(c[3])
        : "r"(a[0]), "r"(a[1]), "r"(a[2]), "r"(a[3]), "r"(b[0]), "r"(b[1]));
}
__device__ __forceinline__ float ex2f(float x) {
    float r;
    asm("ex2.approx.f32 %0, %1;" : "=f"(r) : "f"(x));
    return r;
}
__device__ __forceinline__ void cp_async16(uint32_t dst, const void* src) {
    asm volatile("cp.async.cg.shared.global [%0], [%1], 16;" :: "r"(dst), "l"(src));
}
#define CP_COMMIT() asm volatile("cp.async.commit_group;" ::: "memory")
#define CP_WAIT0()  asm volatile("cp.async.wait_group 0;" ::: "memory")

// Q pre-scale: 1/sqrt(HD) * log2(e)
#define QSCALE 0.1803368801111244f

// ---------------------------------------------------------------------------
// Fused pre-convert fp32 -> fp16: x then w_q|w_k|w_v|w_o (one launch).
// ---------------------------------------------------------------------------
#define NX4 (TOK * EMB / 4)
#define NW4 (EMB * EMB / 4)

__global__ __launch_bounds__(256) void cvt_all_kernel(
    const float* __restrict__ x,
    const float* __restrict__ wq, const float* __restrict__ wk,
    const float* __restrict__ wv, const float* __restrict__ wo)
{
    int i = blockIdx.x * blockDim.x + threadIdx.x;
    const float4* src;
    uint2* dst;
    if (i < NX4) {
        src = (const float4*)x + i;
        dst = (uint2*)g_Xh + i;
    } else {
        int j = i - NX4;
        int w = j / NW4;
        int r = j - w * NW4;
        const float* s = (w == 0) ? wq : (w == 1) ? wk : (w == 2) ? wv : wo;
        src = (const float4*)s + r;
        dst = (uint2*)g_Wh + j;
    }
    float4 v = *src;
    __half2 h0 = __floats2half2_rn(v.x, v.y);
    __half2 h1 = __floats2half2_rn(v.z, v.w);
    uint2 o = { *reinterpret_cast<uint32_t*>(&h0), *reinterpret_cast<uint32_t*>(&h1) };
    *dst = o;
}

// ---------------------------------------------------------------------------
// fp16 GEMM, BK=64, cp.async 2-stage + register double-buffered fragments.
// C[m,n] = sum_k A[m,k]*W[n,k] + bias[n].  CTA 128x128, 8 warps (32x64 each).
// mode 0: fused QKV (blockIdx.z selects W + scatter dest).
// mode 1: out projection (A = g_Oh, W = W[3], fp32 store + bias).
// smem/stage: A 16KB | B 16KB; 2 stages = 64KB static.
// Rows 128B (64 fp16); chunk16 swizzle: ch ^ (row&7).
// ---------------------------------------------------------------------------
#define GSTG 32768

__device__ __forceinline__ void gemm_stage64(
    uint32_t sbs, int tid, int bm, int bn, int k0,
    const __half* __restrict__ Ag, const __half* __restrict__ Bg)
{
#pragma unroll
    for (int l = 0; l < 8; l++) {
        const int buf = l >> 2;                 // 0=A, 1=B
        int i   = (l & 3) * 256 + tid;          // 0..1023
        int row = i >> 3;                       // 0..127
        int ch  = i & 7;
        uint32_t dst = sbs + buf * 16384 + row * 128 + ((ch ^ (row & 7)) * 16);
        const __half* src = (buf ? Bg + (size_t)(bn + row) * EMB
                                 : Ag + (size_t)(bm + row) * EMB) + k0 + ch * 8;
        cp_async16(dst, src);
    }
}

__device__ __forceinline__ void load_afrag(
    uint32_t sbs, int wm, int a_row, int a_ch, int ks, uint32_t ah[2][4])
{
#pragma unroll
    for (int mi = 0; mi < 2; mi++) {
        int ar = wm * 32 + mi * 16 + a_row;
        int lc = ks * 2 + a_ch;
        ldsm_x4(ah[mi], sbs + ar * 128 + ((lc ^ (ar & 7)) * 16));
    }
}
__device__ __forceinline__ void load_bfrag(
    uint32_t sbs, int wn, int b_row, int b_ch, int ks, uint32_t bb[4][4])
{
#pragma unroll
    for (int np = 0; np < 4; np++) {
        int br = wn * 64 + np * 16 + b_row;
        int lc = ks * 2 + b_ch;
        ldsm_x4(bb[np], sbs + 16384 + br * 128 + ((lc ^ (br & 7)) * 16));
    }
}

__global__ __launch_bounds__(256, 2) void gemm_h_kernel(
    int mode,
    const float* __restrict__ bias0,
    const float* __restrict__ bias1,
    const float* __restrict__ bias2,
    float* __restrict__ Cout)
{
    __shared__ __align__(16) char smem[2 * GSTG];
    uint32_t sb = smem_to_u32(smem);

    const int proj = (mode == 0) ? blockIdx.z : 3;
    const __half* Ag = (mode == 0) ? g_Xh : g_Oh;
    const __half* Bg = g_Wh + (size_t)proj * EMB * EMB;
    const float* bias = (mode == 1) ? bias0
                       : (proj == 0) ? bias0 : (proj == 1) ? bias1 : bias2;

    const int tid  = threadIdx.x;
    const int lane = tid & 31;
    const int w    = tid >> 5;
    const int wm   = w & 3;
    const int wn   = w >> 2;
    const int bm   = blockIdx.y * 128;
    const int bn   = blockIdx.x * 128;

    float acc[2][8][4];
#pragma unroll
    for (int i = 0; i < 2; i++)
#pragma unroll
        for (int j = 0; j < 8; j++)
#pragma unroll
            for (int c = 0; c < 4; c++) acc[i][j][c] = 0.f;

    const int a_row = lane & 15;
    const int a_ch  = lane >> 4;
    const int b_row = ((lane >> 4) & 1) * 8 + (lane & 7);
    const int b_ch  = (lane >> 3) & 1;

    const int NK = EMB / 64;
    gemm_stage64(sb, tid, bm, bn, 0, Ag, Bg);
    CP_COMMIT();

    uint32_t ah[2][2][4];
    uint32_t bb[2][4][4];

    for (int kc = 0; kc < NK; kc++) {
        CP_WAIT0();
        __syncthreads();
        if (kc + 1 < NK) {
            gemm_stage64(sb + ((kc + 1) & 1) * GSTG, tid, bm, bn, (kc + 1) * 64, Ag, Bg);
            CP_COMMIT();
        }
        uint32_t sbs = sb + (kc & 1) * GSTG;

        load_afrag(sbs, wm, a_row, a_ch, 0, ah[0]);
        load_bfrag(sbs, wn, b_row, b_ch, 0, bb[0]);
#pragma unroll
        for (int ks = 0; ks < 4; ks++) {
            const int cur = ks & 1;
            if (ks < 3) {
                load_afrag(sbs, wm, a_row, a_ch, ks + 1, ah[1 - cur]);
                load_bfrag(sbs, wn, b_row, b_ch, ks + 1, bb[1 - cur]);
            }
#pragma unroll
            for (int np = 0; np < 4; np++)
#pragma unroll
                for (int sub = 0; sub < 2; sub++)
#pragma unroll
                    for (int mi = 0; mi < 2; mi++)
                        mma16816h(acc[mi][np * 2 + sub], ah[cur][mi], &bb[cur][np][sub * 2]);
        }
    }

    // epilogue
#pragma unroll
    for (int mi = 0; mi < 2; mi++) {
#pragma unroll
        for (int nf = 0; nf < 8; nf++) {
            int col = bn + wn * 64 + nf * 8 + (lane & 3) * 2;
            float2 bv = *(const float2*)(bias + col);
#pragma unroll
            for (int h = 0; h < 2; h++) {
                int m = bm + wm * 32 + mi * 16 + (lane >> 2) + h * 8;
                float2 o;
                o.x = acc[mi][nf][h * 2 + 0] + bv.x;
                o.y = acc[mi][nf][h * 2 + 1] + bv.y;
                if (mode == 1) {
                    *(float2*)(Cout + (size_t)m * EMB + col) = o;
                } else {
                    int b = m >> 11;
                    int s = m & (SEQ - 1);
                    int hh = col >> 6;
                    int d  = col & (HD - 1);
                    float sc = (proj == 0) ? QSCALE : 1.0f;
                    __half2 hv = __floats2half2_rn(o.x * sc, o.y * sc);
                    __half* dst = (proj == 0) ? g_Qh : (proj == 1) ? g_Kh : g_Vh;
                    *(__half2*)(dst + (((size_t)(b * NH + hh)) * SEQ + s) * HD + d) = hv;
                }
            }
        }
    }
}

// ---------------------------------------------------------------------------
// Tensor-core flash attention, fp16 mma, cp.async double-buffered K/V.
// CTA = 256 threads (8 warps); warp owns 16 q rows; CTA q tile = 128.
// KV tile = 128. Dynamic smem: Q 16KB + 2 x (K 16KB + V 16KB) = 80KB.
// 16 warps/SM at occ 2 (vs 8 before) for latency hiding.
// ---------------------------------------------------------------------------
#define ATTN_SMEM (16384 + 2 * 32768)

__global__ __launch_bounds__(256, 2) void attn_tc_kernel()
{
    extern __shared__ __align__(16) char asmem[];
    const uint32_t sQ  = smem_to_u32(asmem);
    const uint32_t sKV = sQ + 16384;

    const int tid  = threadIdx.x;
    const int lane = tid & 31;
    const int w    = tid >> 5;          // 0..7
    const int bh   = blockIdx.y;
    const int it   = blockIdx.x;        // q tile 0..15 (128 rows)

    const __half* Qg = g_Qh + ((size_t)bh * SEQ + (size_t)it * 128) * HD;
    const __half* Kg = g_Kh + (size_t)bh * SEQ * HD;
    const __half* Vg = g_Vh + (size_t)bh * SEQ * HD;

    // stage Q tile (128 rows x 64 halfs, swizzled)
    __half* Qs = (__half*)asmem;
#pragma unroll
    for (int l = 0; l < 4; l++) {
        int idx = tid + l * 256;       // 0..1023
        int row = idx >> 3;            // 0..127
        int ch  = idx & 7;
        *(uint4*)&Qs[row * 64 + ((ch ^ (row & 7)) * 8)] =
            *(const uint4*)(Qg + (size_t)row * HD + ch * 8);
    }

    // prologue: issue KV tile 0 (128 rows each of K and V)
    {
#pragma unroll
        for (int l = 0; l < 8; l++) {
            const int kv = l >> 2;
            int i   = (l & 3) * 256 + tid;       // 0..1023
            int row = i >> 3;                    // 0..127
            int ch  = i & 7;
            uint32_t dst = sKV + kv * 16384 + row * 128 + ((ch ^ (row & 7)) * 16);
            const __half* src = (kv ? Vg : Kg) + (size_t)row * HD + ch * 8;
            cp_async16(dst, src);
        }
        CP_COMMIT();
    }
    __syncthreads();

    // loop-invariant Q A-fragments
    const int a_row = lane & 15;
    const int a_ch  = lane >> 4;
    uint32_t qa[4][4];
#pragma unroll
    for (int ks = 0; ks < 4; ks++) {
        int qr = w * 16 + a_row;
        int lc = ks * 2 + a_ch;
        ldsm_x4(qa[ks], sQ + qr * 128 + ((lc ^ (qr & 7)) * 16));
    }

    const int b_row = ((lane >> 4) & 1) * 8 + (lane & 7);
    const int b_ch  = (lane >> 3) & 1;
    const int v_row = lane & 15;
    const int v_ch  = lane >> 4;

    float o[8][4];
#pragma unroll
    for (int nf = 0; nf < 8; nf++)
#pragma unroll
        for (int c = 0; c < 4; c++) o[nf][c] = 0.f;
    float m0 = -1e30f, m1 = -1e30f, sum0 = 0.f, sum1 = 0.f;

    const int NT = SEQ / 128;
    for (int jt = 0; jt < NT; jt++) {
        CP_WAIT0();
        __syncthreads();
        if (jt + 1 < NT) {
            const __half* kg = Kg + (size_t)(jt + 1) * 128 * HD;
            const __half* vg = Vg + (size_t)(jt + 1) * 128 * HD;
            uint32_t sbs = sKV + ((jt + 1) & 1) * 32768;
#pragma unroll
            for (int l = 0; l < 8; l++) {
                const int kv = l >> 2;
                int i   = (l & 3) * 256 + tid;
                int row = i >> 3;
                int ch  = i & 7;
                uint32_t dst = sbs + kv * 16384 + row * 128 + ((ch ^ (row & 7)) * 16);
                const __half* src = (kv ? vg : kg) + (size_t)row * HD + ch * 8;
                cp_async16(dst, src);
            }
            CP_COMMIT();
        }
        uint32_t sK = sKV + (jt & 1) * 32768;
        uint32_t sV = sK + 16384;

        // S = Q K^T  (16 x 128 per warp)
        float s[16][4];
#pragma unroll
        for (int nf = 0; nf < 16; nf++)
#pragma unroll
            for (int c = 0; c < 4; c++) s[nf][c] = 0.f;
#pragma unroll
        for (int nt = 0; nt < 8; nt++) {
#pragma unroll
            for (int ks = 0; ks < 4; ks++) {
                uint32_t kb[4];
                int kr = nt * 16 + b_row;
                int lc = ks * 2 + b_ch;
                ldsm_x4(kb, sK + kr * 128 + ((lc ^ (kr & 7)) * 16));
                mma16816h(s[nt * 2 + 0], qa[ks], &kb[0]);
                mma16816h(s[nt * 2 + 1], qa[ks], &kb[2]);
            }
        }

        // online softmax
        float mx0 = -1e30f, mx1 = -1e30f;
#pragma unroll
        for (int nf = 0; nf < 16; nf++) {
            mx0 = fmaxf(mx0, fmaxf(s[nf][0], s[nf][1]));
            mx1 = fmaxf(mx1, fmaxf(s[nf][2], s[nf][3]));
        }
        mx0 = fmaxf(mx0, __shfl_xor_sync(0xffffffffu, mx0, 1));
        mx0 = fmaxf(mx0, __shfl_xor_sync(0xffffffffu, mx0, 2));
        mx1 = fmaxf(mx1, __shfl_xor_sync(0xffffffffu, mx1, 1));
        mx1 = fmaxf(mx1, __shfl_xor_sync(0xffffffffu, mx1, 2));

        float mn0 = fmaxf(m0, mx0);
        float mn1 = fmaxf(m1, mx1);
        float sc0 = ex2f(m0 - mn0);
        float sc1 = ex2f(m1 - mn1);

        float ps0 = 0.f, ps1 = 0.f;
#pragma unroll
        for (int nf = 0; nf < 16; nf++) {
            s[nf][0] = ex2f(s[nf][0] - mn0);
            s[nf][1] = ex2f(s[nf][1] - mn0);
            s[nf][2] = ex2f(s[nf][2] - mn1);
            s[nf][3] = ex2f(s[nf][3] - mn1);
            ps0 += s[nf][0] + s[nf][1];
            ps1 += s[nf][2] + s[nf][3];
        }
        ps0 += __shfl_xor_sync(0xffffffffu, ps0, 1);
        ps0 += __shfl_xor_sync(0xffffffffu, ps0, 2);
        ps1 += __shfl_xor_sync(0xffffffffu, ps1, 1);
        ps1 += __shfl_xor_sync(0xffffffffu, ps1, 2);

        sum0 = sum0 * sc0 + ps0;  m0 = mn0;
        sum1 = sum1 * sc1 + ps1;  m1 = mn1;

#pragma unroll
        for (int nf = 0; nf < 8; nf++) {
            o[nf][0] *= sc0; o[nf][1] *= sc0;
            o[nf][2] *= sc1; o[nf][3] *= sc1;
        }

        // P C-frags -> A-frags (register cvt)
        uint32_t pa[8][4];
#pragma unroll
        for (int kt = 0; kt < 8; kt++) {
            __half2 h0 = __floats2half2_rn(s[2 * kt][0],     s[2 * kt][1]);
            __half2 h1 = __floats2half2_rn(s[2 * kt][2],     s[2 * kt][3]);
            __half2 h2 = __floats2half2_rn(s[2 * kt + 1][0], s[2 * kt + 1][1]);
            __half2 h3 = __floats2half2_rn(s[2 * kt + 1][2], s[2 * kt + 1][3]);
            pa[kt][0] = *reinterpret_cast<uint32_t*>(&h0);
            pa[kt][1] = *reinterpret_cast<uint32_t*>(&h1);
            pa[kt][2] = *reinterpret_cast<uint32_t*>(&h2);
            pa[kt][3] = *reinterpret_cast<uint32_t*>(&h3);
        }

        // O += P V  (P 16x128, V 128x64 via ldmatrix.trans)
#pragma unroll
        for (int kt = 0; kt < 8; kt++) {
#pragma unroll
            for (int nt = 0; nt < 4; nt++) {
                uint32_t vb[4];
                int vr = kt * 16 + v_row;
                int lc = nt * 2 + v_ch;
                ldsm_x4_t(vb, sV + vr * 128 + ((lc ^ (vr & 7)) * 16));
                mma16816h(o[nt * 2 + 0], pa[kt], &vb[0]);
                mma16816h(o[nt * 2 + 1], pa[kt], &vb[2]);
            }
        }
    }

    // epilogue: normalize, write fp16 to g_Oh in [b, s, e] layout
    const int b = bh >> 4;
    const int h = bh & (NH - 1);
    const float inv0 = 1.f / sum0;
    const float inv1 = 1.f / sum1;
    const int r0 = it * 128 + w * 16 + (lane >> 2);
#pragma unroll
    for (int nf = 0; nf < 8; nf++) {
        int col = h * HD + nf * 8 + (lane & 3) * 2;
        __half2 v0 = __floats2half2_rn(o[nf][0] * inv0, o[nf][1] * inv0);
        __half2 v1 = __floats2half2_rn(o[nf][2] * inv1, o[nf][3] * inv1);
        *(__half2*)(g_Oh + ((size_t)(b * SEQ + r0))     * EMB + col) = v0;
        *(__half2*)(g_Oh + ((size_t)(b * SEQ + r0 + 8)) * EMB + col) = v1;
    }
}

// ---------------------------------------------------------------------------

extern "C" void kernel_launch(void* const* d_in, const int* in_sizes, int n_in,
                              void* d_out, int out_size)
{
    (void)in_sizes; (void)n_in; (void)out_size;
    const float* x   = (const float*)d_in[0];
    const float* w_q = (const float*)d_in[1];
    const float* b_q = (const float*)d_in[2];
    const float* w_k = (const float*)d_in[3];
    const float* b_k = (const float*)d_in[4];
    const float* w_v = (const float*)d_in[5];
    const float* b_v = (const float*)d_in[6];
    const float* w_o = (const float*)d_in[7];
    const float* b_o = (const float*)d_in[8];
    float* out = (float*)d_out;

    cudaFuncSetAttribute(attn_tc_kernel, cudaFuncAttributeMaxDynamicSharedMemorySize,
                         ATTN_SMEM);

    // fused pre-convert (x + 4 weight matrices) in one launch
    cvt_all_kernel<<<(NX4 + 4 * NW4 + 255) / 256, 256>>>(x, w_q, w_k, w_v, w_o);

    // fused Q/K/V projections
    gemm_h_kernel<<<dim3(EMB / 128, TOK / 128, 3), 256>>>(0, b_q, b_k, b_v, nullptr);

    attn_tc_kernel<<<dim3(SEQ / 128, BHN), 256, ATTN_SMEM>>>();

    // out projection
    gemm_h_kernel<<<dim3(EMB / 128, TOK / 128, 1), 256>>>(1, b_o, nullptr, nullptr, out);
}

// round 9
// speedup vs baseline: 8.2954x; 1.0143x over previous
#include <cuda_runtime.h>
#include <cuda_fp16.h>
#include <cstdint>
#include <math.h>

#define SEQ 2048
#define EMB 1024
#define NH  16
#define HD  64
#define NB  4
#define TOK (NB * SEQ)     // 8192
#define BHN (NB * NH)      // 64

// Scratch (device globals: allocation-free rule)
__device__ __align__(128) __half g_Qh[(size_t)BHN * SEQ * HD];
__device__ __align__(128) __half g_Kh[(size_t)BHN * SEQ * HD];
__device__ __align__(128) __half g_Vh[(size_t)BHN * SEQ * HD];
__device__ __align__(128) __half g_Xh[(size_t)TOK * EMB];
__device__ __align__(128) __half g_Oh[(size_t)TOK * EMB];
__device__ __align__(128) __half g_Wh[(size_t)4 * EMB * EMB];

// ---------------------------------------------------------------------------
// PTX helpers
// ---------------------------------------------------------------------------
__device__ __forceinline__ uint32_t smem_to_u32(const void* p) {
    uint32_t a;
    asm("{ .reg .u64 t; cvta.to.shared.u64 t, %1; cvt.u32.u64 %0, t; }" : "=r"(a) : "l"(p));
    return a;
}
__device__ __forceinline__ void ldsm_x4(uint32_t* r, uint32_t addr) {
    asm volatile("ldmatrix.sync.aligned.m8n8.x4.shared.b16 {%0,%1,%2,%3}, [%4];"
        : "=r"(r[0]), "=r"(r[1]), "=r"(r[2]), "=r"(r[3]) : "r"(addr));
}
__device__ __forceinline__ void ldsm_x4_t(uint32_t* r, uint32_t addr) {
    asm volatile("ldmatrix.sync.aligned.m8n8.x4.trans.shared.b16 {%0,%1,%2,%3}, [%4];"
        : "=r"(r[0]), "=r"(r[1]), "=r"(r[2]), "=r"(r[3]) : "r"(addr));
}
__device__ __forceinline__ void mma16816h(float* c, const uint32_t* a, const uint32_t* b) {
    asm volatile("mma.sync.aligned.m16n8k16.row.col.f32.f16.f16.f32 "
        "{%0,%1,%2,%3}, {%4,%5,%6,%7}, {%8,%9}, {%0,%1,%2,%3};"
        : "+f"(c[0]), "+f"(c[1]), "+f"(c[2]), "+f"(c[3])
        : "r"(a[0]), "r"(a[1]), "r"(a[2]), "r"(a[3]), "r"(b[0]), "r"(b[1]));
}
__device__ __forceinline__ float ex2f(float x) {
    float r;
    asm("ex2.approx.f32 %0, %1;" : "=f"(r) : "f"(x));
    return r;
}
__device__ __forceinline__ void cp_async16(uint32_t dst, const void* src) {
    asm volatile("cp.async.cg.shared.global [%0], [%1], 16;" :: "r"(dst), "l"(src));
}
#define CP_COMMIT() asm volatile("cp.async.commit_group;" ::: "memory")
#define CP_WAIT0()  asm volatile("cp.async.wait_group 0;" ::: "memory")
#define CP_WAIT1()  asm volatile("cp.async.wait_group 1;" ::: "memory")

// Q pre-scale: 1/sqrt(HD) * log2(e)
#define QSCALE 0.1803368801111244f

// ---------------------------------------------------------------------------
// Fused pre-convert fp32 -> fp16: x then w_q|w_k|w_v|w_o (one launch).
// ---------------------------------------------------------------------------
#define NX4 (TOK * EMB / 4)
#define NW4 (EMB * EMB / 4)

__global__ __launch_bounds__(256) void cvt_all_kernel(
    const float* __restrict__ x,
    const float* __restrict__ wq, const float* __restrict__ wk,
    const float* __restrict__ wv, const float* __restrict__ wo)
{
    int i = blockIdx.x * blockDim.x + threadIdx.x;
    const float4* src;
    uint2* dst;
    if (i < NX4) {
        src = (const float4*)x + i;
        dst = (uint2*)g_Xh + i;
    } else {
        int j = i - NX4;
        int w = j / NW4;
        int r = j - w * NW4;
        const float* s = (w == 0) ? wq : (w == 1) ? wk : (w == 2) ? wv : wo;
        src = (const float4*)s + r;
        dst = (uint2*)g_Wh + j;
    }
    float4 v = *src;
    __half2 h0 = __floats2half2_rn(v.x, v.y);
    __half2 h1 = __floats2half2_rn(v.z, v.w);
    uint2 o = { *reinterpret_cast<uint32_t*>(&h0), *reinterpret_cast<uint32_t*>(&h1) };
    *dst = o;
}

// ---------------------------------------------------------------------------
// fp16 GEMM, BK=64, 3-stage cp.async pipeline (wait_group 1) + reg-buffered
// fragments. C[m,n] = sum_k A[m,k]*W[n,k] + bias[n]. CTA 128x128, 8 warps.
// mode 0: fused QKV (blockIdx.z selects W + scatter dest).
// mode 1: out projection (A = g_Oh, W = W[3], fp32 store + bias).
// Dynamic smem: 3 stages x (A 16KB | B 16KB) = 96KB.
// Rows 128B (64 fp16); chunk16 swizzle: ch ^ (row&7).
// ---------------------------------------------------------------------------
#define GSTG 32768
#define GEMM_SMEM (3 * GSTG)

__device__ __forceinline__ void gemm_stage64(
    uint32_t sbs, int tid, int bm, int bn, int k0,
    const __half* __restrict__ Ag, const __half* __restrict__ Bg)
{
#pragma unroll
    for (int l = 0; l < 8; l++) {
        const int buf = l >> 2;                 // 0=A, 1=B
        int i   = (l & 3) * 256 + tid;          // 0..1023
        int row = i >> 3;                       // 0..127
        int ch  = i & 7;
        uint32_t dst = sbs + buf * 16384 + row * 128 + ((ch ^ (row & 7)) * 16);
        const __half* src = (buf ? Bg + (size_t)(bn + row) * EMB
                                 : Ag + (size_t)(bm + row) * EMB) + k0 + ch * 8;
        cp_async16(dst, src);
    }
}

__device__ __forceinline__ void load_afrag(
    uint32_t sbs, int wm, int a_row, int a_ch, int ks, uint32_t ah[2][4])
{
#pragma unroll
    for (int mi = 0; mi < 2; mi++) {
        int ar = wm * 32 + mi * 16 + a_row;
        int lc = ks * 2 + a_ch;
        ldsm_x4(ah[mi], sbs + ar * 128 + ((lc ^ (ar & 7)) * 16));
    }
}
__device__ __forceinline__ void load_bfrag(
    uint32_t sbs, int wn, int b_row, int b_ch, int ks, uint32_t bb[4][4])
{
#pragma unroll
    for (int np = 0; np < 4; np++) {
        int br = wn * 64 + np * 16 + b_row;
        int lc = ks * 2 + b_ch;
        ldsm_x4(bb[np], sbs + 16384 + br * 128 + ((lc ^ (br & 7)) * 16));
    }
}

__global__ __launch_bounds__(256, 2) void gemm_h_kernel(
    int mode,
    const float* __restrict__ bias0,
    const float* __restrict__ bias1,
    const float* __restrict__ bias2,
    float* __restrict__ Cout)
{
    extern __shared__ __align__(16) char gsmem[];
    uint32_t sb = smem_to_u32(gsmem);

    const int proj = (mode == 0) ? blockIdx.z : 3;
    const __half* Ag = (mode == 0) ? g_Xh : g_Oh;
    const __half* Bg = g_Wh + (size_t)proj * EMB * EMB;
    const float* bias = (mode == 1) ? bias0
                       : (proj == 0) ? bias0 : (proj == 1) ? bias1 : bias2;

    const int tid  = threadIdx.x;
    const int lane = tid & 31;
    const int w    = tid >> 5;
    const int wm   = w & 3;
    const int wn   = w >> 2;
    const int bm   = blockIdx.y * 128;
    const int bn   = blockIdx.x * 128;

    float acc[2][8][4];
#pragma unroll
    for (int i = 0; i < 2; i++)
#pragma unroll
        for (int j = 0; j < 8; j++)
#pragma unroll
            for (int c = 0; c < 4; c++) acc[i][j][c] = 0.f;

    const int a_row = lane & 15;
    const int a_ch  = lane >> 4;
    const int b_row = ((lane >> 4) & 1) * 8 + (lane & 7);
    const int b_ch  = (lane >> 3) & 1;

    const int NK = EMB / 64;
    gemm_stage64(sb,        tid, bm, bn, 0,  Ag, Bg);
    CP_COMMIT();
    gemm_stage64(sb + GSTG, tid, bm, bn, 64, Ag, Bg);
    CP_COMMIT();

    uint32_t ah[2][2][4];
    uint32_t bb[2][4][4];

    int st_cur = 0, st_nxt = 2;
    for (int kc = 0; kc < NK; kc++) {
        if (kc + 1 < NK) { CP_WAIT1(); } else { CP_WAIT0(); }
        __syncthreads();
        if (kc + 2 < NK) {
            gemm_stage64(sb + st_nxt * GSTG, tid, bm, bn, (kc + 2) * 64, Ag, Bg);
            CP_COMMIT();
        }
        uint32_t sbs = sb + st_cur * GSTG;

        load_afrag(sbs, wm, a_row, a_ch, 0, ah[0]);
        load_bfrag(sbs, wn, b_row, b_ch, 0, bb[0]);
#pragma unroll
        for (int ks = 0; ks < 4; ks++) {
            const int cur = ks & 1;
            if (ks < 3) {
                load_afrag(sbs, wm, a_row, a_ch, ks + 1, ah[1 - cur]);
                load_bfrag(sbs, wn, b_row, b_ch, ks + 1, bb[1 - cur]);
            }
#pragma unroll
            for (int np = 0; np < 4; np++)
#pragma unroll
                for (int sub = 0; sub < 2; sub++)
#pragma unroll
                    for (int mi = 0; mi < 2; mi++)
                        mma16816h(acc[mi][np * 2 + sub], ah[cur][mi], &bb[cur][np][sub * 2]);
        }
        st_cur = (st_cur + 1 == 3) ? 0 : st_cur + 1;
        st_nxt = (st_nxt + 1 == 3) ? 0 : st_nxt + 1;
    }

    // epilogue
#pragma unroll
    for (int mi = 0; mi < 2; mi++) {
#pragma unroll
        for (int nf = 0; nf < 8; nf++) {
            int col = bn + wn * 64 + nf * 8 + (lane & 3) * 2;
            float2 bv = *(const float2*)(bias + col);
#pragma unroll
            for (int h = 0; h < 2; h++) {
                int m = bm + wm * 32 + mi * 16 + (lane >> 2) + h * 8;
                float2 o;
                o.x = acc[mi][nf][h * 2 + 0] + bv.x;
                o.y = acc[mi][nf][h * 2 + 1] + bv.y;
                if (mode == 1) {
                    *(float2*)(Cout + (size_t)m * EMB + col) = o;
                } else {
                    int b = m >> 11;
                    int s = m & (SEQ - 1);
                    int hh = col >> 6;
                    int d  = col & (HD - 1);
                    float sc = (proj == 0) ? QSCALE : 1.0f;
                    __half2 hv = __floats2half2_rn(o.x * sc, o.y * sc);
                    __half* dst = (proj == 0) ? g_Qh : (proj == 1) ? g_Kh : g_Vh;
                    *(__half2*)(dst + (((size_t)(b * NH + hh)) * SEQ + s) * HD + d) = hv;
                }
            }
        }
    }
}

// ---------------------------------------------------------------------------
// Tensor-core flash attention, fp16 mma, 3-stage cp.async KV pipeline.
// CTA = 256 threads (8 warps); warp owns 16 q rows; CTA q tile = 128.
// KV tile = 128. Dynamic smem: Q 16KB + 3 x (K 16KB + V 16KB) = 112KB.
// ---------------------------------------------------------------------------
#define KVSTG 32768
#define ATTN_SMEM (16384 + 3 * KVSTG)

__device__ __forceinline__ void attn_stage_kv(
    uint32_t sbs, int tid, const __half* kg, const __half* vg)
{
#pragma unroll
    for (int l = 0; l < 8; l++) {
        const int kv = l >> 2;
        int i   = (l & 3) * 256 + tid;       // 0..1023
        int row = i >> 3;                    // 0..127
        int ch  = i & 7;
        uint32_t dst = sbs + kv * 16384 + row * 128 + ((ch ^ (row & 7)) * 16);
        const __half* src = (kv ? vg : kg) + (size_t)row * HD + ch * 8;
        cp_async16(dst, src);
    }
}

__global__ __launch_bounds__(256, 2) void attn_tc_kernel()
{
    extern __shared__ __align__(16) char asmem[];
    const uint32_t sQ  = smem_to_u32(asmem);
    const uint32_t sKV = sQ + 16384;

    const int tid  = threadIdx.x;
    const int lane = tid & 31;
    const int w    = tid >> 5;          // 0..7
    const int bh   = blockIdx.y;
    const int it   = blockIdx.x;        // q tile 0..15 (128 rows)

    const __half* Qg = g_Qh + ((size_t)bh * SEQ + (size_t)it * 128) * HD;
    const __half* Kg = g_Kh + (size_t)bh * SEQ * HD;
    const __half* Vg = g_Vh + (size_t)bh * SEQ * HD;

    // stage Q tile (128 rows x 64 halfs, swizzled)
    __half* Qs = (__half*)asmem;
#pragma unroll
    for (int l = 0; l < 4; l++) {
        int idx = tid + l * 256;       // 0..1023
        int row = idx >> 3;            // 0..127
        int ch  = idx & 7;
        *(uint4*)&Qs[row * 64 + ((ch ^ (row & 7)) * 8)] =
            *(const uint4*)(Qg + (size_t)row * HD + ch * 8);
    }

    // prologue: issue KV tiles 0 and 1
    attn_stage_kv(sKV,         tid, Kg, Vg);
    CP_COMMIT();
    attn_stage_kv(sKV + KVSTG, tid, Kg + (size_t)128 * HD, Vg + (size_t)128 * HD);
    CP_COMMIT();
    __syncthreads();

    // loop-invariant Q A-fragments
    const int a_row = lane & 15;
    const int a_ch  = lane >> 4;
    uint32_t qa[4][4];
#pragma unroll
    for (int ks = 0; ks < 4; ks++) {
        int qr = w * 16 + a_row;
        int lc = ks * 2 + a_ch;
        ldsm_x4(qa[ks], sQ + qr * 128 + ((lc ^ (qr & 7)) * 16));
    }

    const int b_row = ((lane >> 4) & 1) * 8 + (lane & 7);
    const int b_ch  = (lane >> 3) & 1;
    const int v_row = lane & 15;
    const int v_ch  = lane >> 4;

    float o[8][4];
#pragma unroll
    for (int nf = 0; nf < 8; nf++)
#pragma unroll
        for (int c = 0; c < 4; c++) o[nf][c] = 0.f;
    float m0 = -1e30f, m1 = -1e30f, sum0 = 0.f, sum1 = 0.f;

    const int NT = SEQ / 128;
    int st_cur = 0, st_nxt = 2;
    for (int jt = 0; jt < NT; jt++) {
        if (jt + 1 < NT) { CP_WAIT1(); } else { CP_WAIT0(); }
        __syncthreads();
        if (jt + 2 < NT) {
            attn_stage_kv(sKV + st_nxt * KVSTG, tid,
                          Kg + (size_t)(jt + 2) * 128 * HD,
                          Vg + (size_t)(jt + 2) * 128 * HD);
            CP_COMMIT();
        }
        uint32_t sK = sKV + st_cur * KVSTG;
        uint32_t sV = sK + 16384;

        // S = Q K^T  (16 x 128 per warp)
        float s[16][4];
#pragma unroll
        for (int nf = 0; nf < 16; nf++)
#pragma unroll
            for (int c = 0; c < 4; c++) s[nf][c] = 0.f;
#pragma unroll
        for (int nt = 0; nt < 8; nt++) {
#pragma unroll
            for (int ks = 0; ks < 4; ks++) {
                uint32_t kb[4];
                int kr = nt * 16 + b_row;
                int lc = ks * 2 + b_ch;
                ldsm_x4(kb, sK + kr * 128 + ((lc ^ (kr & 7)) * 16));
                mma16816h(s[nt * 2 + 0], qa[ks], &kb[0]);
                mma16816h(s[nt * 2 + 1], qa[ks], &kb[2]);
            }
        }

        // online softmax
        float mx0 = -1e30f, mx1 = -1e30f;
#pragma unroll
        for (int nf = 0; nf < 16; nf++) {
            mx0 = fmaxf(mx0, fmaxf(s[nf][0], s[nf][1]));
            mx1 = fmaxf(mx1, fmaxf(s[nf][2], s[nf][3]));
        }
        mx0 = fmaxf(mx0, __shfl_xor_sync(0xffffffffu, mx0, 1));
        mx0 = fmaxf(mx0, __shfl_xor_sync(0xffffffffu, mx0, 2));
        mx1 = fmaxf(mx1, __shfl_xor_sync(0xffffffffu, mx1, 1));
        mx1 = fmaxf(mx1, __shfl_xor_sync(0xffffffffu, mx1, 2));

        float mn0 = fmaxf(m0, mx0);
        float mn1 = fmaxf(m1, mx1);
        float sc0 = ex2f(m0 - mn0);
        float sc1 = ex2f(m1 - mn1);

        float ps0 = 0.f, ps1 = 0.f;
#pragma unroll
        for (int nf = 0; nf < 16; nf++) {
            s[nf][0] = ex2f(s[nf][0] - mn0);
            s[nf][1] = ex2f(s[nf][1] - mn0);
            s[nf][2] = ex2f(s[nf][2] - mn1);
            s[nf][3] = ex2f(s[nf][3] - mn1);
            ps0 += s[nf][0] + s[nf][1];
            ps1 += s[nf][2] + s[nf][3];
        }
        ps0 += __shfl_xor_sync(0xffffffffu, ps0, 1);
        ps0 += __shfl_xor_sync(0xffffffffu, ps0, 2);
        ps1 += __shfl_xor_sync(0xffffffffu, ps1, 1);
        ps1 += __shfl_xor_sync(0xffffffffu, ps1, 2);

        sum0 = sum0 * sc0 + ps0;  m0 = mn0;
        sum1 = sum1 * sc1 + ps1;  m1 = mn1;

#pragma unroll
        for (int nf = 0; nf < 8; nf++) {
            o[nf][0] *= sc0; o[nf][1] *= sc0;
            o[nf][2] *= sc1; o[nf][3] *= sc1;
        }

        // P C-frags -> A-frags (register cvt)
        uint32_t pa[8][4];
#pragma unroll
        for (int kt = 0; kt < 8; kt++) {
            __half2 h0 = __floats2half2_rn(s[2 * kt][0],     s[2 * kt][1]);
            __half2 h1 = __floats2half2_rn(s[2 * kt][2],     s[2 * kt][3]);
            __half2 h2 = __floats2half2_rn(s[2 * kt + 1][0], s[2 * kt + 1][1]);
            __half2 h3 = __floats2half2_rn(s[2 * kt + 1][2], s[2 * kt + 1][3]);
            pa[kt][0] = *reinterpret_cast<uint32_t*>(&h0);
            pa[kt][1] = *reinterpret_cast<uint32_t*>(&h1);
            pa[kt][2] = *reinterpret_cast<uint32_t*>(&h2);
            pa[kt][3] = *reinterpret_cast<uint32_t*>(&h3);
        }

        // O += P V  (P 16x128, V 128x64 via ldmatrix.trans)
#pragma unroll
        for (int kt = 0; kt < 8; kt++) {
#pragma unroll
            for (int nt = 0; nt < 4; nt++) {
                uint32_t vb[4];
                int vr = kt * 16 + v_row;
                int lc = nt * 2 + v_ch;
                ldsm_x4_t(vb, sV + vr * 128 + ((lc ^ (vr & 7)) * 16));
                mma16816h(o[nt * 2 + 0], pa[kt], &vb[0]);
                mma16816h(o[nt * 2 + 1], pa[kt], &vb[2]);
            }
        }
        st_cur = (st_cur + 1 == 3) ? 0 : st_cur + 1;
        st_nxt = (st_nxt + 1 == 3) ? 0 : st_nxt + 1;
    }

    // epilogue: normalize, write fp16 to g_Oh in [b, s, e] layout
    const int b = bh >> 4;
    const int h = bh & (NH - 1);
    const float inv0 = 1.f / sum0;
    const float inv1 = 1.f / sum1;
    const int r0 = it * 128 + w * 16 + (lane >> 2);
#pragma unroll
    for (int nf = 0; nf < 8; nf++) {
        int col = h * HD + nf * 8 + (lane & 3) * 2;
        __half2 v0 = __floats2half2_rn(o[nf][0] * inv0, o[nf][1] * inv0);
        __half2 v1 = __floats2half2_rn(o[nf][2] * inv1, o[nf][3] * inv1);
        *(__half2*)(g_Oh + ((size_t)(b * SEQ + r0))     * EMB + col) = v0;
        *(__half2*)(g_Oh + ((size_t)(b * SEQ + r0 + 8)) * EMB + col) = v1;
    }
}

// ---------------------------------------------------------------------------

extern "C" void kernel_launch(void* const* d_in, const int* in_sizes, int n_in,
                              void* d_out, int out_size)
{
    (void)in_sizes; (void)n_in; (void)out_size;
    const float* x   = (const float*)d_in[0];
    const float* w_q = (const float*)d_in[1];
    const float* b_q = (const float*)d_in[2];
    const float* w_k = (const float*)d_in[3];
    const float* b_k = (const float*)d_in[4];
    const float* w_v = (const float*)d_in[5];
    const float* b_v = (const float*)d_in[6];
    const float* w_o = (const float*)d_in[7];
    const float* b_o = (const float*)d_in[8];
    float* out = (float*)d_out;

    cudaFuncSetAttribute(gemm_h_kernel, cudaFuncAttributeMaxDynamicSharedMemorySize,
                         GEMM_SMEM);
    cudaFuncSetAttribute(attn_tc_kernel, cudaFuncAttributeMaxDynamicSharedMemorySize,
                         ATTN_SMEM);

    // fused pre-convert (x + 4 weight matrices) in one launch
    cvt_all_kernel<<<(NX4 + 4 * NW4 + 255) / 256, 256>>>(x, w_q, w_k, w_v, w_o);

    // fused Q/K/V projections
    gemm_h_kernel<<<dim3(EMB / 128, TOK / 128, 3), 256, GEMM_SMEM>>>(
        0, b_q, b_k, b_v, nullptr);

    attn_tc_kernel<<<dim3(SEQ / 128, BHN), 256, ATTN_SMEM>>>();

    // out projection
    gemm_h_kernel<<<dim3(EMB / 128, TOK / 128, 1), 256, GEMM_SMEM>>>(
        1, b_o, nullptr, nullptr, out);
}

// round 10
// speedup vs baseline: 8.8333x; 1.0648x over previous
#include <cuda_runtime.h>
#include <cuda_fp16.h>
#include <cstdint>
#include <math.h>

#define SEQ 2048
#define EMB 1024
#define NH  16
#define HD  64
#define NB  4
#define TOK (NB * SEQ)     // 8192
#define BHN (NB * NH)      // 64

// Scratch (device globals: allocation-free rule)
__device__ __align__(128) __half g_Qh[(size_t)BHN * SEQ * HD];
__device__ __align__(128) __half g_Kh[(size_t)BHN * SEQ * HD];
__device__ __align__(128) __half g_Vh[(size_t)BHN * SEQ * HD];
__device__ __align__(128) __half g_Xh[(size_t)TOK * EMB];
__device__ __align__(128) __half g_Oh[(size_t)TOK * EMB];
__device__ __align__(128) __half g_Wh[(size_t)4 * EMB * EMB];

// ---------------------------------------------------------------------------
// PTX helpers
// ---------------------------------------------------------------------------
__device__ __forceinline__ uint32_t smem_to_u32(const void* p) {
    uint32_t a;
    asm("{ .reg .u64 t; cvta.to.shared.u64 t, %1; cvt.u32.u64 %0, t; }" : "=r"(a) : "l"(p));
    return a;
}
__device__ __forceinline__ void ldsm_x4(uint32_t* r, uint32_t addr) {
    asm volatile("ldmatrix.sync.aligned.m8n8.x4.shared.b16 {%0,%1,%2,%3}, [%4];"
        : "=r"(r[0]), "=r"(r[1]), "=r"(r[2]), "=r"(r[3]) : "r"(addr));
}
__device__ __forceinline__ void ldsm_x4_t(uint32_t* r, uint32_t addr) {
    asm volatile("ldmatrix.sync.aligned.m8n8.x4.trans.shared.b16 {%0,%1,%2,%3}, [%4];"
        : "=r"(r[0]), "=r"(r[1]), "=r"(r[2]), "=r"(r[3]) : "r"(addr));
}
__device__ __forceinline__ void mma16816h(float* c, const uint32_t* a, const uint32_t* b) {
    asm volatile("mma.sync.aligned.m16n8k16.row.col.f32.f16.f16.f32 "
        "{%0,%1,%2,%3}, {%4,%5,%6,%7}, {%8,%9}, {%0,%1,%2,%3};"
        : "+f"(c[0]), "+f"(c[1]), "+f"(c[2]), "+f"(c[3])
        : "r"(a[0]), "r"(a[1]), "r"(a[2]), "r"(a[3]), "r"(b[0]), "r"(b[1]));
}
__device__ __forceinline__ float ex2f(float x) {
    float r;
    asm("ex2.approx.f32 %0, %1;" : "=f"(r) : "f"(x));
    return r;
}
// pack two fp32 into half2 (lo = a, hi = b), then 2^x elementwise in fp16
__device__ __forceinline__ uint32_t ex2_pack_h2(float a, float b) {
    uint32_t d;
    asm("cvt.rn.f16x2.f32 %0, %1, %2;" : "=r"(d) : "f"(b), "f"(a));
    asm("ex2.approx.f16x2 %0, %0;" : "+r"(d));
    return d;
}
__device__ __forceinline__ void cp_async16(uint32_t dst, const void* src) {
    asm volatile("cp.async.cg.shared.global [%0], [%1], 16;" :: "r"(dst), "l"(src));
}
#define CP_COMMIT() asm volatile("cp.async.commit_group;" ::: "memory")
#define CP_WAIT0()  asm volatile("cp.async.wait_group 0;" ::: "memory")
#define CP_WAIT1()  asm volatile("cp.async.wait_group 1;" ::: "memory")

// Q pre-scale: 1/sqrt(HD) * log2(e)
#define QSCALE 0.1803368801111244f

// ---------------------------------------------------------------------------
// Fused pre-convert fp32 -> fp16: x then w_q|w_k|w_v|w_o (one launch).
// ---------------------------------------------------------------------------
#define NX4 (TOK * EMB / 4)
#define NW4 (EMB * EMB / 4)

__global__ __launch_bounds__(256) void cvt_all_kernel(
    const float* __restrict__ x,
    const float* __restrict__ wq, const float* __restrict__ wk,
    const float* __restrict__ wv, const float* __restrict__ wo)
{
    int i = blockIdx.x * blockDim.x + threadIdx.x;
    const float4* src;
    uint2* dst;
    if (i < NX4) {
        src = (const float4*)x + i;
        dst = (uint2*)g_Xh + i;
    } else {
        int j = i - NX4;
        int w = j / NW4;
        int r = j - w * NW4;
        const float* s = (w == 0) ? wq : (w == 1) ? wk : (w == 2) ? wv : wo;
        src = (const float4*)s + r;
        dst = (uint2*)g_Wh + j;
    }
    float4 v = *src;
    __half2 h0 = __floats2half2_rn(v.x, v.y);
    __half2 h1 = __floats2half2_rn(v.z, v.w);
    uint2 o = { *reinterpret_cast<uint32_t*>(&h0), *reinterpret_cast<uint32_t*>(&h1) };
    *dst = o;
}

// ---------------------------------------------------------------------------
// fp16 GEMM, BK=64, 3-stage cp.async pipeline + reg-buffered fragments.
// (unchanged from R9)
// ---------------------------------------------------------------------------
#define GSTG 32768
#define GEMM_SMEM (3 * GSTG)

__device__ __forceinline__ void gemm_stage64(
    uint32_t sbs, int tid, int bm, int bn, int k0,
    const __half* __restrict__ Ag, const __half* __restrict__ Bg)
{
#pragma unroll
    for (int l = 0; l < 8; l++) {
        const int buf = l >> 2;                 // 0=A, 1=B
        int i   = (l & 3) * 256 + tid;          // 0..1023
        int row = i >> 3;                       // 0..127
        int ch  = i & 7;
        uint32_t dst = sbs + buf * 16384 + row * 128 + ((ch ^ (row & 7)) * 16);
        const __half* src = (buf ? Bg + (size_t)(bn + row) * EMB
                                 : Ag + (size_t)(bm + row) * EMB) + k0 + ch * 8;
        cp_async16(dst, src);
    }
}

__device__ __forceinline__ void load_afrag(
    uint32_t sbs, int wm, int a_row, int a_ch, int ks, uint32_t ah[2][4])
{
#pragma unroll
    for (int mi = 0; mi < 2; mi++) {
        int ar = wm * 32 + mi * 16 + a_row;
        int lc = ks * 2 + a_ch;
        ldsm_x4(ah[mi], sbs + ar * 128 + ((lc ^ (ar & 7)) * 16));
    }
}
__device__ __forceinline__ void load_bfrag(
    uint32_t sbs, int wn, int b_row, int b_ch, int ks, uint32_t bb[4][4])
{
#pragma unroll
    for (int np = 0; np < 4; np++) {
        int br = wn * 64 + np * 16 + b_row;
        int lc = ks * 2 + b_ch;
        ldsm_x4(bb[np], sbs + 16384 + br * 128 + ((lc ^ (br & 7)) * 16));
    }
}

__global__ __launch_bounds__(256, 2) void gemm_h_kernel(
    int mode,
    const float* __restrict__ bias0,
    const float* __restrict__ bias1,
    const float* __restrict__ bias2,
    float* __restrict__ Cout)
{
    extern __shared__ __align__(16) char gsmem[];
    uint32_t sb = smem_to_u32(gsmem);

    const int proj = (mode == 0) ? blockIdx.z : 3;
    const __half* Ag = (mode == 0) ? g_Xh : g_Oh;
    const __half* Bg = g_Wh + (size_t)proj * EMB * EMB;
    const float* bias = (mode == 1) ? bias0
                       : (proj == 0) ? bias0 : (proj == 1) ? bias1 : bias2;

    const int tid  = threadIdx.x;
    const int lane = tid & 31;
    const int w    = tid >> 5;
    const int wm   = w & 3;
    const int wn   = w >> 2;
    const int bm   = blockIdx.y * 128;
    const int bn   = blockIdx.x * 128;

    float acc[2][8][4];
#pragma unroll
    for (int i = 0; i < 2; i++)
#pragma unroll
        for (int j = 0; j < 8; j++)
#pragma unroll
            for (int c = 0; c < 4; c++) acc[i][j][c] = 0.f;

    const int a_row = lane & 15;
    const int a_ch  = lane >> 4;
    const int b_row = ((lane >> 4) & 1) * 8 + (lane & 7);
    const int b_ch  = (lane >> 3) & 1;

    const int NK = EMB / 64;
    gemm_stage64(sb,        tid, bm, bn, 0,  Ag, Bg);
    CP_COMMIT();
    gemm_stage64(sb + GSTG, tid, bm, bn, 64, Ag, Bg);
    CP_COMMIT();

    uint32_t ah[2][2][4];
    uint32_t bb[2][4][4];

    int st_cur = 0, st_nxt = 2;
    for (int kc = 0; kc < NK; kc++) {
        if (kc + 1 < NK) { CP_WAIT1(); } else { CP_WAIT0(); }
        __syncthreads();
        if (kc + 2 < NK) {
            gemm_stage64(sb + st_nxt * GSTG, tid, bm, bn, (kc + 2) * 64, Ag, Bg);
            CP_COMMIT();
        }
        uint32_t sbs = sb + st_cur * GSTG;

        load_afrag(sbs, wm, a_row, a_ch, 0, ah[0]);
        load_bfrag(sbs, wn, b_row, b_ch, 0, bb[0]);
#pragma unroll
        for (int ks = 0; ks < 4; ks++) {
            const int cur = ks & 1;
            if (ks < 3) {
                load_afrag(sbs, wm, a_row, a_ch, ks + 1, ah[1 - cur]);
                load_bfrag(sbs, wn, b_row, b_ch, ks + 1, bb[1 - cur]);
            }
#pragma unroll
            for (int np = 0; np < 4; np++)
#pragma unroll
                for (int sub = 0; sub < 2; sub++)
#pragma unroll
                    for (int mi = 0; mi < 2; mi++)
                        mma16816h(acc[mi][np * 2 + sub], ah[cur][mi], &bb[cur][np][sub * 2]);
        }
        st_cur = (st_cur + 1 == 3) ? 0 : st_cur + 1;
        st_nxt = (st_nxt + 1 == 3) ? 0 : st_nxt + 1;
    }

    // epilogue
#pragma unroll
    for (int mi = 0; mi < 2; mi++) {
#pragma unroll
        for (int nf = 0; nf < 8; nf++) {
            int col = bn + wn * 64 + nf * 8 + (lane & 3) * 2;
            float2 bv = *(const float2*)(bias + col);
#pragma unroll
            for (int h = 0; h < 2; h++) {
                int m = bm + wm * 32 + mi * 16 + (lane >> 2) + h * 8;
                float2 o;
                o.x = acc[mi][nf][h * 2 + 0] + bv.x;
                o.y = acc[mi][nf][h * 2 + 1] + bv.y;
                if (mode == 1) {
                    *(float2*)(Cout + (size_t)m * EMB + col) = o;
                } else {
                    int b = m >> 11;
                    int s = m & (SEQ - 1);
                    int hh = col >> 6;
                    int d  = col & (HD - 1);
                    float sc = (proj == 0) ? QSCALE : 1.0f;
                    __half2 hv = __floats2half2_rn(o.x * sc, o.y * sc);
                    __half* dst = (proj == 0) ? g_Qh : (proj == 1) ? g_Kh : g_Vh;
                    *(__half2*)(dst + (((size_t)(b * NH + hh)) * SEQ + s) * HD + d) = hv;
                }
            }
        }
    }
}

// ---------------------------------------------------------------------------
// Tensor-core flash attention, fp16 mma, 3-stage cp.async KV pipeline.
// CTA = 256 threads (8 warps); warp owns 16 q rows; CTA q tile = 128.
// KV tile = 128. Dynamic smem: Q 16KB + 3 x (K 16KB + V 16KB) = 112KB.
// Softmax: exp via ex2.approx.f16x2 (P fragments produced directly);
// row-sums via ones-column MMA into an fp32 accumulator (no shfl reduce).
// ---------------------------------------------------------------------------
#define KVSTG 32768
#define ATTN_SMEM (16384 + 3 * KVSTG)

__device__ __forceinline__ void attn_stage_kv(
    uint32_t sbs, int tid, const __half* kg, const __half* vg)
{
#pragma unroll
    for (int l = 0; l < 8; l++) {
        const int kv = l >> 2;
        int i   = (l & 3) * 256 + tid;       // 0..1023
        int row = i >> 3;                    // 0..127
        int ch  = i & 7;
        uint32_t dst = sbs + kv * 16384 + row * 128 + ((ch ^ (row & 7)) * 16);
        const __half* src = (kv ? vg : kg) + (size_t)row * HD + ch * 8;
        cp_async16(dst, src);
    }
}

__global__ __launch_bounds__(256, 2) void attn_tc_kernel()
{
    extern __shared__ __align__(16) char asmem[];
    const uint32_t sQ  = smem_to_u32(asmem);
    const uint32_t sKV = sQ + 16384;

    const int tid  = threadIdx.x;
    const int lane = tid & 31;
    const int w    = tid >> 5;          // 0..7
    const int bh   = blockIdx.y;
    const int it   = blockIdx.x;        // q tile 0..15 (128 rows)

    const __half* Qg = g_Qh + ((size_t)bh * SEQ + (size_t)it * 128) * HD;
    const __half* Kg = g_Kh + (size_t)bh * SEQ * HD;
    const __half* Vg = g_Vh + (size_t)bh * SEQ * HD;

    // stage Q tile (128 rows x 64 halfs, swizzled)
    __half* Qs = (__half*)asmem;
#pragma unroll
    for (int l = 0; l < 4; l++) {
        int idx = tid + l * 256;       // 0..1023
        int row = idx >> 3;            // 0..127
        int ch  = idx & 7;
        *(uint4*)&Qs[row * 64 + ((ch ^ (row & 7)) * 8)] =
            *(const uint4*)(Qg + (size_t)row * HD + ch * 8);
    }

    // prologue: issue KV tiles 0 and 1
    attn_stage_kv(sKV,         tid, Kg, Vg);
    CP_COMMIT();
    attn_stage_kv(sKV + KVSTG, tid, Kg + (size_t)128 * HD, Vg + (size_t)128 * HD);
    CP_COMMIT();
    __syncthreads();

    // loop-invariant Q A-fragments
    const int a_row = lane & 15;
    const int a_ch  = lane >> 4;
    uint32_t qa[4][4];
#pragma unroll
    for (int ks = 0; ks < 4; ks++) {
        int qr = w * 16 + a_row;
        int lc = ks * 2 + a_ch;
        ldsm_x4(qa[ks], sQ + qr * 128 + ((lc ^ (qr & 7)) * 16));
    }

    const int b_row = ((lane >> 4) & 1) * 8 + (lane & 7);
    const int b_ch  = (lane >> 3) & 1;
    const int v_row = lane & 15;
    const int v_ch  = lane >> 4;

    const uint32_t ones_b[2] = { 0x3C003C00u, 0x3C003C00u };   // fp16 1.0 x4

    float o[8][4];
#pragma unroll
    for (int nf = 0; nf < 8; nf++)
#pragma unroll
        for (int c = 0; c < 4; c++) o[nf][c] = 0.f;
    float lacc[4] = { 0.f, 0.f, 0.f, 0.f };    // row-sum accumulator (ones-MMA)
    float m0 = -1e30f, m1 = -1e30f;

    const int NT = SEQ / 128;
    int st_cur = 0, st_nxt = 2;
    for (int jt = 0; jt < NT; jt++) {
        if (jt + 1 < NT) { CP_WAIT1(); } else { CP_WAIT0(); }
        __syncthreads();
        if (jt + 2 < NT) {
            attn_stage_kv(sKV + st_nxt * KVSTG, tid,
                          Kg + (size_t)(jt + 2) * 128 * HD,
                          Vg + (size_t)(jt + 2) * 128 * HD);
            CP_COMMIT();
        }
        uint32_t sK = sKV + st_cur * KVSTG;
        uint32_t sV = sK + 16384;

        // S = Q K^T  (16 x 128 per warp)
        float s[16][4];
#pragma unroll
        for (int nf = 0; nf < 16; nf++)
#pragma unroll
            for (int c = 0; c < 4; c++) s[nf][c] = 0.f;
#pragma unroll
        for (int nt = 0; nt < 8; nt++) {
#pragma unroll
            for (int ks = 0; ks < 4; ks++) {
                uint32_t kb[4];
                int kr = nt * 16 + b_row;
                int lc = ks * 2 + b_ch;
                ldsm_x4(kb, sK + kr * 128 + ((lc ^ (kr & 7)) * 16));
                mma16816h(s[nt * 2 + 0], qa[ks], &kb[0]);
                mma16816h(s[nt * 2 + 1], qa[ks], &kb[2]);
            }
        }

        // online softmax: row max (quad shfl), then exp in packed fp16
        float mx0 = -1e30f, mx1 = -1e30f;
#pragma unroll
        for (int nf = 0; nf < 16; nf++) {
            mx0 = fmaxf(mx0, fmaxf(s[nf][0], s[nf][1]));
            mx1 = fmaxf(mx1, fmaxf(s[nf][2], s[nf][3]));
        }
        mx0 = fmaxf(mx0, __shfl_xor_sync(0xffffffffu, mx0, 1));
        mx0 = fmaxf(mx0, __shfl_xor_sync(0xffffffffu, mx0, 2));
        mx1 = fmaxf(mx1, __shfl_xor_sync(0xffffffffu, mx1, 1));
        mx1 = fmaxf(mx1, __shfl_xor_sync(0xffffffffu, mx1, 2));

        float mn0 = fmaxf(m0, mx0);
        float mn1 = fmaxf(m1, mx1);
        float sc0 = ex2f(m0 - mn0);
        float sc1 = ex2f(m1 - mn1);
        m0 = mn0;  m1 = mn1;

        // P A-fragments directly from packed fp16 exp
        uint32_t pa[8][4];
#pragma unroll
        for (int kt = 0; kt < 8; kt++) {
            pa[kt][0] = ex2_pack_h2(s[2 * kt][0] - mn0,     s[2 * kt][1] - mn0);
            pa[kt][1] = ex2_pack_h2(s[2 * kt][2] - mn1,     s[2 * kt][3] - mn1);
            pa[kt][2] = ex2_pack_h2(s[2 * kt + 1][0] - mn0, s[2 * kt + 1][1] - mn0);
            pa[kt][3] = ex2_pack_h2(s[2 * kt + 1][2] - mn1, s[2 * kt + 1][3] - mn1);
        }

        // rescale O and row-sum accumulator
#pragma unroll
        for (int nf = 0; nf < 8; nf++) {
            o[nf][0] *= sc0; o[nf][1] *= sc0;
            o[nf][2] *= sc1; o[nf][3] *= sc1;
        }
        lacc[0] *= sc0; lacc[1] *= sc0;
        lacc[2] *= sc1; lacc[3] *= sc1;

        // O += P V ; row sums += P * ones  (both on tensor pipe, fp32 accum)
#pragma unroll
        for (int kt = 0; kt < 8; kt++) {
            mma16816h(lacc, pa[kt], ones_b);
#pragma unroll
            for (int nt = 0; nt < 4; nt++) {
                uint32_t vb[4];
                int vr = kt * 16 + v_row;
                int lc = nt * 2 + v_ch;
                ldsm_x4_t(vb, sV + vr * 128 + ((lc ^ (vr & 7)) * 16));
                mma16816h(o[nt * 2 + 0], pa[kt], &vb[0]);
                mma16816h(o[nt * 2 + 1], pa[kt], &vb[2]);
            }
        }
        st_cur = (st_cur + 1 == 3) ? 0 : st_cur + 1;
        st_nxt = (st_nxt + 1 == 3) ? 0 : st_nxt + 1;
    }

    // epilogue: normalize, write fp16 to g_Oh in [b, s, e] layout
    const int b = bh >> 4;
    const int h = bh & (NH - 1);
    const float inv0 = 1.f / lacc[0];
    const float inv1 = 1.f / lacc[2];
    const int r0 = it * 128 + w * 16 + (lane >> 2);
#pragma unroll
    for (int nf = 0; nf < 8; nf++) {
        int col = h * HD + nf * 8 + (lane & 3) * 2;
        __half2 v0 = __floats2half2_rn(o[nf][0] * inv0, o[nf][1] * inv0);
        __half2 v1 = __floats2half2_rn(o[nf][2] * inv1, o[nf][3] * inv1);
        *(__half2*)(g_Oh + ((size_t)(b * SEQ + r0))     * EMB + col) = v0;
        *(__half2*)(g_Oh + ((size_t)(b * SEQ + r0 + 8)) * EMB + col) = v1;
    }
}

// ---------------------------------------------------------------------------

extern "C" void kernel_launch(void* const* d_in, const int* in_sizes, int n_in,
                              void* d_out, int out_size)
{
    (void)in_sizes; (void)n_in; (void)out_size;
    const float* x   = (const float*)d_in[0];
    const float* w_q = (const float*)d_in[1];
    const float* b_q = (const float*)d_in[2];
    const float* w_k = (const float*)d_in[3];
    const float* b_k = (const float*)d_in[4];
    const float* w_v = (const float*)d_in[5];
    const float* b_v = (const float*)d_in[6];
    const float* w_o = (const float*)d_in[7];
    const float* b_o = (const float*)d_in[8];
    float* out = (float*)d_out;

    cudaFuncSetAttribute(gemm_h_kernel, cudaFuncAttributeMaxDynamicSharedMemorySize,
                         GEMM_SMEM);
    cudaFuncSetAttribute(attn_tc_kernel, cudaFuncAttributeMaxDynamicSharedMemorySize,
                         ATTN_SMEM);

    // fused pre-convert (x + 4 weight matrices) in one launch
    cvt_all_kernel<<<(NX4 + 4 * NW4 + 255) / 256, 256>>>(x, w_q, w_k, w_v, w_o);

    // fused Q/K/V projections
    gemm_h_kernel<<<dim3(EMB / 128, TOK / 128, 3), 256, GEMM_SMEM>>>(
        0, b_q, b_k, b_v, nullptr);

    attn_tc_kernel<<<dim3(SEQ / 128, BHN), 256, ATTN_SMEM>>>();

    // out projection
    gemm_h_kernel<<<dim3(EMB / 128, TOK / 128, 1), 256, GEMM_SMEM>>>(
        1, b_o, nullptr, nullptr, out);
}

// round 11
// speedup vs baseline: 9.1390x; 1.0346x over previous
#include <cuda_runtime.h>
#include <cuda_fp16.h>
#include <cstdint>
#include <math.h>

#define SEQ 2048
#define EMB 1024
#define NH  16
#define HD  64
#define NB  4
#define TOK (NB * SEQ)     // 8192
#define BHN (NB * NH)      // 64

// Scratch (device globals: allocation-free rule)
__device__ __align__(128) __half g_Qh[(size_t)BHN * SEQ * HD];
__device__ __align__(128) __half g_Kh[(size_t)BHN * SEQ * HD];
__device__ __align__(128) __half g_Vh[(size_t)BHN * SEQ * HD];
__device__ __align__(128) __half g_Xh[(size_t)TOK * EMB];
__device__ __align__(128) __half g_Oh[(size_t)TOK * EMB];
__device__ __align__(128) __half g_Wh[(size_t)4 * EMB * EMB];

// ---------------------------------------------------------------------------
// PTX helpers
// ---------------------------------------------------------------------------
__device__ __forceinline__ uint32_t smem_to_u32(const void* p) {
    uint32_t a;
    asm("{ .reg .u64 t; cvta.to.shared.u64 t, %1; cvt.u32.u64 %0, t; }" : "=r"(a) : "l"(p));
    return a;
}
__device__ __forceinline__ void ldsm_x4(uint32_t* r, uint32_t addr) {
    asm volatile("ldmatrix.sync.aligned.m8n8.x4.shared.b16 {%0,%1,%2,%3}, [%4];"
        : "=r"(r[0]), "=r"(r[1]), "=r"(r[2]), "=r"(r[3]) : "r"(addr));
}
__device__ __forceinline__ void ldsm_x4_t(uint32_t* r, uint32_t addr) {
    asm volatile("ldmatrix.sync.aligned.m8n8.x4.trans.shared.b16 {%0,%1,%2,%3}, [%4];"
        : "=r"(r[0]), "=r"(r[1]), "=r"(r[2]), "=r"(r[3]) : "r"(addr));
}
__device__ __forceinline__ void mma16816h(float* c, const uint32_t* a, const uint32_t* b) {
    asm volatile("mma.sync.aligned.m16n8k16.row.col.f32.f16.f16.f32 "
        "{%0,%1,%2,%3}, {%4,%5,%6,%7}, {%8,%9}, {%0,%1,%2,%3};"
        : "+f"(c[0]), "+f"(c[1]), "+f"(c[2]), "+f"(c[3])
        : "r"(a[0]), "r"(a[1]), "r"(a[2]), "r"(a[3]), "r"(b[0]), "r"(b[1]));
}
__device__ __forceinline__ float ex2f(float x) {
    float r;
    asm("ex2.approx.f32 %0, %1;" : "=f"(r) : "f"(x));
    return r;
}
// pack two fp32 into half2 (lo = a, hi = b), then 2^x elementwise in fp16
__device__ __forceinline__ uint32_t ex2_pack_h2(float a, float b) {
    uint32_t d;
    asm("cvt.rn.f16x2.f32 %0, %1, %2;" : "=r"(d) : "f"(b), "f"(a));
    asm("ex2.approx.f16x2 %0, %0;" : "+r"(d));
    return d;
}
__device__ __forceinline__ void cp_async16(uint32_t dst, const void* src) {
    asm volatile("cp.async.cg.shared.global [%0], [%1], 16;" :: "r"(dst), "l"(src));
}
#define CP_COMMIT() asm volatile("cp.async.commit_group;" ::: "memory")
#define CP_WAIT0()  asm volatile("cp.async.wait_group 0;" ::: "memory")
#define CP_WAIT1()  asm volatile("cp.async.wait_group 1;" ::: "memory")

// Q pre-scale: 1/sqrt(HD) * log2(e)
#define QSCALE 0.1803368801111244f

// ---------------------------------------------------------------------------
// Fused pre-convert fp32 -> fp16: x then w_q|w_k|w_v|w_o (one launch).
// ---------------------------------------------------------------------------
#define NX4 (TOK * EMB / 4)
#define NW4 (EMB * EMB / 4)

__global__ __launch_bounds__(256) void cvt_all_kernel(
    const float* __restrict__ x,
    const float* __restrict__ wq, const float* __restrict__ wk,
    const float* __restrict__ wv, const float* __restrict__ wo)
{
    int i = blockIdx.x * blockDim.x + threadIdx.x;
    const float4* src;
    uint2* dst;
    if (i < NX4) {
        src = (const float4*)x + i;
        dst = (uint2*)g_Xh + i;
    } else {
        int j = i - NX4;
        int w = j / NW4;
        int r = j - w * NW4;
        const float* s = (w == 0) ? wq : (w == 1) ? wk : (w == 2) ? wv : wo;
        src = (const float4*)s + r;
        dst = (uint2*)g_Wh + j;
    }
    float4 v = *src;
    __half2 h0 = __floats2half2_rn(v.x, v.y);
    __half2 h1 = __floats2half2_rn(v.z, v.w);
    uint2 o = { *reinterpret_cast<uint32_t*>(&h0), *reinterpret_cast<uint32_t*>(&h1) };
    *dst = o;
}

// ---------------------------------------------------------------------------
// fp16 GEMM, BK=64, 3-stage cp.async pipeline + reg-buffered fragments.
// (unchanged from R10)
// ---------------------------------------------------------------------------
#define GSTG 32768
#define GEMM_SMEM (3 * GSTG)

__device__ __forceinline__ void gemm_stage64(
    uint32_t sbs, int tid, int bm, int bn, int k0,
    const __half* __restrict__ Ag, const __half* __restrict__ Bg)
{
#pragma unroll
    for (int l = 0; l < 8; l++) {
        const int buf = l >> 2;                 // 0=A, 1=B
        int i   = (l & 3) * 256 + tid;          // 0..1023
        int row = i >> 3;                       // 0..127
        int ch  = i & 7;
        uint32_t dst = sbs + buf * 16384 + row * 128 + ((ch ^ (row & 7)) * 16);
        const __half* src = (buf ? Bg + (size_t)(bn + row) * EMB
                                 : Ag + (size_t)(bm + row) * EMB) + k0 + ch * 8;
        cp_async16(dst, src);
    }
}

__device__ __forceinline__ void load_afrag(
    uint32_t sbs, int wm, int a_row, int a_ch, int ks, uint32_t ah[2][4])
{
#pragma unroll
    for (int mi = 0; mi < 2; mi++) {
        int ar = wm * 32 + mi * 16 + a_row;
        int lc = ks * 2 + a_ch;
        ldsm_x4(ah[mi], sbs + ar * 128 + ((lc ^ (ar & 7)) * 16));
    }
}
__device__ __forceinline__ void load_bfrag(
    uint32_t sbs, int wn, int b_row, int b_ch, int ks, uint32_t bb[4][4])
{
#pragma unroll
    for (int np = 0; np < 4; np++) {
        int br = wn * 64 + np * 16 + b_row;
        int lc = ks * 2 + b_ch;
        ldsm_x4(bb[np], sbs + 16384 + br * 128 + ((lc ^ (br & 7)) * 16));
    }
}

__global__ __launch_bounds__(256, 2) void gemm_h_kernel(
    int mode,
    const float* __restrict__ bias0,
    const float* __restrict__ bias1,
    const float* __restrict__ bias2,
    float* __restrict__ Cout)
{
    extern __shared__ __align__(16) char gsmem[];
    uint32_t sb = smem_to_u32(gsmem);

    const int proj = (mode == 0) ? blockIdx.z : 3;
    const __half* Ag = (mode == 0) ? g_Xh : g_Oh;
    const __half* Bg = g_Wh + (size_t)proj * EMB * EMB;
    const float* bias = (mode == 1) ? bias0
                       : (proj == 0) ? bias0 : (proj == 1) ? bias1 : bias2;

    const int tid  = threadIdx.x;
    const int lane = tid & 31;
    const int w    = tid >> 5;
    const int wm   = w & 3;
    const int wn   = w >> 2;
    const int bm   = blockIdx.y * 128;
    const int bn   = blockIdx.x * 128;

    float acc[2][8][4];
#pragma unroll
    for (int i = 0; i < 2; i++)
#pragma unroll
        for (int j = 0; j < 8; j++)
#pragma unroll
            for (int c = 0; c < 4; c++) acc[i][j][c] = 0.f;

    const int a_row = lane & 15;
    const int a_ch  = lane >> 4;
    const int b_row = ((lane >> 4) & 1) * 8 + (lane & 7);
    const int b_ch  = (lane >> 3) & 1;

    const int NK = EMB / 64;
    gemm_stage64(sb,        tid, bm, bn, 0,  Ag, Bg);
    CP_COMMIT();
    gemm_stage64(sb + GSTG, tid, bm, bn, 64, Ag, Bg);
    CP_COMMIT();

    uint32_t ah[2][2][4];
    uint32_t bb[2][4][4];

    int st_cur = 0, st_nxt = 2;
    for (int kc = 0; kc < NK; kc++) {
        if (kc + 1 < NK) { CP_WAIT1(); } else { CP_WAIT0(); }
        __syncthreads();
        if (kc + 2 < NK) {
            gemm_stage64(sb + st_nxt * GSTG, tid, bm, bn, (kc + 2) * 64, Ag, Bg);
            CP_COMMIT();
        }
        uint32_t sbs = sb + st_cur * GSTG;

        load_afrag(sbs, wm, a_row, a_ch, 0, ah[0]);
        load_bfrag(sbs, wn, b_row, b_ch, 0, bb[0]);
#pragma unroll
        for (int ks = 0; ks < 4; ks++) {
            const int cur = ks & 1;
            if (ks < 3) {
                load_afrag(sbs, wm, a_row, a_ch, ks + 1, ah[1 - cur]);
                load_bfrag(sbs, wn, b_row, b_ch, ks + 1, bb[1 - cur]);
            }
#pragma unroll
            for (int np = 0; np < 4; np++)
#pragma unroll
                for (int sub = 0; sub < 2; sub++)
#pragma unroll
                    for (int mi = 0; mi < 2; mi++)
                        mma16816h(acc[mi][np * 2 + sub], ah[cur][mi], &bb[cur][np][sub * 2]);
        }
        st_cur = (st_cur + 1 == 3) ? 0 : st_cur + 1;
        st_nxt = (st_nxt + 1 == 3) ? 0 : st_nxt + 1;
    }

    // epilogue
#pragma unroll
    for (int mi = 0; mi < 2; mi++) {
#pragma unroll
        for (int nf = 0; nf < 8; nf++) {
            int col = bn + wn * 64 + nf * 8 + (lane & 3) * 2;
            float2 bv = *(const float2*)(bias + col);
#pragma unroll
            for (int h = 0; h < 2; h++) {
                int m = bm + wm * 32 + mi * 16 + (lane >> 2) + h * 8;
                float2 o;
                o.x = acc[mi][nf][h * 2 + 0] + bv.x;
                o.y = acc[mi][nf][h * 2 + 1] + bv.y;
                if (mode == 1) {
                    *(float2*)(Cout + (size_t)m * EMB + col) = o;
                } else {
                    int b = m >> 11;
                    int s = m & (SEQ - 1);
                    int hh = col >> 6;
                    int d  = col & (HD - 1);
                    float sc = (proj == 0) ? QSCALE : 1.0f;
                    __half2 hv = __floats2half2_rn(o.x * sc, o.y * sc);
                    __half* dst = (proj == 0) ? g_Qh : (proj == 1) ? g_Kh : g_Vh;
                    *(__half2*)(dst + (((size_t)(b * NH + hh)) * SEQ + s) * HD + d) = hv;
                }
            }
        }
    }
}

// ---------------------------------------------------------------------------
// Tensor-core flash attention v2: 32 q rows per warp (halves K/V smem
// re-reads). CTA = 128 threads (4 warps); CTA q tile = 128; KV tile = 64.
// 3-stage cp.async KV pipeline. Dynamic smem: Q 16KB + 3 x 16KB = 64KB.
// K and V fragments are shared across both 16-row m-halves of each warp.
// ---------------------------------------------------------------------------
#define KVSTG 16384
#define ATTN_SMEM (16384 + 3 * KVSTG)

__device__ __forceinline__ void attn_stage_kv64(
    uint32_t sbs, int tid, const __half* kg, const __half* vg)
{
#pragma unroll
    for (int l = 0; l < 8; l++) {
        const int kv = l >> 2;
        int i   = (l & 3) * 128 + tid;       // 0..511
        int row = i >> 3;                    // 0..63
        int ch  = i & 7;
        uint32_t dst = sbs + kv * 8192 + row * 128 + ((ch ^ (row & 7)) * 16);
        const __half* src = (kv ? vg : kg) + (size_t)row * HD + ch * 8;
        cp_async16(dst, src);
    }
}

__global__ __launch_bounds__(128) void attn_tc_kernel()
{
    extern __shared__ __align__(16) char asmem[];
    const uint32_t sQ  = smem_to_u32(asmem);
    const uint32_t sKV = sQ + 16384;

    const int tid  = threadIdx.x;
    const int lane = tid & 31;
    const int w    = tid >> 5;          // 0..3, owns q rows [w*32, w*32+32)
    const int bh   = blockIdx.y;
    const int it   = blockIdx.x;        // q tile 0..15 (128 rows)

    const __half* Qg = g_Qh + ((size_t)bh * SEQ + (size_t)it * 128) * HD;
    const __half* Kg = g_Kh + (size_t)bh * SEQ * HD;
    const __half* Vg = g_Vh + (size_t)bh * SEQ * HD;

    // stage Q tile (128 rows x 64 halfs, swizzled)
    __half* Qs = (__half*)asmem;
#pragma unroll
    for (int l = 0; l < 8; l++) {
        int idx = tid + l * 128;       // 0..1023
        int row = idx >> 3;            // 0..127
        int ch  = idx & 7;
        *(uint4*)&Qs[row * 64 + ((ch ^ (row & 7)) * 8)] =
            *(const uint4*)(Qg + (size_t)row * HD + ch * 8);
    }

    // prologue: issue KV tiles 0 and 1
    attn_stage_kv64(sKV,         tid, Kg, Vg);
    CP_COMMIT();
    attn_stage_kv64(sKV + KVSTG, tid, Kg + (size_t)64 * HD, Vg + (size_t)64 * HD);
    CP_COMMIT();
    __syncthreads();

    // loop-invariant Q A-fragments: two 16-row halves per warp
    const int a_row = lane & 15;
    const int a_ch  = lane >> 4;
    uint32_t qa[2][4][4];
#pragma unroll
    for (int mi = 0; mi < 2; mi++)
#pragma unroll
        for (int ks = 0; ks < 4; ks++) {
            int qr = w * 32 + mi * 16 + a_row;
            int lc = ks * 2 + a_ch;
            ldsm_x4(qa[mi][ks], sQ + qr * 128 + ((lc ^ (qr & 7)) * 16));
        }

    const int b_row = ((lane >> 4) & 1) * 8 + (lane & 7);
    const int b_ch  = (lane >> 3) & 1;
    const int v_row = lane & 15;
    const int v_ch  = lane >> 4;

    const uint32_t ones_b[2] = { 0x3C003C00u, 0x3C003C00u };   // fp16 1.0 x4

    float o[2][8][4];
#pragma unroll
    for (int mi = 0; mi < 2; mi++)
#pragma unroll
        for (int nf = 0; nf < 8; nf++)
#pragma unroll
            for (int c = 0; c < 4; c++) o[mi][nf][c] = 0.f;
    float lacc[2][4] = { {0.f,0.f,0.f,0.f}, {0.f,0.f,0.f,0.f} };
    float m0[2] = { -1e30f, -1e30f };   // rows lane>>2 (+mi*16)
    float m1[2] = { -1e30f, -1e30f };   // rows lane>>2 + 8 (+mi*16)

    const int NT = SEQ / 64;
    int st_cur = 0, st_nxt = 2;
    for (int jt = 0; jt < NT; jt++) {
        if (jt + 1 < NT) { CP_WAIT1(); } else { CP_WAIT0(); }
        __syncthreads();
        if (jt + 2 < NT) {
            attn_stage_kv64(sKV + st_nxt * KVSTG, tid,
                            Kg + (size_t)(jt + 2) * 64 * HD,
                            Vg + (size_t)(jt + 2) * 64 * HD);
            CP_COMMIT();
        }
        uint32_t sK = sKV + st_cur * KVSTG;
        uint32_t sV = sK + 8192;

        // S = Q K^T  (32 x 64 per warp; K frags shared across mi)
        float s[2][8][4];
#pragma unroll
        for (int mi = 0; mi < 2; mi++)
#pragma unroll
            for (int nf = 0; nf < 8; nf++)
#pragma unroll
                for (int c = 0; c < 4; c++) s[mi][nf][c] = 0.f;
#pragma unroll
        for (int nt = 0; nt < 4; nt++) {
#pragma unroll
            for (int ks = 0; ks < 4; ks++) {
                uint32_t kb[4];
                int kr = nt * 16 + b_row;
                int lc = ks * 2 + b_ch;
                ldsm_x4(kb, sK + kr * 128 + ((lc ^ (kr & 7)) * 16));
#pragma unroll
                for (int mi = 0; mi < 2; mi++) {
                    mma16816h(s[mi][nt * 2 + 0], qa[mi][ks], &kb[0]);
                    mma16816h(s[mi][nt * 2 + 1], qa[mi][ks], &kb[2]);
                }
            }
        }

        // online softmax per mi-half; exp in packed fp16 -> P A-frags
        uint32_t pa[2][4][4];
#pragma unroll
        for (int mi = 0; mi < 2; mi++) {
            float mx0 = -1e30f, mx1 = -1e30f;
#pragma unroll
            for (int nf = 0; nf < 8; nf++) {
                mx0 = fmaxf(mx0, fmaxf(s[mi][nf][0], s[mi][nf][1]));
                mx1 = fmaxf(mx1, fmaxf(s[mi][nf][2], s[mi][nf][3]));
            }
            mx0 = fmaxf(mx0, __shfl_xor_sync(0xffffffffu, mx0, 1));
            mx0 = fmaxf(mx0, __shfl_xor_sync(0xffffffffu, mx0, 2));
            mx1 = fmaxf(mx1, __shfl_xor_sync(0xffffffffu, mx1, 1));
            mx1 = fmaxf(mx1, __shfl_xor_sync(0xffffffffu, mx1, 2));

            float mn0 = fmaxf(m0[mi], mx0);
            float mn1 = fmaxf(m1[mi], mx1);
            float sc0 = ex2f(m0[mi] - mn0);
            float sc1 = ex2f(m1[mi] - mn1);
            m0[mi] = mn0;  m1[mi] = mn1;

#pragma unroll
            for (int kt = 0; kt < 4; kt++) {
                pa[mi][kt][0] = ex2_pack_h2(s[mi][2*kt][0] - mn0,   s[mi][2*kt][1] - mn0);
                pa[mi][kt][1] = ex2_pack_h2(s[mi][2*kt][2] - mn1,   s[mi][2*kt][3] - mn1);
                pa[mi][kt][2] = ex2_pack_h2(s[mi][2*kt+1][0] - mn0, s[mi][2*kt+1][1] - mn0);
                pa[mi][kt][3] = ex2_pack_h2(s[mi][2*kt+1][2] - mn1, s[mi][2*kt+1][3] - mn1);
            }

#pragma unroll
            for (int nf = 0; nf < 8; nf++) {
                o[mi][nf][0] *= sc0; o[mi][nf][1] *= sc0;
                o[mi][nf][2] *= sc1; o[mi][nf][3] *= sc1;
            }
            lacc[mi][0] *= sc0; lacc[mi][1] *= sc0;
            lacc[mi][2] *= sc1; lacc[mi][3] *= sc1;
        }

        // O += P V ; row sums += P * ones  (V frags shared across mi)
#pragma unroll
        for (int kt = 0; kt < 4; kt++) {
            mma16816h(lacc[0], pa[0][kt], ones_b);
            mma16816h(lacc[1], pa[1][kt], ones_b);
#pragma unroll
            for (int nt = 0; nt < 4; nt++) {
                uint32_t vb[4];
                int vr = kt * 16 + v_row;
                int lc = nt * 2 + v_ch;
                ldsm_x4_t(vb, sV + vr * 128 + ((lc ^ (vr & 7)) * 16));
#pragma unroll
                for (int mi = 0; mi < 2; mi++) {
                    mma16816h(o[mi][nt * 2 + 0], pa[mi][kt], &vb[0]);
                    mma16816h(o[mi][nt * 2 + 1], pa[mi][kt], &vb[2]);
                }
            }
        }
        st_cur = (st_cur + 1 == 3) ? 0 : st_cur + 1;
        st_nxt = (st_nxt + 1 == 3) ? 0 : st_nxt + 1;
    }

    // epilogue: normalize, write fp16 to g_Oh in [b, s, e] layout
    const int b = bh >> 4;
    const int h = bh & (NH - 1);
#pragma unroll
    for (int mi = 0; mi < 2; mi++) {
        const float inv0 = 1.f / lacc[mi][0];
        const float inv1 = 1.f / lacc[mi][2];
        const int r0 = it * 128 + w * 32 + mi * 16 + (lane >> 2);
#pragma unroll
        for (int nf = 0; nf < 8; nf++) {
            int col = h * HD + nf * 8 + (lane & 3) * 2;
            __half2 v0 = __floats2half2_rn(o[mi][nf][0] * inv0, o[mi][nf][1] * inv0);
            __half2 v1 = __floats2half2_rn(o[mi][nf][2] * inv1, o[mi][nf][3] * inv1);
            *(__half2*)(g_Oh + ((size_t)(b * SEQ + r0))     * EMB + col) = v0;
            *(__half2*)(g_Oh + ((size_t)(b * SEQ + r0 + 8)) * EMB + col) = v1;
        }
    }
}

// ---------------------------------------------------------------------------

extern "C" void kernel_launch(void* const* d_in, const int* in_sizes, int n_in,
                              void* d_out, int out_size)
{
    (void)in_sizes; (void)n_in; (void)out_size;
    const float* x   = (const float*)d_in[0];
    const float* w_q = (const float*)d_in[1];
    const float* b_q = (const float*)d_in[2];
    const float* w_k = (const float*)d_in[3];
    const float* b_k = (const float*)d_in[4];
    const float* w_v = (const float*)d_in[5];
    const float* b_v = (const float*)d_in[6];
    const float* w_o = (const float*)d_in[7];
    const float* b_o = (const float*)d_in[8];
    float* out = (float*)d_out;

    cudaFuncSetAttribute(gemm_h_kernel, cudaFuncAttributeMaxDynamicSharedMemorySize,
                         GEMM_SMEM);
    cudaFuncSetAttribute(attn_tc_kernel, cudaFuncAttributeMaxDynamicSharedMemorySize,
                         ATTN_SMEM);

    // fused pre-convert (x + 4 weight matrices) in one launch
    cvt_all_kernel<<<(NX4 + 4 * NW4 + 255) / 256, 256>>>(x, w_q, w_k, w_v, w_o);

    // fused Q/K/V projections
    gemm_h_kernel<<<dim3(EMB / 128, TOK / 128, 3), 256, GEMM_SMEM>>>(
        0, b_q, b_k, b_v, nullptr);

    attn_tc_kernel<<<dim3(SEQ / 128, BHN), 128, ATTN_SMEM>>>();

    // out projection
    gemm_h_kernel<<<dim3(EMB / 128, TOK / 128, 1), 256, GEMM_SMEM>>>(
        1, b_o, nullptr, nullptr, out);
}

// round 12
// speedup vs baseline: 9.2620x; 1.0135x over previous
#include <cuda_runtime.h>
#include <cuda_fp16.h>
#include <cstdint>
#include <math.h>

#define SEQ 2048
#define EMB 1024
#define NH  16
#define HD  64
#define NB  4
#define TOK (NB * SEQ)     // 8192
#define BHN (NB * NH)      // 64

// Scratch (device globals: allocation-free rule)
__device__ __align__(128) __half g_Qh[(size_t)BHN * SEQ * HD];
__device__ __align__(128) __half g_Kh[(size_t)BHN * SEQ * HD];
__device__ __align__(128) __half g_Vh[(size_t)BHN * SEQ * HD];
__device__ __align__(128) __half g_Xh[(size_t)TOK * EMB];
__device__ __align__(128) __half g_Oh[(size_t)TOK * EMB];
__device__ __align__(128) __half g_Wh[(size_t)4 * EMB * EMB];

// ---------------------------------------------------------------------------
// PTX helpers
// ---------------------------------------------------------------------------
__device__ __forceinline__ uint32_t smem_to_u32(const void* p) {
    uint32_t a;
    asm("{ .reg .u64 t; cvta.to.shared.u64 t, %1; cvt.u32.u64 %0, t; }" : "=r"(a) : "l"(p));
    return a;
}
__device__ __forceinline__ void ldsm_x4(uint32_t* r, uint32_t addr) {
    asm volatile("ldmatrix.sync.aligned.m8n8.x4.shared.b16 {%0,%1,%2,%3}, [%4];"
        : "=r"(r[0]), "=r"(r[1]), "=r"(r[2]), "=r"(r[3]) : "r"(addr));
}
__device__ __forceinline__ void ldsm_x4_t(uint32_t* r, uint32_t addr) {
    asm volatile("ldmatrix.sync.aligned.m8n8.x4.trans.shared.b16 {%0,%1,%2,%3}, [%4];"
        : "=r"(r[0]), "=r"(r[1]), "=r"(r[2]), "=r"(r[3]) : "r"(addr));
}
__device__ __forceinline__ void mma16816h(float* c, const uint32_t* a, const uint32_t* b) {
    asm volatile("mma.sync.aligned.m16n8k16.row.col.f32.f16.f16.f32 "
        "{%0,%1,%2,%3}, {%4,%5,%6,%7}, {%8,%9}, {%0,%1,%2,%3};"
        : "+f"(c[0]), "+f"(c[1]), "+f"(c[2]), "+f"(c[3])
        : "r"(a[0]), "r"(a[1]), "r"(a[2]), "r"(a[3]), "r"(b[0]), "r"(b[1]));
}
__device__ __forceinline__ float ex2f(float x) {
    float r;
    asm("ex2.approx.f32 %0, %1;" : "=f"(r) : "f"(x));
    return r;
}
// pack two fp32 into half2 (lo = a, hi = b), then 2^x elementwise in fp16
__device__ __forceinline__ uint32_t ex2_pack_h2(float a, float b) {
    uint32_t d;
    asm("cvt.rn.f16x2.f32 %0, %1, %2;" : "=r"(d) : "f"(b), "f"(a));
    asm("ex2.approx.f16x2 %0, %0;" : "+r"(d));
    return d;
}
__device__ __forceinline__ void cp_async16(uint32_t dst, const void* src) {
    asm volatile("cp.async.cg.shared.global [%0], [%1], 16;" :: "r"(dst), "l"(src));
}
#define CP_COMMIT() asm volatile("cp.async.commit_group;" ::: "memory")
#define CP_WAIT0()  asm volatile("cp.async.wait_group 0;" ::: "memory")
#define CP_WAIT1()  asm volatile("cp.async.wait_group 1;" ::: "memory")

// Q pre-scale: 1/sqrt(HD) * log2(e)
#define QSCALE 0.1803368801111244f

// ---------------------------------------------------------------------------
// Fused pre-convert fp32 -> fp16: x then w_q|w_k|w_v|w_o (one launch).
// ---------------------------------------------------------------------------
#define NX4 (TOK * EMB / 4)
#define NW4 (EMB * EMB / 4)

__global__ __launch_bounds__(256) void cvt_all_kernel(
    const float* __restrict__ x,
    const float* __restrict__ wq, const float* __restrict__ wk,
    const float* __restrict__ wv, const float* __restrict__ wo)
{
    int i = blockIdx.x * blockDim.x + threadIdx.x;
    const float4* src;
    uint2* dst;
    if (i < NX4) {
        src = (const float4*)x + i;
        dst = (uint2*)g_Xh + i;
    } else {
        int j = i - NX4;
        int w = j / NW4;
        int r = j - w * NW4;
        const float* s = (w == 0) ? wq : (w == 1) ? wk : (w == 2) ? wv : wo;
        src = (const float4*)s + r;
        dst = (uint2*)g_Wh + j;
    }
    float4 v = *src;
    __half2 h0 = __floats2half2_rn(v.x, v.y);
    __half2 h1 = __floats2half2_rn(v.z, v.w);
    uint2 o = { *reinterpret_cast<uint32_t*>(&h0), *reinterpret_cast<uint32_t*>(&h1) };
    *dst = o;
}

// ---------------------------------------------------------------------------
// fp16 GEMM v2: CTA 128x128, 4 warps, warp tile 64x64 (8 ldsm : 32 MMA).
// BK=64, 3-stage cp.async pipeline. Dynamic smem: 3 x 32KB = 96KB.
// mode 0: fused QKV (blockIdx.z selects W + scatter dest).
// mode 1: out projection (A = g_Oh, W = W[3], fp32 store + bias).
// Rows 128B (64 fp16); chunk16 swizzle: ch ^ (row&7).
// ---------------------------------------------------------------------------
#define GSTG 32768
#define GEMM_SMEM (3 * GSTG)

__device__ __forceinline__ void gemm_stage64(
    uint32_t sbs, int tid, int bm, int bn, int k0,
    const __half* __restrict__ Ag, const __half* __restrict__ Bg)
{
#pragma unroll
    for (int l = 0; l < 16; l++) {
        const int buf = l >> 3;                 // 0=A, 1=B
        int i   = (l & 7) * 128 + tid;          // 0..1023
        int row = i >> 3;                       // 0..127
        int ch  = i & 7;
        uint32_t dst = sbs + buf * 16384 + row * 128 + ((ch ^ (row & 7)) * 16);
        const __half* src = (buf ? Bg + (size_t)(bn + row) * EMB
                                 : Ag + (size_t)(bm + row) * EMB) + k0 + ch * 8;
        cp_async16(dst, src);
    }
}

__global__ __launch_bounds__(128, 2) void gemm_h_kernel(
    int mode,
    const float* __restrict__ bias0,
    const float* __restrict__ bias1,
    const float* __restrict__ bias2,
    float* __restrict__ Cout)
{
    extern __shared__ __align__(16) char gsmem[];
    uint32_t sb = smem_to_u32(gsmem);

    const int proj = (mode == 0) ? blockIdx.z : 3;
    const __half* Ag = (mode == 0) ? g_Xh : g_Oh;
    const __half* Bg = g_Wh + (size_t)proj * EMB * EMB;
    const float* bias = (mode == 1) ? bias0
                       : (proj == 0) ? bias0 : (proj == 1) ? bias1 : bias2;

    const int tid  = threadIdx.x;
    const int lane = tid & 31;
    const int w    = tid >> 5;          // 0..3
    const int wm   = w & 1;             // 64-row slice
    const int wn   = w >> 1;            // 64-col slice
    const int bm   = blockIdx.y * 128;
    const int bn   = blockIdx.x * 128;

    float acc[4][8][4];
#pragma unroll
    for (int i = 0; i < 4; i++)
#pragma unroll
        for (int j = 0; j < 8; j++)
#pragma unroll
            for (int c = 0; c < 4; c++) acc[i][j][c] = 0.f;

    const int a_row = lane & 15;
    const int a_ch  = lane >> 4;
    const int b_row = ((lane >> 4) & 1) * 8 + (lane & 7);
    const int b_ch  = (lane >> 3) & 1;

    const int NK = EMB / 64;
    gemm_stage64(sb,        tid, bm, bn, 0,  Ag, Bg);
    CP_COMMIT();
    gemm_stage64(sb + GSTG, tid, bm, bn, 64, Ag, Bg);
    CP_COMMIT();

    int st_cur = 0, st_nxt = 2;
    for (int kc = 0; kc < NK; kc++) {
        if (kc + 1 < NK) { CP_WAIT1(); } else { CP_WAIT0(); }
        __syncthreads();
        if (kc + 2 < NK) {
            gemm_stage64(sb + st_nxt * GSTG, tid, bm, bn, (kc + 2) * 64, Ag, Bg);
            CP_COMMIT();
        }
        uint32_t sbs = sb + st_cur * GSTG;

#pragma unroll
        for (int ks = 0; ks < 4; ks++) {
            uint32_t ah[4][4], bb[4][4];
#pragma unroll
            for (int mi = 0; mi < 4; mi++) {
                int ar = wm * 64 + mi * 16 + a_row;
                int lc = ks * 2 + a_ch;
                ldsm_x4(ah[mi], sbs + ar * 128 + ((lc ^ (ar & 7)) * 16));
            }
#pragma unroll
            for (int np = 0; np < 4; np++) {
                int br = wn * 64 + np * 16 + b_row;
                int lc = ks * 2 + b_ch;
                ldsm_x4(bb[np], sbs + 16384 + br * 128 + ((lc ^ (br & 7)) * 16));
            }
#pragma unroll
            for (int np = 0; np < 4; np++)
#pragma unroll
                for (int sub = 0; sub < 2; sub++)
#pragma unroll
                    for (int mi = 0; mi < 4; mi++)
                        mma16816h(acc[mi][np * 2 + sub], ah[mi], &bb[np][sub * 2]);
        }
        st_cur = (st_cur + 1 == 3) ? 0 : st_cur + 1;
        st_nxt = (st_nxt + 1 == 3) ? 0 : st_nxt + 1;
    }

    // epilogue
#pragma unroll
    for (int mi = 0; mi < 4; mi++) {
#pragma unroll
        for (int nf = 0; nf < 8; nf++) {
            int col = bn + wn * 64 + nf * 8 + (lane & 3) * 2;
            float2 bv = *(const float2*)(bias + col);
#pragma unroll
            for (int h = 0; h < 2; h++) {
                int m = bm + wm * 64 + mi * 16 + (lane >> 2) + h * 8;
                float2 o;
                o.x = acc[mi][nf][h * 2 + 0] + bv.x;
                o.y = acc[mi][nf][h * 2 + 1] + bv.y;
                if (mode == 1) {
                    *(float2*)(Cout + (size_t)m * EMB + col) = o;
                } else {
                    int b = m >> 11;
                    int s = m & (SEQ - 1);
                    int hh = col >> 6;
                    int d  = col & (HD - 1);
                    float sc = (proj == 0) ? QSCALE : 1.0f;
                    __half2 hv = __floats2half2_rn(o.x * sc, o.y * sc);
                    __half* dst = (proj == 0) ? g_Qh : (proj == 1) ? g_Kh : g_Vh;
                    *(__half2*)(dst + (((size_t)(b * NH + hh)) * SEQ + s) * HD + d) = hv;
                }
            }
        }
    }
}

// ---------------------------------------------------------------------------
// Tensor-core flash attention (unchanged from R11): 32 q rows per warp.
// CTA = 128 threads (4 warps); CTA q tile = 128; KV tile = 64.
// 3-stage cp.async KV pipeline. Dynamic smem: Q 16KB + 3 x 16KB = 64KB.
// ---------------------------------------------------------------------------
#define KVSTG 16384
#define ATTN_SMEM (16384 + 3 * KVSTG)

__device__ __forceinline__ void attn_stage_kv64(
    uint32_t sbs, int tid, const __half* kg, const __half* vg)
{
#pragma unroll
    for (int l = 0; l < 8; l++) {
        const int kv = l >> 2;
        int i   = (l & 3) * 128 + tid;       // 0..511
        int row = i >> 3;                    // 0..63
        int ch  = i & 7;
        uint32_t dst = sbs + kv * 8192 + row * 128 + ((ch ^ (row & 7)) * 16);
        const __half* src = (kv ? vg : kg) + (size_t)row * HD + ch * 8;
        cp_async16(dst, src);
    }
}

__global__ __launch_bounds__(128) void attn_tc_kernel()
{
    extern __shared__ __align__(16) char asmem[];
    const uint32_t sQ  = smem_to_u32(asmem);
    const uint32_t sKV = sQ + 16384;

    const int tid  = threadIdx.x;
    const int lane = tid & 31;
    const int w    = tid >> 5;          // 0..3, owns q rows [w*32, w*32+32)
    const int bh   = blockIdx.y;
    const int it   = blockIdx.x;        // q tile 0..15 (128 rows)

    const __half* Qg = g_Qh + ((size_t)bh * SEQ + (size_t)it * 128) * HD;
    const __half* Kg = g_Kh + (size_t)bh * SEQ * HD;
    const __half* Vg = g_Vh + (size_t)bh * SEQ * HD;

    // stage Q tile (128 rows x 64 halfs, swizzled)
    __half* Qs = (__half*)asmem;
#pragma unroll
    for (int l = 0; l < 8; l++) {
        int idx = tid + l * 128;       // 0..1023
        int row = idx >> 3;            // 0..127
        int ch  = idx & 7;
        *(uint4*)&Qs[row * 64 + ((ch ^ (row & 7)) * 8)] =
            *(const uint4*)(Qg + (size_t)row * HD + ch * 8);
    }

    // prologue: issue KV tiles 0 and 1
    attn_stage_kv64(sKV,         tid, Kg, Vg);
    CP_COMMIT();
    attn_stage_kv64(sKV + KVSTG, tid, Kg + (size_t)64 * HD, Vg + (size_t)64 * HD);
    CP_COMMIT();
    __syncthreads();

    // loop-invariant Q A-fragments: two 16-row halves per warp
    const int a_row = lane & 15;
    const int a_ch  = lane >> 4;
    uint32_t qa[2][4][4];
#pragma unroll
    for (int mi = 0; mi < 2; mi++)
#pragma unroll
        for (int ks = 0; ks < 4; ks++) {
            int qr = w * 32 + mi * 16 + a_row;
            int lc = ks * 2 + a_ch;
            ldsm_x4(qa[mi][ks], sQ + qr * 128 + ((lc ^ (qr & 7)) * 16));
        }

    const int b_row = ((lane >> 4) & 1) * 8 + (lane & 7);
    const int b_ch  = (lane >> 3) & 1;
    const int v_row = lane & 15;
    const int v_ch  = lane >> 4;

    const uint32_t ones_b[2] = { 0x3C003C00u, 0x3C003C00u };   // fp16 1.0 x4

    float o[2][8][4];
#pragma unroll
    for (int mi = 0; mi < 2; mi++)
#pragma unroll
        for (int nf = 0; nf < 8; nf++)
#pragma unroll
            for (int c = 0; c < 4; c++) o[mi][nf][c] = 0.f;
    float lacc[2][4] = { {0.f,0.f,0.f,0.f}, {0.f,0.f,0.f,0.f} };
    float m0[2] = { -1e30f, -1e30f };
    float m1[2] = { -1e30f, -1e30f };

    const int NT = SEQ / 64;
    int st_cur = 0, st_nxt = 2;
    for (int jt = 0; jt < NT; jt++) {
        if (jt + 1 < NT) { CP_WAIT1(); } else { CP_WAIT0(); }
        __syncthreads();
        if (jt + 2 < NT) {
            attn_stage_kv64(sKV + st_nxt * KVSTG, tid,
                            Kg + (size_t)(jt + 2) * 64 * HD,
                            Vg + (size_t)(jt + 2) * 64 * HD);
            CP_COMMIT();
        }
        uint32_t sK = sKV + st_cur * KVSTG;
        uint32_t sV = sK + 8192;

        // S = Q K^T  (32 x 64 per warp; K frags shared across mi)
        float s[2][8][4];
#pragma unroll
        for (int mi = 0; mi < 2; mi++)
#pragma unroll
            for (int nf = 0; nf < 8; nf++)
#pragma unroll
                for (int c = 0; c < 4; c++) s[mi][nf][c] = 0.f;
#pragma unroll
        for (int nt = 0; nt < 4; nt++) {
#pragma unroll
            for (int ks = 0; ks < 4; ks++) {
                uint32_t kb[4];
                int kr = nt * 16 + b_row;
                int lc = ks * 2 + b_ch;
                ldsm_x4(kb, sK + kr * 128 + ((lc ^ (kr & 7)) * 16));
#pragma unroll
                for (int mi = 0; mi < 2; mi++) {
                    mma16816h(s[mi][nt * 2 + 0], qa[mi][ks], &kb[0]);
                    mma16816h(s[mi][nt * 2 + 1], qa[mi][ks], &kb[2]);
                }
            }
        }

        // online softmax per mi-half; exp in packed fp16 -> P A-frags
        uint32_t pa[2][4][4];
#pragma unroll
        for (int mi = 0; mi < 2; mi++) {
            float mx0 = -1e30f, mx1 = -1e30f;
#pragma unroll
            for (int nf = 0; nf < 8; nf++) {
                mx0 = fmaxf(mx0, fmaxf(s[mi][nf][0], s[mi][nf][1]));
                mx1 = fmaxf(mx1, fmaxf(s[mi][nf][2], s[mi][nf][3]));
            }
            mx0 = fmaxf(mx0, __shfl_xor_sync(0xffffffffu, mx0, 1));
            mx0 = fmaxf(mx0, __shfl_xor_sync(0xffffffffu, mx0, 2));
            mx1 = fmaxf(mx1, __shfl_xor_sync(0xffffffffu, mx1, 1));
            mx1 = fmaxf(mx1, __shfl_xor_sync(0xffffffffu, mx1, 2));

            float mn0 = fmaxf(m0[mi], mx0);
            float mn1 = fmaxf(m1[mi], mx1);
            float sc0 = ex2f(m0[mi] - mn0);
            float sc1 = ex2f(m1[mi] - mn1);
            m0[mi] = mn0;  m1[mi] = mn1;

#pragma unroll
            for (int kt = 0; kt < 4; kt++) {
                pa[mi][kt][0] = ex2_pack_h2(s[mi][2*kt][0] - mn0,   s[mi][2*kt][1] - mn0);
                pa[mi][kt][1] = ex2_pack_h2(s[mi][2*kt][2] - mn1,   s[mi][2*kt][3] - mn1);
                pa[mi][kt][2] = ex2_pack_h2(s[mi][2*kt+1][0] - mn0, s[mi][2*kt+1][1] - mn0);
                pa[mi][kt][3] = ex2_pack_h2(s[mi][2*kt+1][2] - mn1, s[mi][2*kt+1][3] - mn1);
            }

#pragma unroll
            for (int nf = 0; nf < 8; nf++) {
                o[mi][nf][0] *= sc0; o[mi][nf][1] *= sc0;
                o[mi][nf][2] *= sc1; o[mi][nf][3] *= sc1;
            }
            lacc[mi][0] *= sc0; lacc[mi][1] *= sc0;
            lacc[mi][2] *= sc1; lacc[mi][3] *= sc1;
        }

        // O += P V ; row sums += P * ones  (V frags shared across mi)
#pragma unroll
        for (int kt = 0; kt < 4; kt++) {
            mma16816h(lacc[0], pa[0][kt], ones_b);
            mma16816h(lacc[1], pa[1][kt], ones_b);
#pragma unroll
            for (int nt = 0; nt < 4; nt++) {
                uint32_t vb[4];
                int vr = kt * 16 + v_row;
                int lc = nt * 2 + v_ch;
                ldsm_x4_t(vb, sV + vr * 128 + ((lc ^ (vr & 7)) * 16));
#pragma unroll
                for (int mi = 0; mi < 2; mi++) {
                    mma16816h(o[mi][nt * 2 + 0], pa[mi][kt], &vb[0]);
                    mma16816h(o[mi][nt * 2 + 1], pa[mi][kt], &vb[2]);
                }
            }
        }
        st_cur = (st_cur + 1 == 3) ? 0 : st_cur + 1;
        st_nxt = (st_nxt + 1 == 3) ? 0 : st_nxt + 1;
    }

    // epilogue: normalize, write fp16 to g_Oh in [b, s, e] layout
    const int b = bh >> 4;
    const int h = bh & (NH - 1);
#pragma unroll
    for (int mi = 0; mi < 2; mi++) {
        const float inv0 = 1.f / lacc[mi][0];
        const float inv1 = 1.f / lacc[mi][2];
        const int r0 = it * 128 + w * 32 + mi * 16 + (lane >> 2);
#pragma unroll
        for (int nf = 0; nf < 8; nf++) {
            int col = h * HD + nf * 8 + (lane & 3) * 2;
            __half2 v0 = __floats2half2_rn(o[mi][nf][0] * inv0, o[mi][nf][1] * inv0);
            __half2 v1 = __floats2half2_rn(o[mi][nf][2] * inv1, o[mi][nf][3] * inv1);
            *(__half2*)(g_Oh + ((size_t)(b * SEQ + r0))     * EMB + col) = v0;
            *(__half2*)(g_Oh + ((size_t)(b * SEQ + r0 + 8)) * EMB + col) = v1;
        }
    }
}

// ---------------------------------------------------------------------------

extern "C" void kernel_launch(void* const* d_in, const int* in_sizes, int n_in,
                              void* d_out, int out_size)
{
    (void)in_sizes; (void)n_in; (void)out_size;
    const float* x   = (const float*)d_in[0];
    const float* w_q = (const float*)d_in[1];
    const float* b_q = (const float*)d_in[2];
    const float* w_k = (const float*)d_in[3];
    const float* b_k = (const float*)d_in[4];
    const float* w_v = (const float*)d_in[5];
    const float* b_v = (const float*)d_in[6];
    const float* w_o = (const float*)d_in[7];
    const float* b_o = (const float*)d_in[8];
    float* out = (float*)d_out;

    cudaFuncSetAttribute(gemm_h_kernel, cudaFuncAttributeMaxDynamicSharedMemorySize,
                         GEMM_SMEM);
    cudaFuncSetAttribute(attn_tc_kernel, cudaFuncAttributeMaxDynamicSharedMemorySize,
                         ATTN_SMEM);

    // fused pre-convert (x + 4 weight matrices) in one launch
    cvt_all_kernel<<<(NX4 + 4 * NW4 + 255) / 256, 256>>>(x, w_q, w_k, w_v, w_o);

    // fused Q/K/V projections
    gemm_h_kernel<<<dim3(EMB / 128, TOK / 128, 3), 128, GEMM_SMEM>>>(
        0, b_q, b_k, b_v, nullptr);

    attn_tc_kernel<<<dim3(SEQ / 128, BHN), 128, ATTN_SMEM>>>();

    // out projection
    gemm_h_kernel<<<dim3(EMB / 128, TOK / 128, 1), 128, GEMM_SMEM>>>(
        1, b_o, nullptr, nullptr, out);
}